// round 1
// baseline (speedup 1.0000x reference)
#include <cuda_runtime.h>
#include <cuda_bf16.h>
#include <math.h>

// Problem constants
#define Tt 70
#define Bb 80
#define Vv 33278
#define Ee 400
#define Hh 1150
#define TB (Tt*Bb)          // 5600

// ---------------- scratch (device globals; no allocation) ----------------
__device__ float g_X0[(size_t)TB * Hh];           // activations ping
__device__ float g_X1[(size_t)TB * Hh];           // activations pong
__device__ float g_XW[(size_t)TB * 4 * Hh];       // precomputed x@Wih^T + biases
__device__ float g_part[(size_t)12 * Bb * 4 * Hh];// split-K partials
__device__ float g_h[Bb * Hh];
__device__ float g_c[Bb * Hh];

// ---------------- embedding gather ----------------
__global__ void embed_kernel(const int* __restrict__ tokens,
                             const float* __restrict__ emb,
                             float* __restrict__ x, int n) {
    int idx = blockIdx.x * blockDim.x + threadIdx.x;
    if (idx >= n) return;
    int tb = idx / Ee;
    int e  = idx - tb * Ee;
    x[idx] = emb[(size_t)tokens[tb] * Ee + e];
}

// ---------------- generic SGEMM: C[M,N] = A[M,K] * W[N,K]^T + bias0 + bias1 ----------------
#define BM 128
#define BN 128
#define BK 8
#define TM 8
#define TN 8

__global__ __launch_bounds__(256, 1)
void sgemm_nt_bias(const float* __restrict__ A, const float* __restrict__ W,
                   const float* __restrict__ bias0, const float* __restrict__ bias1,
                   float* __restrict__ C, int M, int N, int K)
{
    __shared__ float As[BK][BM];
    __shared__ float Bs[BK][BN];
    const int bn = blockIdx.x * BN;
    const int bm = blockIdx.y * BM;
    const int tid = threadIdx.x;
    const int tx = tid & 15;   // 16 col-groups of 8
    const int ty = tid >> 4;   // 16 row-groups of 8

    const int lrow = tid >> 1;             // 0..127
    const int lk0  = (tid & 1) * 4;        // 0 or 4

    float acc[TM][TN];
#pragma unroll
    for (int i = 0; i < TM; i++)
#pragma unroll
        for (int j = 0; j < TN; j++) acc[i][j] = 0.f;

    for (int k0 = 0; k0 < K; k0 += BK) {
        // load A tile (BM x BK) -> As[k][m]
        {
            int gm = bm + lrow;
            const float* ap = A + (size_t)gm * K + k0 + lk0;
            bool mok = (gm < M);
#pragma unroll
            for (int j = 0; j < 4; j++) {
                int gk = k0 + lk0 + j;
                As[lk0 + j][lrow] = (mok && gk < K) ? ap[j] : 0.f;
            }
        }
        // load W tile (BN x BK) -> Bs[k][n]
        {
            int gn = bn + lrow;
            const float* wp = W + (size_t)gn * K + k0 + lk0;
            bool nok = (gn < N);
#pragma unroll
            for (int j = 0; j < 4; j++) {
                int gk = k0 + lk0 + j;
                Bs[lk0 + j][lrow] = (nok && gk < K) ? wp[j] : 0.f;
            }
        }
        __syncthreads();

#pragma unroll
        for (int kk = 0; kk < BK; kk++) {
            float rm[TM], rn[TN];
            float4 a0 = *(const float4*)&As[kk][ty * TM];
            float4 a1 = *(const float4*)&As[kk][ty * TM + 4];
            float4 b0 = *(const float4*)&Bs[kk][tx * TN];
            float4 b1 = *(const float4*)&Bs[kk][tx * TN + 4];
            rm[0]=a0.x; rm[1]=a0.y; rm[2]=a0.z; rm[3]=a0.w;
            rm[4]=a1.x; rm[5]=a1.y; rm[6]=a1.z; rm[7]=a1.w;
            rn[0]=b0.x; rn[1]=b0.y; rn[2]=b0.z; rn[3]=b0.w;
            rn[4]=b1.x; rn[5]=b1.y; rn[6]=b1.z; rn[7]=b1.w;
#pragma unroll
            for (int i = 0; i < TM; i++)
#pragma unroll
                for (int j = 0; j < TN; j++)
                    acc[i][j] = fmaf(rm[i], rn[j], acc[i][j]);
        }
        __syncthreads();
    }

#pragma unroll
    for (int i = 0; i < TM; i++) {
        int gm = bm + ty * TM + i;
        if (gm >= M) continue;
        float* cp = C + (size_t)gm * N;
#pragma unroll
        for (int j = 0; j < TN; j++) {
            int gn = bn + tx * TN + j;
            if (gn >= N) continue;
            float bv = 0.f;
            if (bias0) bv += bias0[gn];
            if (bias1) bv += bias1[gn];
            cp[gn] = acc[i][j] + bv;
        }
    }
}

// ---------------- recurrent split-K GEMM partials ----------------
// part[s][m][n] = sum_{k in chunk s} h[m][k] * Whh[n][k]
#define RBM 80
#define RBN 128
#define RBK 8

__global__ __launch_bounds__(256, 1)
void rec_gemm_partial(const float* __restrict__ h, const float* __restrict__ Whh,
                      float* __restrict__ part, int N, int K, int S)
{
    const int s = blockIdx.y;
    const int kc = (K + S - 1) / S;
    const int k_begin = s * kc;
    const int k_end = min(K, k_begin + kc);
    const int bn = blockIdx.x * RBN;
    const int tid = threadIdx.x;
    const int tx = tid & 15;   // 16 col groups of 8
    const int ty = tid >> 4;   // 16 row groups of 5

    __shared__ float Hs[RBK][RBM];
    __shared__ float Ws[RBK][RBN];

    float acc[5][8];
#pragma unroll
    for (int i = 0; i < 5; i++)
#pragma unroll
        for (int j = 0; j < 8; j++) acc[i][j] = 0.f;

    const int lrow = tid >> 1;
    const int lk0  = (tid & 1) * 4;

    for (int k0 = k_begin; k0 < k_end; k0 += RBK) {
        // H tile 80 x 8
        for (int i = tid; i < RBM * RBK; i += 256) {
            int k = i / RBM, m = i - k * RBM;
            int gk = k0 + k;
            Hs[k][m] = (gk < k_end) ? h[(size_t)m * K + gk] : 0.f;
        }
        // W tile 128 x 8
        {
            int gn = bn + lrow;
            bool nok = (gn < N);
            const float* wp = Whh + (size_t)gn * K + k0 + lk0;
#pragma unroll
            for (int j = 0; j < 4; j++) {
                int gk = k0 + lk0 + j;
                Ws[lk0 + j][lrow] = (nok && gk < k_end) ? wp[j] : 0.f;
            }
        }
        __syncthreads();

#pragma unroll
        for (int kk = 0; kk < RBK; kk++) {
            float rm[5], rn[8];
#pragma unroll
            for (int i = 0; i < 5; i++) rm[i] = Hs[kk][ty * 5 + i];
            float4 b0 = *(const float4*)&Ws[kk][tx * 8];
            float4 b1 = *(const float4*)&Ws[kk][tx * 8 + 4];
            rn[0]=b0.x; rn[1]=b0.y; rn[2]=b0.z; rn[3]=b0.w;
            rn[4]=b1.x; rn[5]=b1.y; rn[6]=b1.z; rn[7]=b1.w;
#pragma unroll
            for (int i = 0; i < 5; i++)
#pragma unroll
                for (int j = 0; j < 8; j++)
                    acc[i][j] = fmaf(rm[i], rn[j], acc[i][j]);
        }
        __syncthreads();
    }

#pragma unroll
    for (int i = 0; i < 5; i++) {
        int m = ty * 5 + i;   // always < 80
        float* pp = part + ((size_t)s * RBM + m) * N;
#pragma unroll
        for (int j = 0; j < 8; j++) {
            int gn = bn + tx * 8 + j;
            if (gn < N) pp[gn] = acc[i][j];
        }
    }
}

// ---------------- fused split-K reduce + LSTM cell ----------------
__device__ __forceinline__ float sigf(float x) { return 1.f / (1.f + expf(-x)); }

__global__ void lstm_cell_kernel(const float* __restrict__ xw_t,
                                 const float* __restrict__ part,
                                 float* __restrict__ h, float* __restrict__ c,
                                 float* __restrict__ ys_t, int H, int S)
{
    int idx = blockIdx.x * blockDim.x + threadIdx.x;
    if (idx >= Bb * H) return;
    int b = idx / H;
    int j = idx - b * H;
    int N = 4 * H;
    const float* xr = xw_t + (size_t)b * N;
    float gi = xr[j], gf = xr[H + j], gg = xr[2 * H + j], go = xr[3 * H + j];
    for (int s = 0; s < S; s++) {
        const float* p = part + ((size_t)s * Bb + b) * N;
        gi += p[j]; gf += p[H + j]; gg += p[2 * H + j]; go += p[3 * H + j];
    }
    float cn = sigf(gf) * c[idx] + sigf(gi) * tanhf(gg);
    float hn = sigf(go) * tanhf(cn);
    c[idx] = cn;
    h[idx] = hn;
    ys_t[idx] = hn;
}

// ---------------- small copy ----------------
__global__ void copy_f32(float* __restrict__ dst, const float* __restrict__ src, int n) {
    int i = blockIdx.x * blockDim.x + threadIdx.x;
    if (i < n) dst[i] = src[i];
}

// ---------------- host orchestration ----------------
static inline int ceil_div(int a, int b) { return (a + b - 1) / b; }

extern "C" void kernel_launch(void* const* d_in, const int* in_sizes, int n_in,
                              void* d_out, int out_size)
{
    const int*   tokens = (const int*)d_in[0];
    const float* emb_W  = (const float*)d_in[1];
    const float* dec_W  = (const float*)d_in[2];
    const float* dec_b  = (const float*)d_in[3];

    const float *Wih[3], *Whh[3], *bih[3], *bhh[3], *h0[3], *c0[3];
    for (int l = 0; l < 3; l++) {
        int base = 4 + l * 6;
        Wih[l] = (const float*)d_in[base + 0];
        Whh[l] = (const float*)d_in[base + 1];
        bih[l] = (const float*)d_in[base + 2];
        bhh[l] = (const float*)d_in[base + 3];
        h0[l]  = (const float*)d_in[base + 4];
        c0[l]  = (const float*)d_in[base + 5];
    }

    float *pX0, *pX1, *pXW, *pPart, *ph, *pc;
    cudaGetSymbolAddress((void**)&pX0,   g_X0);
    cudaGetSymbolAddress((void**)&pX1,   g_X1);
    cudaGetSymbolAddress((void**)&pXW,   g_XW);
    cudaGetSymbolAddress((void**)&pPart, g_part);
    cudaGetSymbolAddress((void**)&ph,    g_h);
    cudaGetSymbolAddress((void**)&pc,    g_c);

    float* out = (float*)d_out;

    // 1) embedding
    {
        int n = TB * Ee;
        embed_kernel<<<ceil_div(n, 256), 256>>>(tokens, emb_W, pX0, n);
    }

    const int In[3]  = {Ee, Hh, Hh};
    const int Hd[3]  = {Hh, Hh, Ee};
    float* xin  = pX0;
    float* xout = pX1;
    size_t out_off = (size_t)TB * Vv;

    for (int l = 0; l < 3; l++) {
        int I = In[l], H = Hd[l], N4 = 4 * H;

        // xW = x @ Wih^T + bih + bhh   ([T*B, 4H])
        {
            dim3 grid(ceil_div(N4, BN), ceil_div(TB, BM));
            sgemm_nt_bias<<<grid, 256>>>(xin, Wih[l], bih[l], bhh[l], pXW, TB, N4, I);
        }

        // init h, c
        copy_f32<<<ceil_div(Bb * H, 256), 256>>>(ph, h0[l], Bb * H);
        copy_f32<<<ceil_div(Bb * H, 256), 256>>>(pc, c0[l], Bb * H);

        int NB = ceil_div(N4, RBN);
        int S  = (N4 >= 4600) ? 4 : 11;   // ~144 CTAs either way

        for (int t = 0; t < Tt; t++) {
            dim3 grid(NB, S);
            rec_gemm_partial<<<grid, 256>>>(ph, Whh[l], pPart, N4, H, S);
            const float* xw_t = pXW + (size_t)t * Bb * N4;
            float* ys_t = xout + (size_t)t * Bb * H;
            lstm_cell_kernel<<<ceil_div(Bb * H, 256), 256>>>(xw_t, pPart, ph, pc, ys_t, H, S);
        }

        // export hT, cT
        copy_f32<<<ceil_div(Bb * H, 256), 256>>>(out + out_off, ph, Bb * H);
        out_off += (size_t)Bb * H;
        copy_f32<<<ceil_div(Bb * H, 256), 256>>>(out + out_off, pc, Bb * H);
        out_off += (size_t)Bb * H;

        // ping-pong
        float* tmp = xin; xin = xout; xout = tmp;
    }

    // 2) decoder: decoded[T*B, V] = ys @ dec_W^T + dec_b  (ys is in xin after last swap)
    {
        dim3 grid(ceil_div(Vv, BN), ceil_div(TB, BM));
        sgemm_nt_bias<<<grid, 256>>>(xin, dec_W, dec_b, nullptr, out, TB, Vv, Ee);
    }
}

// round 2
// speedup vs baseline: 1.4228x; 1.4228x over previous
#include <cuda_runtime.h>
#include <cuda_bf16.h>
#include <math.h>
#include <stdint.h>

// Problem constants
#define Tt 70
#define Bb 80
#define Vv 33278
#define Ee 400
#define Hh 1150
#define TB (Tt*Bb)          // 5600

// ---------------- scratch (device globals; no allocation) ----------------
__device__ float g_X0[(size_t)TB * Hh];           // activations ping
__device__ float g_X1[(size_t)TB * Hh];           // activations pong
__device__ float g_XW[(size_t)TB * 4 * Hh];       // precomputed x@Wih^T + biases
__device__ float g_part[(size_t)12 * Bb * 4 * Hh];// split-K partials
__device__ float g_h[Bb * Hh];
__device__ float g_c[Bb * Hh];

// ---------------- embedding gather ----------------
__global__ void embed_kernel(const int* __restrict__ tokens,
                             const float* __restrict__ emb,
                             float* __restrict__ x, int n) {
    int idx = blockIdx.x * blockDim.x + threadIdx.x;
    if (idx >= n) return;
    int tb = idx / Ee;
    int e  = idx - tb * Ee;
    x[idx] = emb[(size_t)tokens[tb] * Ee + e];
}

// ---------------- tf32 helpers ----------------
__device__ __forceinline__ float to_tf32(float x) {
    uint32_t u;
    asm("cvt.rna.tf32.f32 %0, %1;" : "=r"(u) : "f"(x));
    return __uint_as_float(u);
}

__device__ __forceinline__ void mma8(float* c, const uint32_t* a, const uint32_t* b) {
    asm volatile(
        "mma.sync.aligned.m16n8k8.row.col.f32.tf32.tf32.f32 "
        "{%0,%1,%2,%3}, {%4,%5,%6,%7}, {%8,%9}, {%0,%1,%2,%3};"
        : "+f"(c[0]), "+f"(c[1]), "+f"(c[2]), "+f"(c[3])
        : "r"(a[0]), "r"(a[1]), "r"(a[2]), "r"(a[3]), "r"(b[0]), "r"(b[1]));
}

// ---------------- tensor-core GEMM: C[M,N] = A[M,K] * W[N,K]^T + bias ----------------
// PASSES=1: plain tf32. PASSES=3: 3xTF32 error-free-split (near-fp32 accuracy).
// CTA tile 128x128, 8 warps as 2(m) x 4(n), warp tile 64x32. BK=16 per stage.
// smem layout: plane[k][ m ^ ((9k)&28) ]  (conflict-free for STS + frag reads).
template<int PASSES>
__global__ __launch_bounds__(256)
void mma_gemm(const float* __restrict__ A, const float* __restrict__ W,
              const float* __restrict__ bias0, const float* __restrict__ bias1,
              float* __restrict__ C, int M, int N, int K)
{
    __shared__ float AsH[16 * 128];
    __shared__ float AsL[16 * 128];
    __shared__ float BsH[16 * 128];
    __shared__ float BsL[16 * 128];

    const int tid  = threadIdx.x;
    const int lane = tid & 31;
    const int warp = tid >> 5;
    const int wm   = warp >> 2;        // 0..1
    const int wn   = warp & 3;         // 0..3
    const int gid  = lane >> 2;        // 0..7
    const int tig  = lane & 3;         // 0..3
    const int bm   = blockIdx.y * 128;
    const int bn   = blockIdx.x * 128;

    float acc[4][4][4];
#pragma unroll
    for (int i = 0; i < 4; i++)
#pragma unroll
        for (int j = 0; j < 4; j++)
#pragma unroll
            for (int q = 0; q < 4; q++) acc[i][j][q] = 0.f;

    // register staging for gmem->smem (float2 granules; tile = 128 rows x 8 granules)
    float2 aR[4], bR[4];

    // load granule indices: g = tid + i*256; m = g>>3; k = (g&7)*2
    auto load_stage = [&](int k0) {
#pragma unroll
        for (int i = 0; i < 4; i++) {
            int g  = tid + i * 256;
            int m  = g >> 3;
            int gk = k0 + ((g & 7) << 1);
            int gm = bm + m;
            if (gm < M && gk < K)
                aR[i] = *(const float2*)(A + (size_t)gm * K + gk);
            else
                aR[i] = make_float2(0.f, 0.f);
            int gn = bn + m;
            if (gn < N && gk < K)
                bR[i] = *(const float2*)(W + (size_t)gn * K + gk);
            else
                bR[i] = make_float2(0.f, 0.f);
        }
    };

    auto store_stage = [&]() {
#pragma unroll
        for (int i = 0; i < 4; i++) {
            int g = tid + i * 256;
            int m = g >> 3;
            int kq = (g & 7) << 1;
#pragma unroll
            for (int j = 0; j < 2; j++) {
                int k = kq + j;
                int idx = k * 128 + (m ^ ((9 * k) & 28));
                {
                    float x  = (j == 0) ? aR[i].x : aR[i].y;
                    float hi = to_tf32(x);
                    AsH[idx] = hi;
                    if (PASSES == 3) AsL[idx] = to_tf32(x - hi);
                }
                {
                    float x  = (j == 0) ? bR[i].x : bR[i].y;
                    float hi = to_tf32(x);
                    BsH[idx] = hi;
                    if (PASSES == 3) BsL[idx] = to_tf32(x - hi);
                }
            }
        }
    };

    load_stage(0);

    for (int k0 = 0; k0 < K; k0 += 16) {
        __syncthreads();   // previous stage's consumers done
        store_stage();
        __syncthreads();
        if (k0 + 16 < K) load_stage(k0 + 16);  // prefetch next (hidden under compute)

#pragma unroll
        for (int ks = 0; ks < 2; ks++) {
            const int k1 = ks * 8 + tig;
            const int k2 = k1 + 4;
            const int s1 = (9 * k1) & 28;
            const int s2 = (9 * k2) & 28;
            const int o1 = k1 * 128;
            const int o2 = k2 * 128;

            uint32_t ah[4][4], al[4][4], bh[4][2], bl[4][2];
#pragma unroll
            for (int mt = 0; mt < 4; mt++) {
                int mb = wm * 64 + mt * 16 + gid;
                ah[mt][0] = __float_as_uint(AsH[o1 + (mb ^ s1)]);
                ah[mt][1] = __float_as_uint(AsH[o1 + ((mb + 8) ^ s1)]);
                ah[mt][2] = __float_as_uint(AsH[o2 + (mb ^ s2)]);
                ah[mt][3] = __float_as_uint(AsH[o2 + ((mb + 8) ^ s2)]);
                if (PASSES == 3) {
                    al[mt][0] = __float_as_uint(AsL[o1 + (mb ^ s1)]);
                    al[mt][1] = __float_as_uint(AsL[o1 + ((mb + 8) ^ s1)]);
                    al[mt][2] = __float_as_uint(AsL[o2 + (mb ^ s2)]);
                    al[mt][3] = __float_as_uint(AsL[o2 + ((mb + 8) ^ s2)]);
                }
            }
#pragma unroll
            for (int nt = 0; nt < 4; nt++) {
                int nb = wn * 32 + nt * 8 + gid;
                bh[nt][0] = __float_as_uint(BsH[o1 + (nb ^ s1)]);
                bh[nt][1] = __float_as_uint(BsH[o2 + (nb ^ s2)]);
                if (PASSES == 3) {
                    bl[nt][0] = __float_as_uint(BsL[o1 + (nb ^ s1)]);
                    bl[nt][1] = __float_as_uint(BsL[o2 + (nb ^ s2)]);
                }
            }
#pragma unroll
            for (int mt = 0; mt < 4; mt++)
#pragma unroll
                for (int nt = 0; nt < 4; nt++) {
                    mma8(acc[mt][nt], ah[mt], bh[nt]);
                    if (PASSES == 3) {
                        mma8(acc[mt][nt], al[mt], bh[nt]);
                        mma8(acc[mt][nt], ah[mt], bl[nt]);
                    }
                }
        }
    }

    // epilogue: add bias, write float2 pairs (cols 2*tig, 2*tig+1)
#pragma unroll
    for (int mt = 0; mt < 4; mt++) {
#pragma unroll
        for (int nt = 0; nt < 4; nt++) {
            int r0 = bm + wm * 64 + mt * 16 + gid;
            int cc = bn + wn * 32 + nt * 8 + 2 * tig;
            if (cc >= N) continue;
            float bv0 = 0.f, bv1 = 0.f;
            if (bias0) { bv0 += bias0[cc]; bv1 += bias0[cc + 1]; }
            if (bias1) { bv0 += bias1[cc]; bv1 += bias1[cc + 1]; }
            if (r0 < M) {
                float2 v = make_float2(acc[mt][nt][0] + bv0, acc[mt][nt][1] + bv1);
                *(float2*)(C + (size_t)r0 * N + cc) = v;
            }
            if (r0 + 8 < M) {
                float2 v = make_float2(acc[mt][nt][2] + bv0, acc[mt][nt][3] + bv1);
                *(float2*)(C + (size_t)(r0 + 8) * N + cc) = v;
            }
        }
    }
}

// ---------------- recurrent split-K GEMM partials (fp32) ----------------
#define RBM 80
#define RBN 128
#define RBK 8

__global__ __launch_bounds__(256, 1)
void rec_gemm_partial(const float* __restrict__ h, const float* __restrict__ Whh,
                      float* __restrict__ part, int N, int K, int S)
{
    const int s = blockIdx.y;
    const int kc = (K + S - 1) / S;
    const int k_begin = s * kc;
    const int k_end = min(K, k_begin + kc);
    const int bn = blockIdx.x * RBN;
    const int tid = threadIdx.x;
    const int tx = tid & 15;
    const int ty = tid >> 4;

    __shared__ float Hs[RBK][RBM];
    __shared__ float Ws[RBK][RBN];

    float acc[5][8];
#pragma unroll
    for (int i = 0; i < 5; i++)
#pragma unroll
        for (int j = 0; j < 8; j++) acc[i][j] = 0.f;

    const int lrow = tid >> 1;
    const int lk0  = (tid & 1) * 4;

    for (int k0 = k_begin; k0 < k_end; k0 += RBK) {
        for (int i = tid; i < RBM * RBK; i += 256) {
            int k = i / RBM, m = i - k * RBM;
            int gk = k0 + k;
            Hs[k][m] = (gk < k_end) ? h[(size_t)m * K + gk] : 0.f;
        }
        {
            int gn = bn + lrow;
            bool nok = (gn < N);
            const float* wp = Whh + (size_t)gn * K + k0 + lk0;
#pragma unroll
            for (int j = 0; j < 4; j++) {
                int gk = k0 + lk0 + j;
                Ws[lk0 + j][lrow] = (nok && gk < k_end) ? wp[j] : 0.f;
            }
        }
        __syncthreads();

#pragma unroll
        for (int kk = 0; kk < RBK; kk++) {
            float rm[5], rn[8];
#pragma unroll
            for (int i = 0; i < 5; i++) rm[i] = Hs[kk][ty * 5 + i];
            float4 b0 = *(const float4*)&Ws[kk][tx * 8];
            float4 b1 = *(const float4*)&Ws[kk][tx * 8 + 4];
            rn[0]=b0.x; rn[1]=b0.y; rn[2]=b0.z; rn[3]=b0.w;
            rn[4]=b1.x; rn[5]=b1.y; rn[6]=b1.z; rn[7]=b1.w;
#pragma unroll
            for (int i = 0; i < 5; i++)
#pragma unroll
                for (int j = 0; j < 8; j++)
                    acc[i][j] = fmaf(rm[i], rn[j], acc[i][j]);
        }
        __syncthreads();
    }

#pragma unroll
    for (int i = 0; i < 5; i++) {
        int m = ty * 5 + i;
        float* pp = part + ((size_t)s * RBM + m) * N;
#pragma unroll
        for (int j = 0; j < 8; j++) {
            int gn = bn + tx * 8 + j;
            if (gn < N) pp[gn] = acc[i][j];
        }
    }
}

// ---------------- fused split-K reduce + LSTM cell ----------------
__device__ __forceinline__ float sigf(float x) { return 1.f / (1.f + expf(-x)); }

__global__ void lstm_cell_kernel(const float* __restrict__ xw_t,
                                 const float* __restrict__ part,
                                 float* __restrict__ h, float* __restrict__ c,
                                 float* __restrict__ ys_t, int H, int S)
{
    int idx = blockIdx.x * blockDim.x + threadIdx.x;
    if (idx >= Bb * H) return;
    int b = idx / H;
    int j = idx - b * H;
    int N = 4 * H;
    const float* xr = xw_t + (size_t)b * N;
    float gi = xr[j], gf = xr[H + j], gg = xr[2 * H + j], go = xr[3 * H + j];
    for (int s = 0; s < S; s++) {
        const float* p = part + ((size_t)s * Bb + b) * N;
        gi += p[j]; gf += p[H + j]; gg += p[2 * H + j]; go += p[3 * H + j];
    }
    float cn = sigf(gf) * c[idx] + sigf(gi) * tanhf(gg);
    float hn = sigf(go) * tanhf(cn);
    c[idx] = cn;
    h[idx] = hn;
    ys_t[idx] = hn;
}

// ---------------- small copy ----------------
__global__ void copy_f32(float* __restrict__ dst, const float* __restrict__ src, int n) {
    int i = blockIdx.x * blockDim.x + threadIdx.x;
    if (i < n) dst[i] = src[i];
}

// ---------------- host orchestration ----------------
static inline int ceil_div(int a, int b) { return (a + b - 1) / b; }

extern "C" void kernel_launch(void* const* d_in, const int* in_sizes, int n_in,
                              void* d_out, int out_size)
{
    const int*   tokens = (const int*)d_in[0];
    const float* emb_W  = (const float*)d_in[1];
    const float* dec_W  = (const float*)d_in[2];
    const float* dec_b  = (const float*)d_in[3];

    const float *Wih[3], *Whh[3], *bih[3], *bhh[3], *h0[3], *c0[3];
    for (int l = 0; l < 3; l++) {
        int base = 4 + l * 6;
        Wih[l] = (const float*)d_in[base + 0];
        Whh[l] = (const float*)d_in[base + 1];
        bih[l] = (const float*)d_in[base + 2];
        bhh[l] = (const float*)d_in[base + 3];
        h0[l]  = (const float*)d_in[base + 4];
        c0[l]  = (const float*)d_in[base + 5];
    }

    float *pX0, *pX1, *pXW, *pPart, *ph, *pc;
    cudaGetSymbolAddress((void**)&pX0,   g_X0);
    cudaGetSymbolAddress((void**)&pX1,   g_X1);
    cudaGetSymbolAddress((void**)&pXW,   g_XW);
    cudaGetSymbolAddress((void**)&pPart, g_part);
    cudaGetSymbolAddress((void**)&ph,    g_h);
    cudaGetSymbolAddress((void**)&pc,    g_c);

    float* out = (float*)d_out;

    // 1) embedding
    {
        int n = TB * Ee;
        embed_kernel<<<ceil_div(n, 256), 256>>>(tokens, emb_W, pX0, n);
    }

    const int In[3]  = {Ee, Hh, Hh};
    const int Hd[3]  = {Hh, Hh, Ee};
    float* xin  = pX0;
    float* xout = pX1;
    size_t out_off = (size_t)TB * Vv;

    for (int l = 0; l < 3; l++) {
        int I = In[l], H = Hd[l], N4 = 4 * H;

        // xW = x @ Wih^T + bih + bhh   ([T*B, 4H])  — 3xTF32 tensor path
        {
            dim3 grid(ceil_div(N4, 128), ceil_div(TB, 128));
            mma_gemm<3><<<grid, 256>>>(xin, Wih[l], bih[l], bhh[l], pXW, TB, N4, I);
        }

        // init h, c
        copy_f32<<<ceil_div(Bb * H, 256), 256>>>(ph, h0[l], Bb * H);
        copy_f32<<<ceil_div(Bb * H, 256), 256>>>(pc, c0[l], Bb * H);

        int NB = ceil_div(N4, RBN);
        int S  = (N4 >= 4600) ? 8 : 12;   // 288 / 156 CTAs per step

        for (int t = 0; t < Tt; t++) {
            dim3 grid(NB, S);
            rec_gemm_partial<<<grid, 256>>>(ph, Whh[l], pPart, N4, H, S);
            const float* xw_t = pXW + (size_t)t * Bb * N4;
            float* ys_t = xout + (size_t)t * Bb * H;
            lstm_cell_kernel<<<ceil_div(Bb * H, 256), 256>>>(xw_t, pPart, ph, pc, ys_t, H, S);
        }

        // export hT, cT
        copy_f32<<<ceil_div(Bb * H, 256), 256>>>(out + out_off, ph, Bb * H);
        out_off += (size_t)Bb * H;
        copy_f32<<<ceil_div(Bb * H, 256), 256>>>(out + out_off, pc, Bb * H);
        out_off += (size_t)Bb * H;

        float* tmp = xin; xin = xout; xout = tmp;
    }

    // 2) decoder: decoded[T*B, V] = ys @ dec_W^T + dec_b — 1xTF32 tensor path
    {
        dim3 grid(ceil_div(Vv, 128), ceil_div(TB, 128));
        mma_gemm<1><<<grid, 256>>>(xin, dec_W, dec_b, nullptr, out, TB, Vv, Ee);
    }
}

// round 3
// speedup vs baseline: 1.8880x; 1.3270x over previous
#include <cuda_runtime.h>
#include <cuda_fp16.h>
#include <math.h>
#include <stdint.h>

// Problem constants
#define Tt 70
#define Bb 80
#define Vv 33278
#define Ee 400
#define Hh 1150
#define TB (Tt*Bb)          // 5600
#define KPAD_MAX 1152       // 1150 padded to /16

// ---------------- scratch (device globals; no allocation) ----------------
__device__ float  g_X0[(size_t)TB * Hh];
__device__ float  g_X1[(size_t)TB * Hh];
__device__ float  g_XW[(size_t)TB * 4 * Hh];
__device__ float  g_h[Bb * Hh];
__device__ float  g_c[Bb * Hh];
__device__ __half g_hHi[2][Bb * KPAD_MAX];
__device__ __half g_hLo[2][Bb * KPAD_MAX];

// ---------------- embedding gather ----------------
__global__ void embed_kernel(const int* __restrict__ tokens,
                             const float* __restrict__ emb,
                             float* __restrict__ x, int n) {
    int idx = blockIdx.x * blockDim.x + threadIdx.x;
    if (idx >= n) return;
    int tb = idx / Ee;
    int e  = idx - tb * Ee;
    x[idx] = emb[(size_t)tokens[tb] * Ee + e];
}

// ---------------- mma wrappers ----------------
__device__ __forceinline__ float to_tf32(float x) {
    uint32_t u;
    asm("cvt.rna.tf32.f32 %0, %1;" : "=r"(u) : "f"(x));
    return __uint_as_float(u);
}

__device__ __forceinline__ void mma_tf32(float* c, const uint32_t* a, const uint32_t* b) {
    asm volatile(
        "mma.sync.aligned.m16n8k8.row.col.f32.tf32.tf32.f32 "
        "{%0,%1,%2,%3}, {%4,%5,%6,%7}, {%8,%9}, {%0,%1,%2,%3};"
        : "+f"(c[0]), "+f"(c[1]), "+f"(c[2]), "+f"(c[3])
        : "r"(a[0]), "r"(a[1]), "r"(a[2]), "r"(a[3]), "r"(b[0]), "r"(b[1]));
}

__device__ __forceinline__ void mma_f16(float* c, const uint32_t* a, const uint32_t* b) {
    asm volatile(
        "mma.sync.aligned.m16n8k16.row.col.f32.f16.f16.f32 "
        "{%0,%1,%2,%3}, {%4,%5,%6,%7}, {%8,%9}, {%0,%1,%2,%3};"
        : "+f"(c[0]), "+f"(c[1]), "+f"(c[2]), "+f"(c[3])
        : "r"(a[0]), "r"(a[1]), "r"(a[2]), "r"(a[3]), "r"(b[0]), "r"(b[1]));
}

// ============================================================================
// 3-pass fp16 GEMM: C[M,N] = A[M,K] * W[N,K]^T + bias0 + bias1  (fp32-accurate)
// CTA 128x128, 8 warps 2(m)x4(n), warp 64x32, k-chunk 16.
// smem: row-major [row][16 halves] planes (hi/lo) — conflict-free STS + frags.
// ============================================================================
__global__ __launch_bounds__(256)
void hgemm3_nt_bias(const float* __restrict__ A, const float* __restrict__ W,
                    const float* __restrict__ bias0, const float* __restrict__ bias1,
                    float* __restrict__ C, int M, int N, int K)
{
    __shared__ __half AsH[128 * 16];
    __shared__ __half AsL[128 * 16];
    __shared__ __half BsH[128 * 16];
    __shared__ __half BsL[128 * 16];

    const int tid  = threadIdx.x;
    const int lane = tid & 31;
    const int warp = tid >> 5;
    const int wm   = warp >> 2;       // 0..1
    const int wn   = warp & 3;        // 0..3
    const int g    = lane >> 2;       // 0..7
    const int t4   = lane & 3;        // 0..3
    const int bm   = blockIdx.y * 128;
    const int bn   = blockIdx.x * 128;

    float acc[4][4][4];
#pragma unroll
    for (int i = 0; i < 4; i++)
#pragma unroll
        for (int j = 0; j < 4; j++)
#pragma unroll
            for (int q = 0; q < 4; q++) acc[i][j][q] = 0.f;

    float2 aR[4], bR[4];

    auto load_stage = [&](int k0) {
#pragma unroll
        for (int i = 0; i < 4; i++) {
            int gg = tid + i * 256;          // 0..1023
            int m  = gg >> 3;
            int gk = k0 + ((gg & 7) << 1);
            int gm = bm + m;
            aR[i] = (gm < M && gk < K) ? *(const float2*)(A + (size_t)gm * K + gk)
                                       : make_float2(0.f, 0.f);
            int gn = bn + m;
            bR[i] = (gn < N && gk < K) ? *(const float2*)(W + (size_t)gn * K + gk)
                                       : make_float2(0.f, 0.f);
        }
    };

    auto store_stage = [&]() {
#pragma unroll
        for (int i = 0; i < 4; i++) {
            int gg = tid + i * 256;
            int m  = gg >> 3;
            int kp = gg & 7;
            {
                __half hx = __float2half_rn(aR[i].x);
                __half hy = __float2half_rn(aR[i].y);
                float lx = aR[i].x - __half2float(hx);
                float ly = aR[i].y - __half2float(hy);
                *(__half2*)&AsH[m * 16 + 2 * kp] = __halves2half2(hx, hy);
                *(__half2*)&AsL[m * 16 + 2 * kp] =
                    __halves2half2(__float2half_rn(lx), __float2half_rn(ly));
            }
            {
                __half hx = __float2half_rn(bR[i].x);
                __half hy = __float2half_rn(bR[i].y);
                float lx = bR[i].x - __half2float(hx);
                float ly = bR[i].y - __half2float(hy);
                *(__half2*)&BsH[m * 16 + 2 * kp] = __halves2half2(hx, hy);
                *(__half2*)&BsL[m * 16 + 2 * kp] =
                    __halves2half2(__float2half_rn(lx), __float2half_rn(ly));
            }
        }
    };

    load_stage(0);

    for (int k0 = 0; k0 < K; k0 += 16) {
        __syncthreads();
        store_stage();
        __syncthreads();
        if (k0 + 16 < K) load_stage(k0 + 16);

        uint32_t ah[4][4], al[4][4], bh[4][2], bl[4][2];
#pragma unroll
        for (int mt = 0; mt < 4; mt++) {
            int r0 = wm * 64 + mt * 16 + g;
            ah[mt][0] = *(const uint32_t*)&AsH[r0 * 16 + 2 * t4];
            ah[mt][1] = *(const uint32_t*)&AsH[(r0 + 8) * 16 + 2 * t4];
            ah[mt][2] = *(const uint32_t*)&AsH[r0 * 16 + 2 * t4 + 8];
            ah[mt][3] = *(const uint32_t*)&AsH[(r0 + 8) * 16 + 2 * t4 + 8];
            al[mt][0] = *(const uint32_t*)&AsL[r0 * 16 + 2 * t4];
            al[mt][1] = *(const uint32_t*)&AsL[(r0 + 8) * 16 + 2 * t4];
            al[mt][2] = *(const uint32_t*)&AsL[r0 * 16 + 2 * t4 + 8];
            al[mt][3] = *(const uint32_t*)&AsL[(r0 + 8) * 16 + 2 * t4 + 8];
        }
#pragma unroll
        for (int nt = 0; nt < 4; nt++) {
            int n0 = wn * 32 + nt * 8 + g;
            bh[nt][0] = *(const uint32_t*)&BsH[n0 * 16 + 2 * t4];
            bh[nt][1] = *(const uint32_t*)&BsH[n0 * 16 + 2 * t4 + 8];
            bl[nt][0] = *(const uint32_t*)&BsL[n0 * 16 + 2 * t4];
            bl[nt][1] = *(const uint32_t*)&BsL[n0 * 16 + 2 * t4 + 8];
        }
#pragma unroll
        for (int mt = 0; mt < 4; mt++)
#pragma unroll
            for (int nt = 0; nt < 4; nt++) {
                mma_f16(acc[mt][nt], ah[mt], bh[nt]);
                mma_f16(acc[mt][nt], al[mt], bh[nt]);
                mma_f16(acc[mt][nt], ah[mt], bl[nt]);
            }
    }

#pragma unroll
    for (int mt = 0; mt < 4; mt++) {
#pragma unroll
        for (int nt = 0; nt < 4; nt++) {
            int r0 = bm + wm * 64 + mt * 16 + g;
            int cc = bn + wn * 32 + nt * 8 + 2 * t4;
            if (cc >= N) continue;
            float bv0 = 0.f, bv1 = 0.f;
            if (bias0) { bv0 += bias0[cc]; bv1 += bias0[cc + 1]; }
            if (bias1) { bv0 += bias1[cc]; bv1 += bias1[cc + 1]; }
            if (r0 < M)
                *(float2*)(C + (size_t)r0 * N + cc) =
                    make_float2(acc[mt][nt][0] + bv0, acc[mt][nt][1] + bv1);
            if (r0 + 8 < M)
                *(float2*)(C + (size_t)(r0 + 8) * N + cc) =
                    make_float2(acc[mt][nt][2] + bv0, acc[mt][nt][3] + bv1);
        }
    }
}

// ============================================================================
// 1-pass tf32 GEMM (decoder) — proven R2 kernel, PASSES=1 specialization
// ============================================================================
__global__ __launch_bounds__(256)
void tgemm_nt_bias(const float* __restrict__ A, const float* __restrict__ W,
                   const float* __restrict__ bias0,
                   float* __restrict__ C, int M, int N, int K)
{
    __shared__ float AsH[16 * 128];
    __shared__ float BsH[16 * 128];

    const int tid  = threadIdx.x;
    const int lane = tid & 31;
    const int warp = tid >> 5;
    const int wm   = warp >> 2;
    const int wn   = warp & 3;
    const int gid  = lane >> 2;
    const int tig  = lane & 3;
    const int bm   = blockIdx.y * 128;
    const int bn   = blockIdx.x * 128;

    float acc[4][4][4];
#pragma unroll
    for (int i = 0; i < 4; i++)
#pragma unroll
        for (int j = 0; j < 4; j++)
#pragma unroll
            for (int q = 0; q < 4; q++) acc[i][j][q] = 0.f;

    float2 aR[4], bR[4];

    auto load_stage = [&](int k0) {
#pragma unroll
        for (int i = 0; i < 4; i++) {
            int g  = tid + i * 256;
            int m  = g >> 3;
            int gk = k0 + ((g & 7) << 1);
            int gm = bm + m;
            aR[i] = (gm < M && gk < K) ? *(const float2*)(A + (size_t)gm * K + gk)
                                       : make_float2(0.f, 0.f);
            int gn = bn + m;
            bR[i] = (gn < N && gk < K) ? *(const float2*)(W + (size_t)gn * K + gk)
                                       : make_float2(0.f, 0.f);
        }
    };

    auto store_stage = [&]() {
#pragma unroll
        for (int i = 0; i < 4; i++) {
            int g = tid + i * 256;
            int m = g >> 3;
            int kq = (g & 7) << 1;
#pragma unroll
            for (int j = 0; j < 2; j++) {
                int k = kq + j;
                int idx = k * 128 + (m ^ ((9 * k) & 28));
                AsH[idx] = to_tf32((j == 0) ? aR[i].x : aR[i].y);
                BsH[idx] = to_tf32((j == 0) ? bR[i].x : bR[i].y);
            }
        }
    };

    load_stage(0);

    for (int k0 = 0; k0 < K; k0 += 16) {
        __syncthreads();
        store_stage();
        __syncthreads();
        if (k0 + 16 < K) load_stage(k0 + 16);

#pragma unroll
        for (int ks = 0; ks < 2; ks++) {
            const int k1 = ks * 8 + tig;
            const int k2 = k1 + 4;
            const int s1 = (9 * k1) & 28;
            const int s2 = (9 * k2) & 28;
            const int o1 = k1 * 128;
            const int o2 = k2 * 128;

            uint32_t ah[4][4], bh[4][2];
#pragma unroll
            for (int mt = 0; mt < 4; mt++) {
                int mb = wm * 64 + mt * 16 + gid;
                ah[mt][0] = __float_as_uint(AsH[o1 + (mb ^ s1)]);
                ah[mt][1] = __float_as_uint(AsH[o1 + ((mb + 8) ^ s1)]);
                ah[mt][2] = __float_as_uint(AsH[o2 + (mb ^ s2)]);
                ah[mt][3] = __float_as_uint(AsH[o2 + ((mb + 8) ^ s2)]);
            }
#pragma unroll
            for (int nt = 0; nt < 4; nt++) {
                int nb = wn * 32 + nt * 8 + gid;
                bh[nt][0] = __float_as_uint(BsH[o1 + (nb ^ s1)]);
                bh[nt][1] = __float_as_uint(BsH[o2 + (nb ^ s2)]);
            }
#pragma unroll
            for (int mt = 0; mt < 4; mt++)
#pragma unroll
                for (int nt = 0; nt < 4; nt++)
                    mma_tf32(acc[mt][nt], ah[mt], bh[nt]);
        }
    }

#pragma unroll
    for (int mt = 0; mt < 4; mt++) {
#pragma unroll
        for (int nt = 0; nt < 4; nt++) {
            int r0 = bm + wm * 64 + mt * 16 + gid;
            int cc = bn + wn * 32 + nt * 8 + 2 * tig;
            if (cc >= N) continue;
            float bv0 = bias0 ? bias0[cc] : 0.f;
            float bv1 = bias0 ? bias0[cc + 1] : 0.f;
            if (r0 < M)
                *(float2*)(C + (size_t)r0 * N + cc) =
                    make_float2(acc[mt][nt][0] + bv0, acc[mt][nt][1] + bv1);
            if (r0 + 8 < M)
                *(float2*)(C + (size_t)(r0 + 8) * N + cc) =
                    make_float2(acc[mt][nt][2] + bv0, acc[mt][nt][3] + bv1);
        }
    }
}

// ============================================================================
// Fused recurrent step: gates = h@Whh^T (3-pass fp16 tensor) + xw, then cell.
// CTA owns 8 hidden units j (all 4 gates = 32 output cols), full K.
// 8 warps: 2(m: 48 rows) x 4(n: one gate each). h rows padded 80->96.
// ============================================================================
__device__ __forceinline__ float sigf(float x) { return 1.f / (1.f + expf(-x)); }

__global__ __launch_bounds__(256)
void rec_step_kernel(const __half* __restrict__ hHi, const __half* __restrict__ hLo,
                     const float* __restrict__ Whh, const float* __restrict__ xw_t,
                     float* __restrict__ cst,
                     __half* __restrict__ hHiO, __half* __restrict__ hLoO,
                     float* __restrict__ hF, float* __restrict__ ys_t,
                     int H, int Kpad)
{
    __shared__ __half Ah[96 * 16], Al[96 * 16];
    __shared__ __half Bh[32 * 16], Bl[32 * 16];
    __shared__ float  sg[96 * 33];

    const int tid  = threadIdx.x;
    const int lane = tid & 31;
    const int warp = tid >> 5;
    const int wm   = warp >> 2;    // 0..1  (row half)
    const int wn   = warp & 3;     // 0..3  (= gate index)
    const int g    = lane >> 2;    // 0..7
    const int t4   = lane & 3;     // 0..3
    const int j0   = blockIdx.x * 8;
    const int K    = H;

    float acc[3][4];
#pragma unroll
    for (int i = 0; i < 3; i++)
#pragma unroll
        for (int q = 0; q < 4; q++) acc[i][q] = 0.f;

    __half2 aHr[3], aLr[3];
    float2  bRr;

    auto loadA = [&](int k0) {
#pragma unroll
        for (int i = 0; i < 3; i++) {
            int e = tid + i * 256;           // 0..767
            int row = e >> 3, kp = e & 7;
            if (row < Bb) {
                size_t off = (size_t)row * Kpad + k0 + 2 * kp;
                aHr[i] = *(const __half2*)(hHi + off);
                aLr[i] = *(const __half2*)(hLo + off);
            } else {
                aHr[i] = __halves2half2(__ushort_as_half(0), __ushort_as_half(0));
                aLr[i] = aHr[i];
            }
        }
    };
    auto loadB = [&](int k0) {
        int row = tid >> 3, kp = tid & 7;    // row 0..31
        int gate = row >> 3, jj = row & 7;
        int j = j0 + jj;
        int k = k0 + 2 * kp;
        float x = 0.f, y = 0.f;
        if (j < H && k < K) {
            const float* wp = Whh + (size_t)(gate * H + j) * K + k;
            if (k + 1 < K) { float2 v = *(const float2*)wp; x = v.x; y = v.y; }
            else           { x = wp[0]; }
        }
        bRr = make_float2(x, y);
    };
    auto storeStage = [&]() {
#pragma unroll
        for (int i = 0; i < 3; i++) {
            int e = tid + i * 256;
            int row = e >> 3, kp = e & 7;
            *(__half2*)&Ah[row * 16 + 2 * kp] = aHr[i];
            *(__half2*)&Al[row * 16 + 2 * kp] = aLr[i];
        }
        int row = tid >> 3, kp = tid & 7;
        __half hx = __float2half_rn(bRr.x);
        __half hy = __float2half_rn(bRr.y);
        float lx = bRr.x - __half2float(hx);
        float ly = bRr.y - __half2float(hy);
        *(__half2*)&Bh[row * 16 + 2 * kp] = __halves2half2(hx, hy);
        *(__half2*)&Bl[row * 16 + 2 * kp] =
            __halves2half2(__float2half_rn(lx), __float2half_rn(ly));
    };

    loadA(0); loadB(0);

    for (int k0 = 0; k0 < Kpad; k0 += 16) {
        __syncthreads();
        storeStage();
        __syncthreads();
        if (k0 + 16 < Kpad) { loadA(k0 + 16); loadB(k0 + 16); }

        uint32_t bF[2], blF[2];
        {
            int n0 = wn * 8 + g;
            bF[0]  = *(const uint32_t*)&Bh[n0 * 16 + 2 * t4];
            bF[1]  = *(const uint32_t*)&Bh[n0 * 16 + 2 * t4 + 8];
            blF[0] = *(const uint32_t*)&Bl[n0 * 16 + 2 * t4];
            blF[1] = *(const uint32_t*)&Bl[n0 * 16 + 2 * t4 + 8];
        }
#pragma unroll
        for (int mt = 0; mt < 3; mt++) {
            int r0 = wm * 48 + mt * 16 + g;
            uint32_t ah[4], al[4];
            ah[0] = *(const uint32_t*)&Ah[r0 * 16 + 2 * t4];
            ah[1] = *(const uint32_t*)&Ah[(r0 + 8) * 16 + 2 * t4];
            ah[2] = *(const uint32_t*)&Ah[r0 * 16 + 2 * t4 + 8];
            ah[3] = *(const uint32_t*)&Ah[(r0 + 8) * 16 + 2 * t4 + 8];
            al[0] = *(const uint32_t*)&Al[r0 * 16 + 2 * t4];
            al[1] = *(const uint32_t*)&Al[(r0 + 8) * 16 + 2 * t4];
            al[2] = *(const uint32_t*)&Al[r0 * 16 + 2 * t4 + 8];
            al[3] = *(const uint32_t*)&Al[(r0 + 8) * 16 + 2 * t4 + 8];
            mma_f16(acc[mt], ah, bF);
            mma_f16(acc[mt], al, bF);
            mma_f16(acc[mt], ah, blF);
        }
    }

    // gates tile -> smem for cross-warp exchange
#pragma unroll
    for (int mt = 0; mt < 3; mt++) {
        int r0 = wm * 48 + mt * 16 + g;
        int col = wn * 8 + 2 * t4;
        sg[r0 * 33 + col]           = acc[mt][0];
        sg[r0 * 33 + col + 1]       = acc[mt][1];
        sg[(r0 + 8) * 33 + col]     = acc[mt][2];
        sg[(r0 + 8) * 33 + col + 1] = acc[mt][3];
    }
    __syncthreads();

    // LSTM cell (rows < 80, j < H)
    for (int e = tid; e < Bb * 8; e += 256) {
        int row = e >> 3, jj = e & 7;
        int j = j0 + jj;
        if (j >= H) continue;
        const float* xr = xw_t + (size_t)row * 4 * H;
        float gi = sg[row * 33 + jj]      + xr[j];
        float gf = sg[row * 33 + 8 + jj]  + xr[H + j];
        float gg = sg[row * 33 + 16 + jj] + xr[2 * H + j];
        float go = sg[row * 33 + 24 + jj] + xr[3 * H + j];
        float cv = cst[(size_t)row * H + j];
        float cn = sigf(gf) * cv + sigf(gi) * tanhf(gg);
        float hn = sigf(go) * tanhf(cn);
        cst[(size_t)row * H + j] = cn;
        hF[(size_t)row * H + j]  = hn;
        ys_t[(size_t)row * H + j] = hn;
        __half hh = __float2half_rn(hn);
        hHiO[(size_t)row * Kpad + j] = hh;
        hLoO[(size_t)row * Kpad + j] = __float2half_rn(hn - __half2float(hh));
    }
}

// ---------------- prep: h0 -> hi/lo planes (zero both ping-pong bufs) --------
__global__ void prep_h_kernel(const float* __restrict__ h0,
                              __half* __restrict__ hHi0, __half* __restrict__ hLo0,
                              __half* __restrict__ hHi1, __half* __restrict__ hLo1,
                              int H, int Kpad)
{
    int idx = blockIdx.x * blockDim.x + threadIdx.x;
    if (idx >= Bb * Kpad) return;
    int row = idx / Kpad, j = idx - row * Kpad;
    float v = (j < H) ? h0[(size_t)row * H + j] : 0.f;
    __half hh = __float2half_rn(v);
    hHi0[idx] = hh;
    hLo0[idx] = __float2half_rn(v - __half2float(hh));
    hHi1[idx] = __ushort_as_half(0);
    hLo1[idx] = __ushort_as_half(0);
}

__global__ void copy_f32(float* __restrict__ dst, const float* __restrict__ src, int n) {
    int i = blockIdx.x * blockDim.x + threadIdx.x;
    if (i < n) dst[i] = src[i];
}

// ---------------- host orchestration ----------------
static inline int ceil_div(int a, int b) { return (a + b - 1) / b; }

extern "C" void kernel_launch(void* const* d_in, const int* in_sizes, int n_in,
                              void* d_out, int out_size)
{
    const int*   tokens = (const int*)d_in[0];
    const float* emb_W  = (const float*)d_in[1];
    const float* dec_W  = (const float*)d_in[2];
    const float* dec_b  = (const float*)d_in[3];

    const float *Wih[3], *Whh[3], *bih[3], *bhh[3], *h0[3], *c0[3];
    for (int l = 0; l < 3; l++) {
        int base = 4 + l * 6;
        Wih[l] = (const float*)d_in[base + 0];
        Whh[l] = (const float*)d_in[base + 1];
        bih[l] = (const float*)d_in[base + 2];
        bhh[l] = (const float*)d_in[base + 3];
        h0[l]  = (const float*)d_in[base + 4];
        c0[l]  = (const float*)d_in[base + 5];
    }

    float *pX0, *pX1, *pXW, *ph, *pc;
    __half *pHi, *pLo;
    cudaGetSymbolAddress((void**)&pX0, g_X0);
    cudaGetSymbolAddress((void**)&pX1, g_X1);
    cudaGetSymbolAddress((void**)&pXW, g_XW);
    cudaGetSymbolAddress((void**)&ph,  g_h);
    cudaGetSymbolAddress((void**)&pc,  g_c);
    cudaGetSymbolAddress((void**)&pHi, g_hHi);
    cudaGetSymbolAddress((void**)&pLo, g_hLo);

    float* out = (float*)d_out;

    // 1) embedding
    {
        int n = TB * Ee;
        embed_kernel<<<ceil_div(n, 256), 256>>>(tokens, emb_W, pX0, n);
    }

    const int In[3]   = {Ee, Hh, Hh};
    const int Hd[3]   = {Hh, Hh, Ee};
    const int Kp[3]   = {1152, 1152, 400};
    float* xin  = pX0;
    float* xout = pX1;
    size_t out_off = (size_t)TB * Vv;

    for (int l = 0; l < 3; l++) {
        int I = In[l], H = Hd[l], N4 = 4 * H, Kpad = Kp[l];

        // xW = x @ Wih^T + bih + bhh  — 3-pass fp16 tensor path
        {
            dim3 grid(ceil_div(N4, 128), ceil_div(TB, 128));
            hgemm3_nt_bias<<<grid, 256>>>(xin, Wih[l], bih[l], bhh[l], pXW, TB, N4, I);
        }

        // init h planes + c
        {
            int n = Bb * Kpad;
            prep_h_kernel<<<ceil_div(n, 256), 256>>>(
                h0[l], pHi, pLo, pHi + Bb * KPAD_MAX, pLo + Bb * KPAD_MAX, H, Kpad);
            copy_f32<<<ceil_div(Bb * H, 256), 256>>>(pc, c0[l], Bb * H);
        }

        int NJ = ceil_div(H, 8);
        for (int t = 0; t < Tt; t++) {
            int pin  = (t & 1);
            int pout = 1 - pin;
            const float* xw_t = pXW + (size_t)t * Bb * N4;
            float* ys_t = xout + (size_t)t * Bb * H;
            rec_step_kernel<<<NJ, 256>>>(
                pHi + (size_t)pin * Bb * KPAD_MAX,  pLo + (size_t)pin * Bb * KPAD_MAX,
                Whh[l], xw_t, pc,
                pHi + (size_t)pout * Bb * KPAD_MAX, pLo + (size_t)pout * Bb * KPAD_MAX,
                ph, ys_t, H, Kpad);
        }

        copy_f32<<<ceil_div(Bb * H, 256), 256>>>(out + out_off, ph, Bb * H);
        out_off += (size_t)Bb * H;
        copy_f32<<<ceil_div(Bb * H, 256), 256>>>(out + out_off, pc, Bb * H);
        out_off += (size_t)Bb * H;

        float* tmp = xin; xin = xout; xout = tmp;
    }

    // 2) decoder: decoded = ys @ dec_W^T + dec_b — 1-pass tf32
    {
        dim3 grid(ceil_div(Vv, 128), ceil_div(TB, 128));
        tgemm_nt_bias<<<grid, 256>>>(xin, dec_W, dec_b, out, TB, Vv, Ee);
    }
}

// round 4
// speedup vs baseline: 2.0472x; 1.0843x over previous
#include <cuda_runtime.h>
#include <cuda_fp16.h>
#include <math.h>
#include <stdint.h>

// Problem constants
#define Tt 70
#define Bb 80
#define Vv 33278
#define Ee 400
#define Hh 1150
#define TB (Tt*Bb)          // 5600
#define KPAD_MAX 1152

// ---------------- scratch (device globals; no allocation) ----------------
__device__ float  g_X0[(size_t)TB * Hh];
__device__ float  g_X1[(size_t)TB * Hh];
__device__ float  g_XW[(size_t)TB * 4 * Hh];
__device__ float  g_c[Bb * Hh];
__device__ __half g_hHi[2][Bb * KPAD_MAX];
__device__ __half g_hLo[2][Bb * KPAD_MAX];
__device__ unsigned g_bar;

// ---------------- embedding gather ----------------
__global__ void embed_kernel(const int* __restrict__ tokens,
                             const float* __restrict__ emb,
                             float* __restrict__ x, int n) {
    int idx = blockIdx.x * blockDim.x + threadIdx.x;
    if (idx >= n) return;
    int tb = idx / Ee;
    int e  = idx - tb * Ee;
    x[idx] = emb[(size_t)tokens[tb] * Ee + e];
}

// ---------------- mma wrappers ----------------
__device__ __forceinline__ float to_tf32(float x) {
    uint32_t u;
    asm("cvt.rna.tf32.f32 %0, %1;" : "=r"(u) : "f"(x));
    return __uint_as_float(u);
}

__device__ __forceinline__ void mma_tf32(float* c, const uint32_t* a, const uint32_t* b) {
    asm volatile(
        "mma.sync.aligned.m16n8k8.row.col.f32.tf32.tf32.f32 "
        "{%0,%1,%2,%3}, {%4,%5,%6,%7}, {%8,%9}, {%0,%1,%2,%3};"
        : "+f"(c[0]), "+f"(c[1]), "+f"(c[2]), "+f"(c[3])
        : "r"(a[0]), "r"(a[1]), "r"(a[2]), "r"(a[3]), "r"(b[0]), "r"(b[1]));
}

__device__ __forceinline__ void mma_f16(float* c, const uint32_t* a, const uint32_t* b) {
    asm volatile(
        "mma.sync.aligned.m16n8k16.row.col.f32.f16.f16.f32 "
        "{%0,%1,%2,%3}, {%4,%5,%6,%7}, {%8,%9}, {%0,%1,%2,%3};"
        : "+f"(c[0]), "+f"(c[1]), "+f"(c[2]), "+f"(c[3])
        : "r"(a[0]), "r"(a[1]), "r"(a[2]), "r"(a[3]), "r"(b[0]), "r"(b[1]));
}

// ============================================================================
// 3-pass fp16 GEMM: C = A[M,K] * W[N,K]^T + bias0 + bias1  (fp32-accurate)
// ============================================================================
__global__ __launch_bounds__(256)
void hgemm3_nt_bias(const float* __restrict__ A, const float* __restrict__ W,
                    const float* __restrict__ bias0, const float* __restrict__ bias1,
                    float* __restrict__ C, int M, int N, int K)
{
    __shared__ __half AsH[128 * 16];
    __shared__ __half AsL[128 * 16];
    __shared__ __half BsH[128 * 16];
    __shared__ __half BsL[128 * 16];

    const int tid  = threadIdx.x;
    const int lane = tid & 31;
    const int warp = tid >> 5;
    const int wm   = warp >> 2;
    const int wn   = warp & 3;
    const int g    = lane >> 2;
    const int t4   = lane & 3;
    const int bm   = blockIdx.y * 128;
    const int bn   = blockIdx.x * 128;

    float acc[4][4][4];
#pragma unroll
    for (int i = 0; i < 4; i++)
#pragma unroll
        for (int j = 0; j < 4; j++)
#pragma unroll
            for (int q = 0; q < 4; q++) acc[i][j][q] = 0.f;

    float2 aR[4], bR[4];

    auto load_stage = [&](int k0) {
#pragma unroll
        for (int i = 0; i < 4; i++) {
            int gg = tid + i * 256;
            int m  = gg >> 3;
            int gk = k0 + ((gg & 7) << 1);
            int gm = bm + m;
            aR[i] = (gm < M && gk < K) ? *(const float2*)(A + (size_t)gm * K + gk)
                                       : make_float2(0.f, 0.f);
            int gn = bn + m;
            bR[i] = (gn < N && gk < K) ? *(const float2*)(W + (size_t)gn * K + gk)
                                       : make_float2(0.f, 0.f);
        }
    };

    auto store_stage = [&]() {
#pragma unroll
        for (int i = 0; i < 4; i++) {
            int gg = tid + i * 256;
            int m  = gg >> 3;
            int kp = gg & 7;
            {
                __half hx = __float2half_rn(aR[i].x);
                __half hy = __float2half_rn(aR[i].y);
                float lx = aR[i].x - __half2float(hx);
                float ly = aR[i].y - __half2float(hy);
                *(__half2*)&AsH[m * 16 + 2 * kp] = __halves2half2(hx, hy);
                *(__half2*)&AsL[m * 16 + 2 * kp] =
                    __halves2half2(__float2half_rn(lx), __float2half_rn(ly));
            }
            {
                __half hx = __float2half_rn(bR[i].x);
                __half hy = __float2half_rn(bR[i].y);
                float lx = bR[i].x - __half2float(hx);
                float ly = bR[i].y - __half2float(hy);
                *(__half2*)&BsH[m * 16 + 2 * kp] = __halves2half2(hx, hy);
                *(__half2*)&BsL[m * 16 + 2 * kp] =
                    __halves2half2(__float2half_rn(lx), __float2half_rn(ly));
            }
        }
    };

    load_stage(0);

    for (int k0 = 0; k0 < K; k0 += 16) {
        __syncthreads();
        store_stage();
        __syncthreads();
        if (k0 + 16 < K) load_stage(k0 + 16);

        uint32_t ah[4][4], al[4][4], bh[4][2], bl[4][2];
#pragma unroll
        for (int mt = 0; mt < 4; mt++) {
            int r0 = wm * 64 + mt * 16 + g;
            ah[mt][0] = *(const uint32_t*)&AsH[r0 * 16 + 2 * t4];
            ah[mt][1] = *(const uint32_t*)&AsH[(r0 + 8) * 16 + 2 * t4];
            ah[mt][2] = *(const uint32_t*)&AsH[r0 * 16 + 2 * t4 + 8];
            ah[mt][3] = *(const uint32_t*)&AsH[(r0 + 8) * 16 + 2 * t4 + 8];
            al[mt][0] = *(const uint32_t*)&AsL[r0 * 16 + 2 * t4];
            al[mt][1] = *(const uint32_t*)&AsL[(r0 + 8) * 16 + 2 * t4];
            al[mt][2] = *(const uint32_t*)&AsL[r0 * 16 + 2 * t4 + 8];
            al[mt][3] = *(const uint32_t*)&AsL[(r0 + 8) * 16 + 2 * t4 + 8];
        }
#pragma unroll
        for (int nt = 0; nt < 4; nt++) {
            int n0 = wn * 32 + nt * 8 + g;
            bh[nt][0] = *(const uint32_t*)&BsH[n0 * 16 + 2 * t4];
            bh[nt][1] = *(const uint32_t*)&BsH[n0 * 16 + 2 * t4 + 8];
            bl[nt][0] = *(const uint32_t*)&BsL[n0 * 16 + 2 * t4];
            bl[nt][1] = *(const uint32_t*)&BsL[n0 * 16 + 2 * t4 + 8];
        }
#pragma unroll
        for (int mt = 0; mt < 4; mt++)
#pragma unroll
            for (int nt = 0; nt < 4; nt++) {
                mma_f16(acc[mt][nt], ah[mt], bh[nt]);
                mma_f16(acc[mt][nt], al[mt], bh[nt]);
                mma_f16(acc[mt][nt], ah[mt], bl[nt]);
            }
    }

#pragma unroll
    for (int mt = 0; mt < 4; mt++) {
#pragma unroll
        for (int nt = 0; nt < 4; nt++) {
            int r0 = bm + wm * 64 + mt * 16 + g;
            int cc = bn + wn * 32 + nt * 8 + 2 * t4;
            if (cc >= N) continue;
            float bv0 = 0.f, bv1 = 0.f;
            if (bias0) { bv0 += bias0[cc]; bv1 += bias0[cc + 1]; }
            if (bias1) { bv0 += bias1[cc]; bv1 += bias1[cc + 1]; }
            if (r0 < M)
                *(float2*)(C + (size_t)r0 * N + cc) =
                    make_float2(acc[mt][nt][0] + bv0, acc[mt][nt][1] + bv1);
            if (r0 + 8 < M)
                *(float2*)(C + (size_t)(r0 + 8) * N + cc) =
                    make_float2(acc[mt][nt][2] + bv0, acc[mt][nt][3] + bv1);
        }
    }
}

// ============================================================================
// 1-pass tf32 GEMM (decoder)
// ============================================================================
__global__ __launch_bounds__(256)
void tgemm_nt_bias(const float* __restrict__ A, const float* __restrict__ W,
                   const float* __restrict__ bias0,
                   float* __restrict__ C, int M, int N, int K)
{
    __shared__ float AsH[16 * 128];
    __shared__ float BsH[16 * 128];

    const int tid  = threadIdx.x;
    const int lane = tid & 31;
    const int warp = tid >> 5;
    const int wm   = warp >> 2;
    const int wn   = warp & 3;
    const int gid  = lane >> 2;
    const int tig  = lane & 3;
    const int bm   = blockIdx.y * 128;
    const int bn   = blockIdx.x * 128;

    float acc[4][4][4];
#pragma unroll
    for (int i = 0; i < 4; i++)
#pragma unroll
        for (int j = 0; j < 4; j++)
#pragma unroll
            for (int q = 0; q < 4; q++) acc[i][j][q] = 0.f;

    float2 aR[4], bR[4];

    auto load_stage = [&](int k0) {
#pragma unroll
        for (int i = 0; i < 4; i++) {
            int g  = tid + i * 256;
            int m  = g >> 3;
            int gk = k0 + ((g & 7) << 1);
            int gm = bm + m;
            aR[i] = (gm < M && gk < K) ? *(const float2*)(A + (size_t)gm * K + gk)
                                       : make_float2(0.f, 0.f);
            int gn = bn + m;
            bR[i] = (gn < N && gk < K) ? *(const float2*)(W + (size_t)gn * K + gk)
                                       : make_float2(0.f, 0.f);
        }
    };

    auto store_stage = [&]() {
#pragma unroll
        for (int i = 0; i < 4; i++) {
            int g = tid + i * 256;
            int m = g >> 3;
            int kq = (g & 7) << 1;
#pragma unroll
            for (int j = 0; j < 2; j++) {
                int k = kq + j;
                int idx = k * 128 + (m ^ ((9 * k) & 28));
                AsH[idx] = to_tf32((j == 0) ? aR[i].x : aR[i].y);
                BsH[idx] = to_tf32((j == 0) ? bR[i].x : bR[i].y);
            }
        }
    };

    load_stage(0);

    for (int k0 = 0; k0 < K; k0 += 16) {
        __syncthreads();
        store_stage();
        __syncthreads();
        if (k0 + 16 < K) load_stage(k0 + 16);

#pragma unroll
        for (int ks = 0; ks < 2; ks++) {
            const int k1 = ks * 8 + tig;
            const int k2 = k1 + 4;
            const int s1 = (9 * k1) & 28;
            const int s2 = (9 * k2) & 28;
            const int o1 = k1 * 128;
            const int o2 = k2 * 128;

            uint32_t ah[4][4], bh[4][2];
#pragma unroll
            for (int mt = 0; mt < 4; mt++) {
                int mb = wm * 64 + mt * 16 + gid;
                ah[mt][0] = __float_as_uint(AsH[o1 + (mb ^ s1)]);
                ah[mt][1] = __float_as_uint(AsH[o1 + ((mb + 8) ^ s1)]);
                ah[mt][2] = __float_as_uint(AsH[o2 + (mb ^ s2)]);
                ah[mt][3] = __float_as_uint(AsH[o2 + ((mb + 8) ^ s2)]);
            }
#pragma unroll
            for (int nt = 0; nt < 4; nt++) {
                int nb = wn * 32 + nt * 8 + gid;
                bh[nt][0] = __float_as_uint(BsH[o1 + (nb ^ s1)]);
                bh[nt][1] = __float_as_uint(BsH[o2 + (nb ^ s2)]);
            }
#pragma unroll
            for (int mt = 0; mt < 4; mt++)
#pragma unroll
                for (int nt = 0; nt < 4; nt++)
                    mma_tf32(acc[mt][nt], ah[mt], bh[nt]);
        }
    }

#pragma unroll
    for (int mt = 0; mt < 4; mt++) {
#pragma unroll
        for (int nt = 0; nt < 4; nt++) {
            int r0 = bm + wm * 64 + mt * 16 + gid;
            int cc = bn + wn * 32 + nt * 8 + 2 * tig;
            if (cc >= N) continue;
            float bv0 = bias0 ? bias0[cc] : 0.f;
            float bv1 = bias0 ? bias0[cc + 1] : 0.f;
            if (r0 < M)
                *(float2*)(C + (size_t)r0 * N + cc) =
                    make_float2(acc[mt][nt][0] + bv0, acc[mt][nt][1] + bv1);
            if (r0 + 8 < M)
                *(float2*)(C + (size_t)(r0 + 8) * N + cc) =
                    make_float2(acc[mt][nt][2] + bv0, acc[mt][nt][3] + bv1);
        }
    }
}

// ============================================================================
// Persistent recurrent layer kernel: all Tt steps in one launch.
// Grid = NJ CTAs (NJ = ceil(H/8)); CTA owns 8 hidden units x 4 gates = 32 rows
// of Whh, cached in smem as fp16 hi/lo for the whole layer. Global barrier
// (monotonic atomic counter) between steps. 8 warps: wm(2) x wn(4 = gate).
// ============================================================================
__device__ __forceinline__ float sigf(float x) { return 1.f / (1.f + expf(-x)); }

#define ASTR 24   // A-tile row stride in halves (conflict-free)

__global__ __launch_bounds__(256, 1)
void rec_persist(const float* __restrict__ Whh, const float* __restrict__ xw,
                 float* __restrict__ cst,
                 __half* __restrict__ hi0, __half* __restrict__ lo0,
                 __half* __restrict__ hi1, __half* __restrict__ lo1,
                 float* __restrict__ ys, int H, int Kpad, int NJ)
{
    extern __shared__ char smem_raw[];
    const int BSTR = Kpad + 8;               // B row stride (halves), conflict-free
    __half* Bh = (__half*)smem_raw;          // [32][BSTR]
    __half* Bl = Bh + 32 * BSTR;
    __half* Ah = Bl + 32 * BSTR;             // [2 bufs][96][ASTR]
    __half* Al = Ah + 2 * 96 * ASTR;
    float*  sg = (float*)(Al + 2 * 96 * ASTR);  // [96][33]

    const int tid  = threadIdx.x;
    const int lane = tid & 31;
    const int warp = tid >> 5;
    const int wm   = warp >> 2;
    const int wn   = warp & 3;               // = gate
    const int g    = lane >> 2;
    const int t4   = lane & 3;
    const int j0   = blockIdx.x * 8;
    const int NC   = Kpad / 16;

    // ---- prologue: load + split this CTA's 32 Whh rows into smem ----
    {
        int Kh = Kpad >> 1;
        for (int idx = tid; idx < 32 * Kh; idx += 256) {
            int r  = idx / Kh;
            int kp = idx - r * Kh;
            int k  = 2 * kp;
            int gate = r >> 3, jj = r & 7;
            int j = j0 + jj;
            float x = 0.f, y = 0.f;
            if (j < H) {
                const float* wp = Whh + (size_t)(gate * H + j) * H;
                if (k < H)     x = wp[k];
                if (k + 1 < H) y = wp[k + 1];
            }
            __half hx = __float2half_rn(x);
            __half hy = __float2half_rn(y);
            *(__half2*)&Bh[r * BSTR + k] = __halves2half2(hx, hy);
            *(__half2*)&Bl[r * BSTR + k] =
                __halves2half2(__float2half_rn(x - __half2float(hx)),
                               __float2half_rn(y - __half2float(hy)));
        }
    }
    __syncthreads();

    __half2 aHr[3], aLr[3];

    for (int t = 0; t < Tt; t++) {
        const __half* hiR = (t & 1) ? hi1 : hi0;
        const __half* loR = (t & 1) ? lo1 : lo0;
        __half* hiW = (t & 1) ? hi0 : hi1;
        __half* loW = (t & 1) ? lo0 : lo1;
        const float* xw_t = xw + (size_t)t * Bb * 4 * H;

        float acc[3][4];
#pragma unroll
        for (int i = 0; i < 3; i++)
#pragma unroll
            for (int q = 0; q < 4; q++) acc[i][q] = 0.f;

        // prefetch chunk 0 A regs
#pragma unroll
        for (int i = 0; i < 3; i++) {
            int e = tid + i * 256;
            int row = e >> 3, kp = e & 7;
            if (row < Bb) {
                size_t off = (size_t)row * Kpad + 2 * kp;
                aHr[i] = *(const __half2*)(hiR + off);
                aLr[i] = *(const __half2*)(loR + off);
            } else {
                aHr[i] = __halves2half2(__ushort_as_half(0), __ushort_as_half(0));
                aLr[i] = aHr[i];
            }
        }

        for (int c = 0; c < NC; c++) {
            const int buf = c & 1;
            __half* AhB = Ah + buf * 96 * ASTR;
            __half* AlB = Al + buf * 96 * ASTR;

            // store staged A regs
#pragma unroll
            for (int i = 0; i < 3; i++) {
                int e = tid + i * 256;
                int row = e >> 3, kp = e & 7;
                *(__half2*)&AhB[row * ASTR + 2 * kp] = aHr[i];
                *(__half2*)&AlB[row * ASTR + 2 * kp] = aLr[i];
            }
            __syncthreads();

            // prefetch next chunk
            if (c + 1 < NC) {
                int k0n = (c + 1) * 16;
#pragma unroll
                for (int i = 0; i < 3; i++) {
                    int e = tid + i * 256;
                    int row = e >> 3, kp = e & 7;
                    if (row < Bb) {
                        size_t off = (size_t)row * Kpad + k0n + 2 * kp;
                        aHr[i] = *(const __half2*)(hiR + off);
                        aLr[i] = *(const __half2*)(loR + off);
                    } else {
                        aHr[i] = __halves2half2(__ushort_as_half(0), __ushort_as_half(0));
                        aLr[i] = aHr[i];
                    }
                }
            }

            // consume: B frags from resident smem, A frags from staged tile
            const int k0 = c * 16;
            uint32_t bF[2], blF[2];
            {
                int n0 = wn * 8 + g;
                bF[0]  = *(const uint32_t*)&Bh[n0 * BSTR + k0 + 2 * t4];
                bF[1]  = *(const uint32_t*)&Bh[n0 * BSTR + k0 + 2 * t4 + 8];
                blF[0] = *(const uint32_t*)&Bl[n0 * BSTR + k0 + 2 * t4];
                blF[1] = *(const uint32_t*)&Bl[n0 * BSTR + k0 + 2 * t4 + 8];
            }
#pragma unroll
            for (int mt = 0; mt < 3; mt++) {
                int r0 = wm * 48 + mt * 16 + g;
                uint32_t ah[4], al[4];
                ah[0] = *(const uint32_t*)&AhB[r0 * ASTR + 2 * t4];
                ah[1] = *(const uint32_t*)&AhB[(r0 + 8) * ASTR + 2 * t4];
                ah[2] = *(const uint32_t*)&AhB[r0 * ASTR + 2 * t4 + 8];
                ah[3] = *(const uint32_t*)&AhB[(r0 + 8) * ASTR + 2 * t4 + 8];
                al[0] = *(const uint32_t*)&AlB[r0 * ASTR + 2 * t4];
                al[1] = *(const uint32_t*)&AlB[(r0 + 8) * ASTR + 2 * t4];
                al[2] = *(const uint32_t*)&AlB[r0 * ASTR + 2 * t4 + 8];
                al[3] = *(const uint32_t*)&AlB[(r0 + 8) * ASTR + 2 * t4 + 8];
                mma_f16(acc[mt], ah, bF);
                mma_f16(acc[mt], al, bF);
                mma_f16(acc[mt], ah, blF);
            }
        }

        // gates -> smem exchange
        __syncthreads();   // all warps done reading A bufs before sg reuse is irrelevant, but ensures chunk loop done
#pragma unroll
        for (int mt = 0; mt < 3; mt++) {
            int r0 = wm * 48 + mt * 16 + g;
            int col = wn * 8 + 2 * t4;
            sg[r0 * 33 + col]           = acc[mt][0];
            sg[r0 * 33 + col + 1]       = acc[mt][1];
            sg[(r0 + 8) * 33 + col]     = acc[mt][2];
            sg[(r0 + 8) * 33 + col + 1] = acc[mt][3];
        }
        __syncthreads();

        // LSTM cell
        for (int e = tid; e < Bb * 8; e += 256) {
            int row = e >> 3, jj = e & 7;
            int j = j0 + jj;
            if (j >= H) continue;
            const float* xr = xw_t + (size_t)row * 4 * H;
            float gi = sg[row * 33 + jj]      + xr[j];
            float gf = sg[row * 33 + 8 + jj]  + xr[H + j];
            float gg = sg[row * 33 + 16 + jj] + xr[2 * H + j];
            float go = sg[row * 33 + 24 + jj] + xr[3 * H + j];
            float cv = cst[(size_t)row * H + j];
            float cn = sigf(gf) * cv + sigf(gi) * tanhf(gg);
            float hn = sigf(go) * tanhf(cn);
            cst[(size_t)row * H + j]  = cn;
            ys[(size_t)t * Bb * H + (size_t)row * H + j] = hn;
            __half hh = __float2half_rn(hn);
            hiW[(size_t)row * Kpad + j] = hh;
            loW[(size_t)row * Kpad + j] = __float2half_rn(hn - __half2float(hh));
        }

        // ---- device-wide barrier (monotonic counter) ----
        __syncthreads();
        if (tid == 0) {
            __threadfence();
            atomicAdd(&g_bar, 1u);
            unsigned target = (unsigned)NJ * (unsigned)(t + 1);
            while (*(volatile unsigned*)&g_bar < target) { }
            __threadfence();
        }
        __syncthreads();
    }
}

// ---------------- prep: h0 -> hi/lo planes, zero pong bufs, zero barrier ----
__global__ void prep_h_kernel(const float* __restrict__ h0,
                              __half* __restrict__ hHi0, __half* __restrict__ hLo0,
                              __half* __restrict__ hHi1, __half* __restrict__ hLo1,
                              int H, int Kpad)
{
    int idx = blockIdx.x * blockDim.x + threadIdx.x;
    if (idx == 0) g_bar = 0;
    if (idx >= Bb * Kpad) return;
    int row = idx / Kpad, j = idx - row * Kpad;
    float v = (j < H) ? h0[(size_t)row * H + j] : 0.f;
    __half hh = __float2half_rn(v);
    hHi0[idx] = hh;
    hLo0[idx] = __float2half_rn(v - __half2float(hh));
    hHi1[idx] = __ushort_as_half(0);
    hLo1[idx] = __ushort_as_half(0);
}

__global__ void copy_f32(float* __restrict__ dst, const float* __restrict__ src, int n) {
    int i = blockIdx.x * blockDim.x + threadIdx.x;
    if (i < n) dst[i] = src[i];
}

// ---------------- host orchestration ----------------
static inline int ceil_div(int a, int b) { return (a + b - 1) / b; }

extern "C" void kernel_launch(void* const* d_in, const int* in_sizes, int n_in,
                              void* d_out, int out_size)
{
    const int*   tokens = (const int*)d_in[0];
    const float* emb_W  = (const float*)d_in[1];
    const float* dec_W  = (const float*)d_in[2];
    const float* dec_b  = (const float*)d_in[3];

    const float *Wih[3], *Whh[3], *bih[3], *bhh[3], *h0[3], *c0[3];
    for (int l = 0; l < 3; l++) {
        int base = 4 + l * 6;
        Wih[l] = (const float*)d_in[base + 0];
        Whh[l] = (const float*)d_in[base + 1];
        bih[l] = (const float*)d_in[base + 2];
        bhh[l] = (const float*)d_in[base + 3];
        h0[l]  = (const float*)d_in[base + 4];
        c0[l]  = (const float*)d_in[base + 5];
    }

    float *pX0, *pX1, *pXW, *pc;
    __half *pHi, *pLo;
    cudaGetSymbolAddress((void**)&pX0, g_X0);
    cudaGetSymbolAddress((void**)&pX1, g_X1);
    cudaGetSymbolAddress((void**)&pXW, g_XW);
    cudaGetSymbolAddress((void**)&pc,  g_c);
    cudaGetSymbolAddress((void**)&pHi, g_hHi);
    cudaGetSymbolAddress((void**)&pLo, g_hLo);

    float* out = (float*)d_out;

    // opt-in smem for the persistent kernel (max layer: Kpad=1152)
    {
        int maxBytes = 2 * 32 * (KPAD_MAX + 8) * 2   // B hi+lo
                     + 2 * 2 * 96 * ASTR * 2          // A bufs hi+lo
                     + 96 * 33 * 4;                   // sg
        cudaFuncSetAttribute(rec_persist,
                             cudaFuncAttributeMaxDynamicSharedMemorySize, maxBytes);
    }

    // 1) embedding
    {
        int n = TB * Ee;
        embed_kernel<<<ceil_div(n, 256), 256>>>(tokens, emb_W, pX0, n);
    }

    const int In[3] = {Ee, Hh, Hh};
    const int Hd[3] = {Hh, Hh, Ee};
    const int Kp[3] = {1152, 1152, 400};
    float* xin  = pX0;
    float* xout = pX1;
    size_t out_off = (size_t)TB * Vv;

    for (int l = 0; l < 3; l++) {
        int I = In[l], H = Hd[l], N4 = 4 * H, Kpad = Kp[l];

        // xW = x @ Wih^T + bih + bhh  — 3-pass fp16 tensor path
        {
            dim3 grid(ceil_div(N4, 128), ceil_div(TB, 128));
            hgemm3_nt_bias<<<grid, 256>>>(xin, Wih[l], bih[l], bhh[l], pXW, TB, N4, I);
        }

        // init h planes + barrier + c
        {
            int n = Bb * Kpad;
            prep_h_kernel<<<ceil_div(n, 256), 256>>>(
                h0[l], pHi, pLo, pHi + Bb * KPAD_MAX, pLo + Bb * KPAD_MAX, H, Kpad);
            copy_f32<<<ceil_div(Bb * H, 256), 256>>>(pc, c0[l], Bb * H);
        }

        // persistent recurrent kernel (all Tt steps)
        {
            int NJ = ceil_div(H, 8);
            int smemBytes = 2 * 32 * (Kpad + 8) * 2
                          + 2 * 2 * 96 * ASTR * 2
                          + 96 * 33 * 4;
            rec_persist<<<NJ, 256, smemBytes>>>(
                Whh[l], pXW, pc,
                pHi, pLo, pHi + Bb * KPAD_MAX, pLo + Bb * KPAD_MAX,
                xout, H, Kpad, NJ);
        }

        // export hT (= ys[t=Tt-1]) and cT
        copy_f32<<<ceil_div(Bb * H, 256), 256>>>(
            out + out_off, xout + (size_t)(Tt - 1) * Bb * H, Bb * H);
        out_off += (size_t)Bb * H;
        copy_f32<<<ceil_div(Bb * H, 256), 256>>>(out + out_off, pc, Bb * H);
        out_off += (size_t)Bb * H;

        float* tmp = xin; xin = xout; xout = tmp;
    }

    // 2) decoder: decoded = ys @ dec_W^T + dec_b — 1-pass tf32
    {
        dim3 grid(ceil_div(Vv, 128), ceil_div(TB, 128));
        tgemm_nt_bias<<<grid, 256>>>(xin, dec_W, dec_b, out, TB, Vv, Ee);
    }
}

// round 5
// speedup vs baseline: 3.0999x; 1.5142x over previous
#include <cuda_runtime.h>
#include <cuda_fp16.h>
#include <math.h>
#include <stdint.h>

// Problem constants
#define Tt 70
#define Bb 80
#define Vv 33278
#define Ee 400
#define Hh 1150
#define TB (Tt*Bb)          // 5600
#define KPAD_MAX 1152

// ---------------- scratch (device globals; no allocation) ----------------
__device__ float  g_X0[(size_t)TB * Hh];
__device__ float  g_X1[(size_t)TB * Hh];
__device__ float  g_XW[(size_t)TB * 4 * Hh];
__device__ float  g_c[Bb * Hh];
__device__ __half g_hHi[2][Bb * KPAD_MAX];
__device__ __half g_hLo[2][Bb * KPAD_MAX];
__device__ unsigned g_bar;

// ---------------- embedding gather ----------------
__global__ void embed_kernel(const int* __restrict__ tokens,
                             const float* __restrict__ emb,
                             float* __restrict__ x, int n) {
    int idx = blockIdx.x * blockDim.x + threadIdx.x;
    if (idx >= n) return;
    int tb = idx / Ee;
    int e  = idx - tb * Ee;
    x[idx] = emb[(size_t)tokens[tb] * Ee + e];
}

// ---------------- ptx helpers ----------------
__device__ __forceinline__ float to_tf32(float x) {
    uint32_t u;
    asm("cvt.rna.tf32.f32 %0, %1;" : "=r"(u) : "f"(x));
    return __uint_as_float(u);
}

__device__ __forceinline__ void mma_tf32(float* c, const uint32_t* a, const uint32_t* b) {
    asm volatile(
        "mma.sync.aligned.m16n8k8.row.col.f32.tf32.tf32.f32 "
        "{%0,%1,%2,%3}, {%4,%5,%6,%7}, {%8,%9}, {%0,%1,%2,%3};"
        : "+f"(c[0]), "+f"(c[1]), "+f"(c[2]), "+f"(c[3])
        : "r"(a[0]), "r"(a[1]), "r"(a[2]), "r"(a[3]), "r"(b[0]), "r"(b[1]));
}

__device__ __forceinline__ void mma_f16(float* c, const uint32_t* a, const uint32_t* b) {
    asm volatile(
        "mma.sync.aligned.m16n8k16.row.col.f32.f16.f16.f32 "
        "{%0,%1,%2,%3}, {%4,%5,%6,%7}, {%8,%9}, {%0,%1,%2,%3};"
        : "+f"(c[0]), "+f"(c[1]), "+f"(c[2]), "+f"(c[3])
        : "r"(a[0]), "r"(a[1]), "r"(a[2]), "r"(a[3]), "r"(b[0]), "r"(b[1]));
}

__device__ __forceinline__ uint32_t smem_u32(const void* p) {
    return (uint32_t)__cvta_generic_to_shared(p);
}
__device__ __forceinline__ void ldsm4(uint32_t* r, uint32_t addr) {
    asm volatile("ldmatrix.sync.aligned.m8n8.x4.shared.b16 {%0,%1,%2,%3}, [%4];"
                 : "=r"(r[0]), "=r"(r[1]), "=r"(r[2]), "=r"(r[3]) : "r"(addr));
}
__device__ __forceinline__ void cp_async16(uint32_t dst, const void* src) {
    asm volatile("cp.async.cg.shared.global [%0], [%1], 16;" :: "r"(dst), "l"(src));
}
__device__ __forceinline__ void cp_commit() {
    asm volatile("cp.async.commit_group;" ::: "memory");
}
__device__ __forceinline__ void cp_wait1() {
    asm volatile("cp.async.wait_group 1;" ::: "memory");
}

// ============================================================================
// 3-pass fp16 GEMM: C = A[M,K] * W[N,K]^T + bias0 + bias1  (fp32-accurate)
// ============================================================================
__global__ __launch_bounds__(256)
void hgemm3_nt_bias(const float* __restrict__ A, const float* __restrict__ W,
                    const float* __restrict__ bias0, const float* __restrict__ bias1,
                    float* __restrict__ C, int M, int N, int K)
{
    __shared__ __half AsH[128 * 16];
    __shared__ __half AsL[128 * 16];
    __shared__ __half BsH[128 * 16];
    __shared__ __half BsL[128 * 16];

    const int tid  = threadIdx.x;
    const int lane = tid & 31;
    const int warp = tid >> 5;
    const int wm   = warp >> 2;
    const int wn   = warp & 3;
    const int g    = lane >> 2;
    const int t4   = lane & 3;
    const int bm   = blockIdx.y * 128;
    const int bn   = blockIdx.x * 128;

    float acc[4][4][4];
#pragma unroll
    for (int i = 0; i < 4; i++)
#pragma unroll
        for (int j = 0; j < 4; j++)
#pragma unroll
            for (int q = 0; q < 4; q++) acc[i][j][q] = 0.f;

    float2 aR[4], bR[4];

    auto load_stage = [&](int k0) {
#pragma unroll
        for (int i = 0; i < 4; i++) {
            int gg = tid + i * 256;
            int m  = gg >> 3;
            int gk = k0 + ((gg & 7) << 1);
            int gm = bm + m;
            aR[i] = (gm < M && gk < K) ? *(const float2*)(A + (size_t)gm * K + gk)
                                       : make_float2(0.f, 0.f);
            int gn = bn + m;
            bR[i] = (gn < N && gk < K) ? *(const float2*)(W + (size_t)gn * K + gk)
                                       : make_float2(0.f, 0.f);
        }
    };

    auto store_stage = [&]() {
#pragma unroll
        for (int i = 0; i < 4; i++) {
            int gg = tid + i * 256;
            int m  = gg >> 3;
            int kp = gg & 7;
            {
                __half hx = __float2half_rn(aR[i].x);
                __half hy = __float2half_rn(aR[i].y);
                float lx = aR[i].x - __half2float(hx);
                float ly = aR[i].y - __half2float(hy);
                *(__half2*)&AsH[m * 16 + 2 * kp] = __halves2half2(hx, hy);
                *(__half2*)&AsL[m * 16 + 2 * kp] =
                    __halves2half2(__float2half_rn(lx), __float2half_rn(ly));
            }
            {
                __half hx = __float2half_rn(bR[i].x);
                __half hy = __float2half_rn(bR[i].y);
                float lx = bR[i].x - __half2float(hx);
                float ly = bR[i].y - __half2float(hy);
                *(__half2*)&BsH[m * 16 + 2 * kp] = __halves2half2(hx, hy);
                *(__half2*)&BsL[m * 16 + 2 * kp] =
                    __halves2half2(__float2half_rn(lx), __float2half_rn(ly));
            }
        }
    };

    load_stage(0);

    for (int k0 = 0; k0 < K; k0 += 16) {
        __syncthreads();
        store_stage();
        __syncthreads();
        if (k0 + 16 < K) load_stage(k0 + 16);

        uint32_t ah[4][4], al[4][4], bh[4][2], bl[4][2];
#pragma unroll
        for (int mt = 0; mt < 4; mt++) {
            int r0 = wm * 64 + mt * 16 + g;
            ah[mt][0] = *(const uint32_t*)&AsH[r0 * 16 + 2 * t4];
            ah[mt][1] = *(const uint32_t*)&AsH[(r0 + 8) * 16 + 2 * t4];
            ah[mt][2] = *(const uint32_t*)&AsH[r0 * 16 + 2 * t4 + 8];
            ah[mt][3] = *(const uint32_t*)&AsH[(r0 + 8) * 16 + 2 * t4 + 8];
            al[mt][0] = *(const uint32_t*)&AsL[r0 * 16 + 2 * t4];
            al[mt][1] = *(const uint32_t*)&AsL[(r0 + 8) * 16 + 2 * t4];
            al[mt][2] = *(const uint32_t*)&AsL[r0 * 16 + 2 * t4 + 8];
            al[mt][3] = *(const uint32_t*)&AsL[(r0 + 8) * 16 + 2 * t4 + 8];
        }
#pragma unroll
        for (int nt = 0; nt < 4; nt++) {
            int n0 = wn * 32 + nt * 8 + g;
            bh[nt][0] = *(const uint32_t*)&BsH[n0 * 16 + 2 * t4];
            bh[nt][1] = *(const uint32_t*)&BsH[n0 * 16 + 2 * t4 + 8];
            bl[nt][0] = *(const uint32_t*)&BsL[n0 * 16 + 2 * t4];
            bl[nt][1] = *(const uint32_t*)&BsL[n0 * 16 + 2 * t4 + 8];
        }
#pragma unroll
        for (int mt = 0; mt < 4; mt++)
#pragma unroll
            for (int nt = 0; nt < 4; nt++) {
                mma_f16(acc[mt][nt], ah[mt], bh[nt]);
                mma_f16(acc[mt][nt], al[mt], bh[nt]);
                mma_f16(acc[mt][nt], ah[mt], bl[nt]);
            }
    }

#pragma unroll
    for (int mt = 0; mt < 4; mt++) {
#pragma unroll
        for (int nt = 0; nt < 4; nt++) {
            int r0 = bm + wm * 64 + mt * 16 + g;
            int cc = bn + wn * 32 + nt * 8 + 2 * t4;
            if (cc >= N) continue;
            float bv0 = 0.f, bv1 = 0.f;
            if (bias0) { bv0 += bias0[cc]; bv1 += bias0[cc + 1]; }
            if (bias1) { bv0 += bias1[cc]; bv1 += bias1[cc + 1]; }
            if (r0 < M)
                *(float2*)(C + (size_t)r0 * N + cc) =
                    make_float2(acc[mt][nt][0] + bv0, acc[mt][nt][1] + bv1);
            if (r0 + 8 < M)
                *(float2*)(C + (size_t)(r0 + 8) * N + cc) =
                    make_float2(acc[mt][nt][2] + bv0, acc[mt][nt][3] + bv1);
        }
    }
}

// ============================================================================
// 1-pass tf32 GEMM (decoder)
// ============================================================================
__global__ __launch_bounds__(256)
void tgemm_nt_bias(const float* __restrict__ A, const float* __restrict__ W,
                   const float* __restrict__ bias0,
                   float* __restrict__ C, int M, int N, int K)
{
    __shared__ float AsH[16 * 128];
    __shared__ float BsH[16 * 128];

    const int tid  = threadIdx.x;
    const int lane = tid & 31;
    const int warp = tid >> 5;
    const int wm   = warp >> 2;
    const int wn   = warp & 3;
    const int gid  = lane >> 2;
    const int tig  = lane & 3;
    const int bm   = blockIdx.y * 128;
    const int bn   = blockIdx.x * 128;

    float acc[4][4][4];
#pragma unroll
    for (int i = 0; i < 4; i++)
#pragma unroll
        for (int j = 0; j < 4; j++)
#pragma unroll
            for (int q = 0; q < 4; q++) acc[i][j][q] = 0.f;

    float2 aR[4], bR[4];

    auto load_stage = [&](int k0) {
#pragma unroll
        for (int i = 0; i < 4; i++) {
            int g  = tid + i * 256;
            int m  = g >> 3;
            int gk = k0 + ((g & 7) << 1);
            int gm = bm + m;
            aR[i] = (gm < M && gk < K) ? *(const float2*)(A + (size_t)gm * K + gk)
                                       : make_float2(0.f, 0.f);
            int gn = bn + m;
            bR[i] = (gn < N && gk < K) ? *(const float2*)(W + (size_t)gn * K + gk)
                                       : make_float2(0.f, 0.f);
        }
    };

    auto store_stage = [&]() {
#pragma unroll
        for (int i = 0; i < 4; i++) {
            int g = tid + i * 256;
            int m = g >> 3;
            int kq = (g & 7) << 1;
#pragma unroll
            for (int j = 0; j < 2; j++) {
                int k = kq + j;
                int idx = k * 128 + (m ^ ((9 * k) & 28));
                AsH[idx] = to_tf32((j == 0) ? aR[i].x : aR[i].y);
                BsH[idx] = to_tf32((j == 0) ? bR[i].x : bR[i].y);
            }
        }
    };

    load_stage(0);

    for (int k0 = 0; k0 < K; k0 += 16) {
        __syncthreads();
        store_stage();
        __syncthreads();
        if (k0 + 16 < K) load_stage(k0 + 16);

#pragma unroll
        for (int ks = 0; ks < 2; ks++) {
            const int k1 = ks * 8 + tig;
            const int k2 = k1 + 4;
            const int s1 = (9 * k1) & 28;
            const int s2 = (9 * k2) & 28;
            const int o1 = k1 * 128;
            const int o2 = k2 * 128;

            uint32_t ah[4][4], bh[4][2];
#pragma unroll
            for (int mt = 0; mt < 4; mt++) {
                int mb = wm * 64 + mt * 16 + gid;
                ah[mt][0] = __float_as_uint(AsH[o1 + (mb ^ s1)]);
                ah[mt][1] = __float_as_uint(AsH[o1 + ((mb + 8) ^ s1)]);
                ah[mt][2] = __float_as_uint(AsH[o2 + (mb ^ s2)]);
                ah[mt][3] = __float_as_uint(AsH[o2 + ((mb + 8) ^ s2)]);
            }
#pragma unroll
            for (int nt = 0; nt < 4; nt++) {
                int nb = wn * 32 + nt * 8 + gid;
                bh[nt][0] = __float_as_uint(BsH[o1 + (nb ^ s1)]);
                bh[nt][1] = __float_as_uint(BsH[o2 + (nb ^ s2)]);
            }
#pragma unroll
            for (int mt = 0; mt < 4; mt++)
#pragma unroll
                for (int nt = 0; nt < 4; nt++)
                    mma_tf32(acc[mt][nt], ah[mt], bh[nt]);
        }
    }

#pragma unroll
    for (int mt = 0; mt < 4; mt++) {
#pragma unroll
        for (int nt = 0; nt < 4; nt++) {
            int r0 = bm + wm * 64 + mt * 16 + gid;
            int cc = bn + wn * 32 + nt * 8 + 2 * tig;
            if (cc >= N) continue;
            float bv0 = bias0 ? bias0[cc] : 0.f;
            float bv1 = bias0 ? bias0[cc + 1] : 0.f;
            if (r0 < M)
                *(float2*)(C + (size_t)r0 * N + cc) =
                    make_float2(acc[mt][nt][0] + bv0, acc[mt][nt][1] + bv1);
            if (r0 + 8 < M)
                *(float2*)(C + (size_t)(r0 + 8) * N + cc) =
                    make_float2(acc[mt][nt][2] + bv0, acc[mt][nt][3] + bv1);
        }
    }
}

// ============================================================================
// Persistent recurrent kernel, round-5 mainloop:
//   warps = 4 k-quarters (wq) x 2 row-halves (wm: 48/32 rows), sync-free
//   per-warp cp.async double-buffered A staging + ldmatrix fragment loads,
//   k-partials combined via smem atomicAdd into sg[80][33].
// ============================================================================
__device__ __forceinline__ float sigf(float x) { return 1.f / (1.f + expf(-x)); }

#define ASTR 24          // A-stage row stride in halves (48B: conflict-free, 16B-aligned)
#define AROWS 320        // 4 wq * (48+32) rows
#define ABUF (AROWS*ASTR)

template<int MTW>
__device__ __forceinline__ void rec_step_gemm(
    const __half* __restrict__ hiR, const __half* __restrict__ loR,
    const __half* Bh, const __half* Bl, __half* Ah, __half* Al, float* sg,
    int BSTR, int Kpad, int lane, int wq, int gRowBase, int rowBaseS)
{
    const int NC   = Kpad >> 4;
    const int ncq  = NC >> 2;
    const int cbeg = wq * ncq;

    float acc[MTW][4][4];
#pragma unroll
    for (int mt = 0; mt < MTW; mt++)
#pragma unroll
        for (int nt = 0; nt < 4; nt++)
#pragma unroll
            for (int q = 0; q < 4; q++) acc[mt][nt][q] = 0.f;

    auto issue = [&](int c, int buf) {
        // MTW*16 rows x 2 k-segments x 2 planes, 16B each
#pragma unroll
        for (int r = 0; r < MTW * 2; r++) {
            int e   = lane + 32 * r;
            int row = e >> 2;
            int seg = (e >> 1) & 1;
            int pl  = e & 1;
            const __half* src = (pl ? loR : hiR)
                              + (size_t)(gRowBase + row) * Kpad + c * 16 + seg * 8;
            __half* dstp = (pl ? Al : Ah) + buf * ABUF + (rowBaseS + row) * ASTR + seg * 8;
            cp_async16(smem_u32(dstp), src);
        }
    };

    issue(cbeg, 0);     cp_commit();
    issue(cbeg + 1, 1); cp_commit();

    for (int i = 0; i < ncq; i++) {
        const int c   = cbeg + i;
        const int buf = i & 1;
        cp_wait1();
        __syncwarp();

        // B fragments: ldmatrix.x4, tile q = gate-rows 8q..8q+7 -> addr row = lane
        uint32_t bh0[4], bh1[4], bl0[4], bl1[4];
        {
            int k0 = c * 16;
            ldsm4(bh0, smem_u32(Bh + (size_t)lane * BSTR + k0));
            ldsm4(bh1, smem_u32(Bh + (size_t)lane * BSTR + k0 + 8));
            ldsm4(bl0, smem_u32(Bl + (size_t)lane * BSTR + k0));
            ldsm4(bl1, smem_u32(Bl + (size_t)lane * BSTR + k0 + 8));
        }
        // A fragments
        uint32_t ah[MTW][4], al[MTW][4];
        {
            int rA   = rowBaseS + (lane & 7) + ((lane >> 3) & 1) * 8;
            int kseg = (lane >> 4) * 8;
#pragma unroll
            for (int mt = 0; mt < MTW; mt++) {
                ldsm4(ah[mt], smem_u32(Ah + buf * ABUF + (rA + mt * 16) * ASTR + kseg));
                ldsm4(al[mt], smem_u32(Al + buf * ABUF + (rA + mt * 16) * ASTR + kseg));
            }
        }
        // prefetch chunk c+2 into the buffer we just finished reading
        if (i + 2 < ncq) issue(c + 2, buf);
        cp_commit();   // exactly one group per iteration (possibly empty)

#pragma unroll
        for (int mt = 0; mt < MTW; mt++)
#pragma unroll
            for (int nt = 0; nt < 4; nt++) {
                uint32_t bb[2]  = { bh0[nt], bh1[nt] };
                uint32_t bbl[2] = { bl0[nt], bl1[nt] };
                mma_f16(acc[mt][nt], ah[mt], bb);
                mma_f16(acc[mt][nt], al[mt], bb);
                mma_f16(acc[mt][nt], ah[mt], bbl);
            }
    }

    // combine k-partials into sg
    const int gq = lane >> 2;
    const int t4 = lane & 3;
#pragma unroll
    for (int mt = 0; mt < MTW; mt++)
#pragma unroll
        for (int nt = 0; nt < 4; nt++) {
            int row = gRowBase + mt * 16 + gq;
            int col = nt * 8 + 2 * t4;
            atomicAdd(&sg[row * 33 + col],           acc[mt][nt][0]);
            atomicAdd(&sg[row * 33 + col + 1],       acc[mt][nt][1]);
            atomicAdd(&sg[(row + 8) * 33 + col],     acc[mt][nt][2]);
            atomicAdd(&sg[(row + 8) * 33 + col + 1], acc[mt][nt][3]);
        }
}

__global__ __launch_bounds__(256, 1)
void rec_persist(const float* __restrict__ Whh, const float* __restrict__ xw,
                 float* __restrict__ cst,
                 __half* __restrict__ hi0, __half* __restrict__ lo0,
                 __half* __restrict__ hi1, __half* __restrict__ lo1,
                 float* __restrict__ ys, int H, int Kpad, int NJ)
{
    extern __shared__ char sraw[];
    const int BSTR = Kpad + 8;
    __half* Bh = (__half*)sraw;              // [32][BSTR]
    __half* Bl = Bh + 32 * BSTR;
    __half* Ah = Bl + 32 * BSTR;             // [2][AROWS][ASTR]
    __half* Al = Ah + 2 * ABUF;
    float*  sg = (float*)(Al + 2 * ABUF);    // [80][33]

    const int tid  = threadIdx.x;
    const int lane = tid & 31;
    const int warp = tid >> 5;
    const int wq   = warp & 3;
    const int wm   = warp >> 2;
    const int gRowBase = wm * 48;
    const int rowBaseS = wq * 80 + wm * 48;
    const int j0   = blockIdx.x * 8;

    // ---- prologue: this CTA's 32 Whh rows -> resident smem (fp16 hi/lo) ----
    {
        int Kh = Kpad >> 1;
        for (int idx = tid; idx < 32 * Kh; idx += 256) {
            int r  = idx / Kh;
            int kp = idx - r * Kh;
            int k  = 2 * kp;
            int gate = r >> 3, jj = r & 7;
            int j = j0 + jj;
            float x = 0.f, y = 0.f;
            if (j < H) {
                const float* wp = Whh + (size_t)(gate * H + j) * H;
                if (k < H)     x = wp[k];
                if (k + 1 < H) y = wp[k + 1];
            }
            __half hx = __float2half_rn(x);
            __half hy = __float2half_rn(y);
            *(__half2*)&Bh[r * BSTR + k] = __halves2half2(hx, hy);
            *(__half2*)&Bl[r * BSTR + k] =
                __halves2half2(__float2half_rn(x - __half2float(hx)),
                               __float2half_rn(y - __half2float(hy)));
        }
    }
    __syncthreads();

    for (int t = 0; t < Tt; t++) {
        const __half* hiR = (t & 1) ? hi1 : hi0;
        const __half* loR = (t & 1) ? lo1 : lo0;
        __half* hiW = (t & 1) ? hi0 : hi1;
        __half* loW = (t & 1) ? lo0 : lo1;
        const float* xw_t = xw + (size_t)t * Bb * 4 * H;

        // zero the gate accumulation tile
        for (int i = tid; i < 80 * 33; i += 256) sg[i] = 0.f;
        __syncthreads();

        if (wm == 0)
            rec_step_gemm<3>(hiR, loR, Bh, Bl, Ah, Al, sg,
                             BSTR, Kpad, lane, wq, gRowBase, rowBaseS);
        else
            rec_step_gemm<2>(hiR, loR, Bh, Bl, Ah, Al, sg,
                             BSTR, Kpad, lane, wq, gRowBase, rowBaseS);
        __syncthreads();

        // LSTM cell
        for (int e = tid; e < Bb * 8; e += 256) {
            int row = e >> 3, jj = e & 7;
            int j = j0 + jj;
            if (j >= H) continue;
            const float* xr = xw_t + (size_t)row * 4 * H;
            float gi = sg[row * 33 + jj]      + xr[j];
            float gf = sg[row * 33 + 8 + jj]  + xr[H + j];
            float gg = sg[row * 33 + 16 + jj] + xr[2 * H + j];
            float go = sg[row * 33 + 24 + jj] + xr[3 * H + j];
            float cv = cst[(size_t)row * H + j];
            float cn = sigf(gf) * cv + sigf(gi) * tanhf(gg);
            float hn = sigf(go) * tanhf(cn);
            cst[(size_t)row * H + j] = cn;
            ys[(size_t)t * Bb * H + (size_t)row * H + j] = hn;
            __half hh = __float2half_rn(hn);
            hiW[(size_t)row * Kpad + j] = hh;
            loW[(size_t)row * Kpad + j] = __float2half_rn(hn - __half2float(hh));
        }

        // ---- device-wide barrier (monotonic counter) ----
        __syncthreads();
        if (tid == 0) {
            __threadfence();
            atomicAdd(&g_bar, 1u);
            unsigned target = (unsigned)NJ * (unsigned)(t + 1);
            while (*(volatile unsigned*)&g_bar < target) { }
            __threadfence();
        }
        __syncthreads();
    }
}

// ---------------- prep: h0 -> hi/lo planes, zero pong bufs, zero barrier ----
__global__ void prep_h_kernel(const float* __restrict__ h0,
                              __half* __restrict__ hHi0, __half* __restrict__ hLo0,
                              __half* __restrict__ hHi1, __half* __restrict__ hLo1,
                              int H, int Kpad)
{
    int idx = blockIdx.x * blockDim.x + threadIdx.x;
    if (idx == 0) g_bar = 0;
    if (idx >= Bb * Kpad) return;
    int row = idx / Kpad, j = idx - row * Kpad;
    float v = (j < H) ? h0[(size_t)row * H + j] : 0.f;
    __half hh = __float2half_rn(v);
    hHi0[idx] = hh;
    hLo0[idx] = __float2half_rn(v - __half2float(hh));
    hHi1[idx] = __ushort_as_half(0);
    hLo1[idx] = __ushort_as_half(0);
}

__global__ void copy_f32(float* __restrict__ dst, const float* __restrict__ src, int n) {
    int i = blockIdx.x * blockDim.x + threadIdx.x;
    if (i < n) dst[i] = src[i];
}

// ---------------- host orchestration ----------------
static inline int ceil_div(int a, int b) { return (a + b - 1) / b; }

extern "C" void kernel_launch(void* const* d_in, const int* in_sizes, int n_in,
                              void* d_out, int out_size)
{
    const int*   tokens = (const int*)d_in[0];
    const float* emb_W  = (const float*)d_in[1];
    const float* dec_W  = (const float*)d_in[2];
    const float* dec_b  = (const float*)d_in[3];

    const float *Wih[3], *Whh[3], *bih[3], *bhh[3], *h0[3], *c0[3];
    for (int l = 0; l < 3; l++) {
        int base = 4 + l * 6;
        Wih[l] = (const float*)d_in[base + 0];
        Whh[l] = (const float*)d_in[base + 1];
        bih[l] = (const float*)d_in[base + 2];
        bhh[l] = (const float*)d_in[base + 3];
        h0[l]  = (const float*)d_in[base + 4];
        c0[l]  = (const float*)d_in[base + 5];
    }

    float *pX0, *pX1, *pXW, *pc;
    __half *pHi, *pLo;
    cudaGetSymbolAddress((void**)&pX0, g_X0);
    cudaGetSymbolAddress((void**)&pX1, g_X1);
    cudaGetSymbolAddress((void**)&pXW, g_XW);
    cudaGetSymbolAddress((void**)&pc,  g_c);
    cudaGetSymbolAddress((void**)&pHi, g_hHi);
    cudaGetSymbolAddress((void**)&pLo, g_hLo);

    float* out = (float*)d_out;

    // opt-in smem for the persistent kernel (max: Kpad=1152)
    {
        int maxBytes = (2 * 32 * (KPAD_MAX + 8) + 4 * ABUF) * 2 + 80 * 33 * 4;
        cudaFuncSetAttribute(rec_persist,
                             cudaFuncAttributeMaxDynamicSharedMemorySize, maxBytes);
    }

    // 1) embedding
    {
        int n = TB * Ee;
        embed_kernel<<<ceil_div(n, 256), 256>>>(tokens, emb_W, pX0, n);
    }

    const int In[3] = {Ee, Hh, Hh};
    const int Hd[3] = {Hh, Hh, Ee};
    const int Kp[3] = {1152, 1152, 448};   // /64 so each k-quarter is whole chunks
    float* xin  = pX0;
    float* xout = pX1;
    size_t out_off = (size_t)TB * Vv;

    for (int l = 0; l < 3; l++) {
        int I = In[l], H = Hd[l], N4 = 4 * H, Kpad = Kp[l];

        // xW = x @ Wih^T + bih + bhh  — 3-pass fp16 tensor path
        {
            dim3 grid(ceil_div(N4, 128), ceil_div(TB, 128));
            hgemm3_nt_bias<<<grid, 256>>>(xin, Wih[l], bih[l], bhh[l], pXW, TB, N4, I);
        }

        // init h planes + barrier + c
        {
            int n = Bb * Kpad;
            prep_h_kernel<<<ceil_div(n, 256), 256>>>(
                h0[l], pHi, pLo, pHi + Bb * KPAD_MAX, pLo + Bb * KPAD_MAX, H, Kpad);
            copy_f32<<<ceil_div(Bb * H, 256), 256>>>(pc, c0[l], Bb * H);
        }

        // persistent recurrent kernel (all Tt steps)
        {
            int NJ = ceil_div(H, 8);
            int smemBytes = (2 * 32 * (Kpad + 8) + 4 * ABUF) * 2 + 80 * 33 * 4;
            rec_persist<<<NJ, 256, smemBytes>>>(
                Whh[l], pXW, pc,
                pHi, pLo, pHi + Bb * KPAD_MAX, pLo + Bb * KPAD_MAX,
                xout, H, Kpad, NJ);
        }

        // export hT (= ys[t=Tt-1]) and cT
        copy_f32<<<ceil_div(Bb * H, 256), 256>>>(
            out + out_off, xout + (size_t)(Tt - 1) * Bb * H, Bb * H);
        out_off += (size_t)Bb * H;
        copy_f32<<<ceil_div(Bb * H, 256), 256>>>(out + out_off, pc, Bb * H);
        out_off += (size_t)Bb * H;

        float* tmp = xin; xin = xout; xout = tmp;
    }

    // 2) decoder: decoded = ys @ dec_W^T + dec_b — 1-pass tf32
    {
        dim3 grid(ceil_div(Vv, 128), ceil_div(TB, 128));
        tgemm_nt_bias<<<grid, 256>>>(xin, dec_W, dec_b, out, TB, Vv, Ee);
    }
}

// round 7
// speedup vs baseline: 3.6644x; 1.1821x over previous
#include <cuda_runtime.h>
#include <cuda_fp16.h>
#include <math.h>
#include <stdint.h>

// Problem constants
#define Tt 70
#define Bb 80
#define Vv 33278
#define Ee 400
#define Hh 1150
#define TB (Tt*Bb)          // 5600
#define KPAD_MAX 1152

// ---------------- scratch (device globals; no allocation) ----------------
__device__ float  g_X0[(size_t)TB * Hh];
__device__ float  g_X1[(size_t)TB * Hh];
__device__ float  g_XW[(size_t)TB * 4 * Hh];
__device__ float  g_c[Bb * Hh];
__device__ __half g_hHi[2][Bb * KPAD_MAX];
__device__ __half g_hLo[2][Bb * KPAD_MAX];
__device__ unsigned g_bar;

// ---------------- embedding gather ----------------
__global__ void embed_kernel(const int* __restrict__ tokens,
                             const float* __restrict__ emb,
                             float* __restrict__ x, int n) {
    int idx = blockIdx.x * blockDim.x + threadIdx.x;
    if (idx >= n) return;
    int tb = idx / Ee;
    int e  = idx - tb * Ee;
    x[idx] = emb[(size_t)tokens[tb] * Ee + e];
}

// ---------------- ptx helpers ----------------
__device__ __forceinline__ void mma_f16(float* c, const uint32_t* a, const uint32_t* b) {
    asm volatile(
        "mma.sync.aligned.m16n8k16.row.col.f32.f16.f16.f32 "
        "{%0,%1,%2,%3}, {%4,%5,%6,%7}, {%8,%9}, {%0,%1,%2,%3};"
        : "+f"(c[0]), "+f"(c[1]), "+f"(c[2]), "+f"(c[3])
        : "r"(a[0]), "r"(a[1]), "r"(a[2]), "r"(a[3]), "r"(b[0]), "r"(b[1]));
}
__device__ __forceinline__ uint32_t smem_u32(const void* p) {
    return (uint32_t)__cvta_generic_to_shared(p);
}
__device__ __forceinline__ void ldsm4(uint32_t* r, uint32_t addr) {
    asm volatile("ldmatrix.sync.aligned.m8n8.x4.shared.b16 {%0,%1,%2,%3}, [%4];"
                 : "=r"(r[0]), "=r"(r[1]), "=r"(r[2]), "=r"(r[3]) : "r"(addr));
}
__device__ __forceinline__ void cp_async16(uint32_t dst, const void* src) {
    asm volatile("cp.async.cg.shared.global [%0], [%1], 16;" :: "r"(dst), "l"(src));
}
__device__ __forceinline__ void cp_commit() {
    asm volatile("cp.async.commit_group;" ::: "memory");
}
__device__ __forceinline__ void cp_wait1() {
    asm volatile("cp.async.wait_group 1;" ::: "memory");
}

// ============================================================================
// Templated fp16 split GEMM: C = A[M,K] * W[N,K]^T + bias0 + bias1
// PASSES=1: plain fp16 (11-bit significand, tf32-equivalent error, 2x rate)
// PASSES=2: A error-free-split (Ah.Bh + Al.Bh)
// PASSES=3: full 3-term split (near-fp32)
// CTA 128x128, 8 warps 2(m)x4(n), warp 64x32, k-chunk 16.
// ============================================================================
template<int PASSES>
__global__ __launch_bounds__(256)
void hgemm_nt_bias(const float* __restrict__ A, const float* __restrict__ W,
                   const float* __restrict__ bias0, const float* __restrict__ bias1,
                   float* __restrict__ C, int M, int N, int K)
{
    __shared__ __half AsH[128 * 16];
    __shared__ __half BsH[128 * 16];
    __shared__ __half AsL[(PASSES >= 2) ? 128 * 16 : 8];
    __shared__ __half BsL[(PASSES >= 3) ? 128 * 16 : 8];

    const int tid  = threadIdx.x;
    const int lane = tid & 31;
    const int warp = tid >> 5;
    const int wm   = warp >> 2;
    const int wn   = warp & 3;
    const int g    = lane >> 2;
    const int t4   = lane & 3;
    const int bm   = blockIdx.y * 128;
    const int bn   = blockIdx.x * 128;

    float acc[4][4][4];
#pragma unroll
    for (int i = 0; i < 4; i++)
#pragma unroll
        for (int j = 0; j < 4; j++)
#pragma unroll
            for (int q = 0; q < 4; q++) acc[i][j][q] = 0.f;

    float2 aR[4], bR[4];

    auto load_stage = [&](int k0) {
#pragma unroll
        for (int i = 0; i < 4; i++) {
            int gg = tid + i * 256;
            int m  = gg >> 3;
            int gk = k0 + ((gg & 7) << 1);
            int gm = bm + m;
            aR[i] = (gm < M && gk < K) ? *(const float2*)(A + (size_t)gm * K + gk)
                                       : make_float2(0.f, 0.f);
            int gn = bn + m;
            bR[i] = (gn < N && gk < K) ? *(const float2*)(W + (size_t)gn * K + gk)
                                       : make_float2(0.f, 0.f);
        }
    };

    auto store_stage = [&]() {
#pragma unroll
        for (int i = 0; i < 4; i++) {
            int gg = tid + i * 256;
            int m  = gg >> 3;
            int kp = gg & 7;
            {
                __half hx = __float2half_rn(aR[i].x);
                __half hy = __float2half_rn(aR[i].y);
                *(__half2*)&AsH[m * 16 + 2 * kp] = __halves2half2(hx, hy);
                if (PASSES >= 2) {
                    float lx = aR[i].x - __half2float(hx);
                    float ly = aR[i].y - __half2float(hy);
                    *(__half2*)&AsL[m * 16 + 2 * kp] =
                        __halves2half2(__float2half_rn(lx), __float2half_rn(ly));
                }
            }
            {
                __half hx = __float2half_rn(bR[i].x);
                __half hy = __float2half_rn(bR[i].y);
                *(__half2*)&BsH[m * 16 + 2 * kp] = __halves2half2(hx, hy);
                if (PASSES >= 3) {
                    float lx = bR[i].x - __half2float(hx);
                    float ly = bR[i].y - __half2float(hy);
                    *(__half2*)&BsL[m * 16 + 2 * kp] =
                        __halves2half2(__float2half_rn(lx), __float2half_rn(ly));
                }
            }
        }
    };

    load_stage(0);

    for (int k0 = 0; k0 < K; k0 += 16) {
        __syncthreads();
        store_stage();
        __syncthreads();
        if (k0 + 16 < K) load_stage(k0 + 16);

        uint32_t ah[4][4], al[4][4], bh[4][2], bl[4][2];
#pragma unroll
        for (int mt = 0; mt < 4; mt++) {
            int r0 = wm * 64 + mt * 16 + g;
            ah[mt][0] = *(const uint32_t*)&AsH[r0 * 16 + 2 * t4];
            ah[mt][1] = *(const uint32_t*)&AsH[(r0 + 8) * 16 + 2 * t4];
            ah[mt][2] = *(const uint32_t*)&AsH[r0 * 16 + 2 * t4 + 8];
            ah[mt][3] = *(const uint32_t*)&AsH[(r0 + 8) * 16 + 2 * t4 + 8];
            if (PASSES >= 2) {
                al[mt][0] = *(const uint32_t*)&AsL[r0 * 16 + 2 * t4];
                al[mt][1] = *(const uint32_t*)&AsL[(r0 + 8) * 16 + 2 * t4];
                al[mt][2] = *(const uint32_t*)&AsL[r0 * 16 + 2 * t4 + 8];
                al[mt][3] = *(const uint32_t*)&AsL[(r0 + 8) * 16 + 2 * t4 + 8];
            }
        }
#pragma unroll
        for (int nt = 0; nt < 4; nt++) {
            int n0 = wn * 32 + nt * 8 + g;
            bh[nt][0] = *(const uint32_t*)&BsH[n0 * 16 + 2 * t4];
            bh[nt][1] = *(const uint32_t*)&BsH[n0 * 16 + 2 * t4 + 8];
            if (PASSES >= 3) {
                bl[nt][0] = *(const uint32_t*)&BsL[n0 * 16 + 2 * t4];
                bl[nt][1] = *(const uint32_t*)&BsL[n0 * 16 + 2 * t4 + 8];
            }
        }
#pragma unroll
        for (int mt = 0; mt < 4; mt++)
#pragma unroll
            for (int nt = 0; nt < 4; nt++) {
                mma_f16(acc[mt][nt], ah[mt], bh[nt]);
                if (PASSES >= 2) mma_f16(acc[mt][nt], al[mt], bh[nt]);
                if (PASSES >= 3) mma_f16(acc[mt][nt], ah[mt], bl[nt]);
            }
    }

#pragma unroll
    for (int mt = 0; mt < 4; mt++) {
#pragma unroll
        for (int nt = 0; nt < 4; nt++) {
            int r0 = bm + wm * 64 + mt * 16 + g;
            int cc = bn + wn * 32 + nt * 8 + 2 * t4;
            if (cc >= N) continue;
            float bv0 = 0.f, bv1 = 0.f;
            if (bias0) { bv0 += bias0[cc]; bv1 += bias0[cc + 1]; }
            if (bias1) { bv0 += bias1[cc]; bv1 += bias1[cc + 1]; }
            if (r0 < M)
                *(float2*)(C + (size_t)r0 * N + cc) =
                    make_float2(acc[mt][nt][0] + bv0, acc[mt][nt][1] + bv1);
            if (r0 + 8 < M)
                *(float2*)(C + (size_t)(r0 + 8) * N + cc) =
                    make_float2(acc[mt][nt][2] + bv0, acc[mt][nt][3] + bv1);
        }
    }
}

// ============================================================================
// Persistent recurrent kernel (R5, proven): warps = 4 k-quarters x 2 row-halves,
// per-warp cp.async double buffering, smem atomicAdd combine, global barrier.
// ============================================================================
__device__ __forceinline__ float sigf(float x) { return 1.f / (1.f + expf(-x)); }

#define ASTR 24
#define AROWS 320
#define ABUF (AROWS*ASTR)

template<int MTW>
__device__ __forceinline__ void rec_step_gemm(
    const __half* __restrict__ hiR, const __half* __restrict__ loR,
    const __half* Bh, const __half* Bl, __half* Ah, __half* Al, float* sg,
    int BSTR, int Kpad, int lane, int wq, int gRowBase, int rowBaseS)
{
    const int NC   = Kpad >> 4;
    const int ncq  = NC >> 2;
    const int cbeg = wq * ncq;

    float acc[MTW][4][4];
#pragma unroll
    for (int mt = 0; mt < MTW; mt++)
#pragma unroll
        for (int nt = 0; nt < 4; nt++)
#pragma unroll
            for (int q = 0; q < 4; q++) acc[mt][nt][q] = 0.f;

    auto issue = [&](int c, int buf) {
#pragma unroll
        for (int r = 0; r < MTW * 2; r++) {
            int e   = lane + 32 * r;
            int row = e >> 2;
            int seg = (e >> 1) & 1;
            int pl  = e & 1;
            const __half* src = (pl ? loR : hiR)
                              + (size_t)(gRowBase + row) * Kpad + c * 16 + seg * 8;
            __half* dstp = (pl ? Al : Ah) + buf * ABUF + (rowBaseS + row) * ASTR + seg * 8;
            cp_async16(smem_u32(dstp), src);
        }
    };

    issue(cbeg, 0);     cp_commit();
    issue(cbeg + 1, 1); cp_commit();

    for (int i = 0; i < ncq; i++) {
        const int c   = cbeg + i;
        const int buf = i & 1;
        cp_wait1();
        __syncwarp();

        uint32_t bh0[4], bh1[4], bl0[4], bl1[4];
        {
            int k0 = c * 16;
            ldsm4(bh0, smem_u32(Bh + (size_t)lane * BSTR + k0));
            ldsm4(bh1, smem_u32(Bh + (size_t)lane * BSTR + k0 + 8));
            ldsm4(bl0, smem_u32(Bl + (size_t)lane * BSTR + k0));
            ldsm4(bl1, smem_u32(Bl + (size_t)lane * BSTR + k0 + 8));
        }
        uint32_t ah[MTW][4], al[MTW][4];
        {
            int rA   = rowBaseS + (lane & 7) + ((lane >> 3) & 1) * 8;
            int kseg = (lane >> 4) * 8;
#pragma unroll
            for (int mt = 0; mt < MTW; mt++) {
                ldsm4(ah[mt], smem_u32(Ah + buf * ABUF + (rA + mt * 16) * ASTR + kseg));
                ldsm4(al[mt], smem_u32(Al + buf * ABUF + (rA + mt * 16) * ASTR + kseg));
            }
        }
        if (i + 2 < ncq) issue(c + 2, buf);
        cp_commit();

#pragma unroll
        for (int mt = 0; mt < MTW; mt++)
#pragma unroll
            for (int nt = 0; nt < 4; nt++) {
                uint32_t bb[2]  = { bh0[nt], bh1[nt] };
                uint32_t bbl[2] = { bl0[nt], bl1[nt] };
                mma_f16(acc[mt][nt], ah[mt], bb);
                mma_f16(acc[mt][nt], al[mt], bb);
                mma_f16(acc[mt][nt], ah[mt], bbl);
            }
    }

    const int gq = lane >> 2;
    const int t4 = lane & 3;
#pragma unroll
    for (int mt = 0; mt < MTW; mt++)
#pragma unroll
        for (int nt = 0; nt < 4; nt++) {
            int row = gRowBase + mt * 16 + gq;
            int col = nt * 8 + 2 * t4;
            atomicAdd(&sg[row * 33 + col],           acc[mt][nt][0]);
            atomicAdd(&sg[row * 33 + col + 1],       acc[mt][nt][1]);
            atomicAdd(&sg[(row + 8) * 33 + col],     acc[mt][nt][2]);
            atomicAdd(&sg[(row + 8) * 33 + col + 1], acc[mt][nt][3]);
        }
}

__global__ __launch_bounds__(256, 1)
void rec_persist(const float* __restrict__ Whh, const float* __restrict__ xw,
                 float* __restrict__ cst,
                 __half* __restrict__ hi0, __half* __restrict__ lo0,
                 __half* __restrict__ hi1, __half* __restrict__ lo1,
                 float* __restrict__ ys, int H, int Kpad, int NJ)
{
    extern __shared__ char sraw[];
    const int BSTR = Kpad + 8;
    __half* Bh = (__half*)sraw;
    __half* Bl = Bh + 32 * BSTR;
    __half* Ah = Bl + 32 * BSTR;
    __half* Al = Ah + 2 * ABUF;
    float*  sg = (float*)(Al + 2 * ABUF);

    const int tid  = threadIdx.x;
    const int lane = tid & 31;
    const int warp = tid >> 5;
    const int wq   = warp & 3;
    const int wm   = warp >> 2;
    const int gRowBase = wm * 48;
    const int rowBaseS = wq * 80 + wm * 48;
    const int j0   = blockIdx.x * 8;

    {
        int Kh = Kpad >> 1;
        for (int idx = tid; idx < 32 * Kh; idx += 256) {
            int r  = idx / Kh;
            int kp = idx - r * Kh;
            int k  = 2 * kp;
            int gate = r >> 3, jj = r & 7;
            int j = j0 + jj;
            float x = 0.f, y = 0.f;
            if (j < H) {
                const float* wp = Whh + (size_t)(gate * H + j) * H;
                if (k < H)     x = wp[k];
                if (k + 1 < H) y = wp[k + 1];
            }
            __half hx = __float2half_rn(x);
            __half hy = __float2half_rn(y);
            *(__half2*)&Bh[r * BSTR + k] = __halves2half2(hx, hy);
            *(__half2*)&Bl[r * BSTR + k] =
                __halves2half2(__float2half_rn(x - __half2float(hx)),
                               __float2half_rn(y - __half2float(hy)));
        }
    }
    __syncthreads();

    for (int t = 0; t < Tt; t++) {
        const __half* hiR = (t & 1) ? hi1 : hi0;
        const __half* loR = (t & 1) ? lo1 : lo0;
        __half* hiW = (t & 1) ? hi0 : hi1;
        __half* loW = (t & 1) ? lo0 : lo1;
        const float* xw_t = xw + (size_t)t * Bb * 4 * H;

        for (int i = tid; i < 80 * 33; i += 256) sg[i] = 0.f;
        __syncthreads();

        if (wm == 0)
            rec_step_gemm<3>(hiR, loR, Bh, Bl, Ah, Al, sg,
                             BSTR, Kpad, lane, wq, gRowBase, rowBaseS);
        else
            rec_step_gemm<2>(hiR, loR, Bh, Bl, Ah, Al, sg,
                             BSTR, Kpad, lane, wq, gRowBase, rowBaseS);
        __syncthreads();

        for (int e = tid; e < Bb * 8; e += 256) {
            int row = e >> 3, jj = e & 7;
            int j = j0 + jj;
            if (j >= H) continue;
            const float* xr = xw_t + (size_t)row * 4 * H;
            float gi = sg[row * 33 + jj]      + xr[j];
            float gf = sg[row * 33 + 8 + jj]  + xr[H + j];
            float gg = sg[row * 33 + 16 + jj] + xr[2 * H + j];
            float go = sg[row * 33 + 24 + jj] + xr[3 * H + j];
            float cv = cst[(size_t)row * H + j];
            float cn = sigf(gf) * cv + sigf(gi) * tanhf(gg);
            float hn = sigf(go) * tanhf(cn);
            cst[(size_t)row * H + j] = cn;
            ys[(size_t)t * Bb * H + (size_t)row * H + j] = hn;
            __half hh = __float2half_rn(hn);
            hiW[(size_t)row * Kpad + j] = hh;
            loW[(size_t)row * Kpad + j] = __float2half_rn(hn - __half2float(hh));
        }

        __syncthreads();
        if (tid == 0) {
            __threadfence();
            atomicAdd(&g_bar, 1u);
            unsigned target = (unsigned)NJ * (unsigned)(t + 1);
            while (*(volatile unsigned*)&g_bar < target) { }
            __threadfence();
        }
        __syncthreads();
    }
}

// ---------------- prep: h0 -> hi/lo planes, zero pong bufs, zero barrier ----
__global__ void prep_h_kernel(const float* __restrict__ h0,
                              __half* __restrict__ hHi0, __half* __restrict__ hLo0,
                              __half* __restrict__ hHi1, __half* __restrict__ hLo1,
                              int H, int Kpad)
{
    int idx = blockIdx.x * blockDim.x + threadIdx.x;
    if (idx == 0) g_bar = 0;
    if (idx >= Bb * Kpad) return;
    int row = idx / Kpad, j = idx - row * Kpad;
    float v = (j < H) ? h0[(size_t)row * H + j] : 0.f;
    __half hh = __float2half_rn(v);
    hHi0[idx] = hh;
    hLo0[idx] = __float2half_rn(v - __half2float(hh));
    hHi1[idx] = __ushort_as_half(0);
    hLo1[idx] = __ushort_as_half(0);
}

__global__ void copy_f32(float* __restrict__ dst, const float* __restrict__ src, int n) {
    int i = blockIdx.x * blockDim.x + threadIdx.x;
    if (i < n) dst[i] = src[i];
}

// ---------------- host orchestration ----------------
static inline int ceil_div(int a, int b) { return (a + b - 1) / b; }

extern "C" void kernel_launch(void* const* d_in, const int* in_sizes, int n_in,
                              void* d_out, int out_size)
{
    const int*   tokens = (const int*)d_in[0];
    const float* emb_W  = (const float*)d_in[1];
    const float* dec_W  = (const float*)d_in[2];
    const float* dec_b  = (const float*)d_in[3];

    const float *Wih[3], *Whh[3], *bih[3], *bhh[3], *h0[3], *c0[3];
    for (int l = 0; l < 3; l++) {
        int base = 4 + l * 6;
        Wih[l] = (const float*)d_in[base + 0];
        Whh[l] = (const float*)d_in[base + 1];
        bih[l] = (const float*)d_in[base + 2];
        bhh[l] = (const float*)d_in[base + 3];
        h0[l]  = (const float*)d_in[base + 4];
        c0[l]  = (const float*)d_in[base + 5];
    }

    float *pX0, *pX1, *pXW, *pc;
    __half *pHi, *pLo;
    cudaGetSymbolAddress((void**)&pX0, g_X0);
    cudaGetSymbolAddress((void**)&pX1, g_X1);
    cudaGetSymbolAddress((void**)&pXW, g_XW);
    cudaGetSymbolAddress((void**)&pc,  g_c);
    cudaGetSymbolAddress((void**)&pHi, g_hHi);
    cudaGetSymbolAddress((void**)&pLo, g_hLo);

    float* out = (float*)d_out;

    // opt-in smem for the persistent kernel
    {
        int recBytes = (2 * 32 * (KPAD_MAX + 8) + 4 * ABUF) * 2 + 80 * 33 * 4;
        cudaFuncSetAttribute(rec_persist,
                             cudaFuncAttributeMaxDynamicSharedMemorySize, recBytes);
    }

    // 1) embedding
    {
        int n = TB * Ee;
        embed_kernel<<<ceil_div(n, 256), 256>>>(tokens, emb_W, pX0, n);
    }

    const int In[3] = {Ee, Hh, Hh};
    const int Hd[3] = {Hh, Hh, Ee};
    const int Kp[3] = {1152, 1152, 448};
    float* xin  = pX0;
    float* xout = pX1;
    size_t out_off = (size_t)TB * Vv;

    for (int l = 0; l < 3; l++) {
        int I = In[l], H = Hd[l], N4 = 4 * H, Kpad = Kp[l];

        // xW = x @ Wih^T + bih + bhh  — 2-pass fp16 split (A error-free)
        {
            dim3 grid(ceil_div(N4, 128), ceil_div(TB, 128));
            hgemm_nt_bias<2><<<grid, 256>>>(xin, Wih[l], bih[l], bhh[l], pXW, TB, N4, I);
        }

        // init h planes + barrier + c
        {
            int n = Bb * Kpad;
            prep_h_kernel<<<ceil_div(n, 256), 256>>>(
                h0[l], pHi, pLo, pHi + Bb * KPAD_MAX, pLo + Bb * KPAD_MAX, H, Kpad);
            copy_f32<<<ceil_div(Bb * H, 256), 256>>>(pc, c0[l], Bb * H);
        }

        // persistent recurrent kernel (all Tt steps)
        {
            int NJ = ceil_div(H, 8);
            int smemBytes = (2 * 32 * (Kpad + 8) + 4 * ABUF) * 2 + 80 * 33 * 4;
            rec_persist<<<NJ, 256, smemBytes>>>(
                Whh[l], pXW, pc,
                pHi, pLo, pHi + Bb * KPAD_MAX, pLo + Bb * KPAD_MAX,
                xout, H, Kpad, NJ);
        }

        copy_f32<<<ceil_div(Bb * H, 256), 256>>>(
            out + out_off, xout + (size_t)(Tt - 1) * Bb * H, Bb * H);
        out_off += (size_t)Bb * H;
        copy_f32<<<ceil_div(Bb * H, 256), 256>>>(out + out_off, pc, Bb * H);
        out_off += (size_t)Bb * H;

        float* tmp = xin; xin = xout; xout = tmp;
    }

    // 2) decoder: decoded = ys @ dec_W^T + dec_b — 1-pass fp16 (tf32-equivalent error, 2x rate)
    {
        dim3 grid(ceil_div(Vv, 128), ceil_div(TB, 128));
        hgemm_nt_bias<1><<<grid, 256>>>(xin, dec_W, dec_b, nullptr, out, TB, Vv, Ee);
    }
}

// round 8
// speedup vs baseline: 4.2494x; 1.1596x over previous
#include <cuda_runtime.h>
#include <cuda_fp16.h>
#include <math.h>
#include <stdint.h>

// Problem constants
#define Tt 70
#define Bb 80
#define Vv 33278
#define Ee 400
#define Hh 1150
#define TB (Tt*Bb)          // 5600
#define KPAD_MAX 1152

// ---------------- scratch (device globals; no allocation) ----------------
__device__ float  g_X0[(size_t)TB * Hh];
__device__ float  g_X1[(size_t)TB * Hh];
__device__ float  g_XW[(size_t)TB * 4 * Hh];
__device__ float  g_c[Bb * Hh];
__device__ __half g_hHi[2][Bb * KPAD_MAX];
__device__ unsigned g_bar;

// ---------------- embedding gather ----------------
__global__ void embed_kernel(const int* __restrict__ tokens,
                             const float* __restrict__ emb,
                             float* __restrict__ x, int n) {
    int idx = blockIdx.x * blockDim.x + threadIdx.x;
    if (idx >= n) return;
    int tb = idx / Ee;
    int e  = idx - tb * Ee;
    x[idx] = emb[(size_t)tokens[tb] * Ee + e];
}

// ---------------- ptx helpers ----------------
__device__ __forceinline__ void mma_f16(float* c, const uint32_t* a, const uint32_t* b) {
    asm volatile(
        "mma.sync.aligned.m16n8k16.row.col.f32.f16.f16.f32 "
        "{%0,%1,%2,%3}, {%4,%5,%6,%7}, {%8,%9}, {%0,%1,%2,%3};"
        : "+f"(c[0]), "+f"(c[1]), "+f"(c[2]), "+f"(c[3])
        : "r"(a[0]), "r"(a[1]), "r"(a[2]), "r"(a[3]), "r"(b[0]), "r"(b[1]));
}
__device__ __forceinline__ uint32_t smem_u32(const void* p) {
    return (uint32_t)__cvta_generic_to_shared(p);
}
__device__ __forceinline__ void ldsm4(uint32_t* r, uint32_t addr) {
    asm volatile("ldmatrix.sync.aligned.m8n8.x4.shared.b16 {%0,%1,%2,%3}, [%4];"
                 : "=r"(r[0]), "=r"(r[1]), "=r"(r[2]), "=r"(r[3]) : "r"(addr));
}
__device__ __forceinline__ void cp_async16(uint32_t dst, const void* src) {
    asm volatile("cp.async.cg.shared.global [%0], [%1], 16;" :: "r"(dst), "l"(src));
}
__device__ __forceinline__ void cp_commit() {
    asm volatile("cp.async.commit_group;" ::: "memory");
}
__device__ __forceinline__ void cp_wait1() {
    asm volatile("cp.async.wait_group 1;" ::: "memory");
}

// ============================================================================
// Templated fp16 split GEMM: C = A[M,K] * W[N,K]^T + bias0 + bias1
// PASSES=1: plain fp16.  PASSES=2: A error-free-split.  PASSES=3: full split.
// ============================================================================
template<int PASSES>
__global__ __launch_bounds__(256)
void hgemm_nt_bias(const float* __restrict__ A, const float* __restrict__ W,
                   const float* __restrict__ bias0, const float* __restrict__ bias1,
                   float* __restrict__ C, int M, int N, int K)
{
    __shared__ __half AsH[128 * 16];
    __shared__ __half BsH[128 * 16];
    __shared__ __half AsL[(PASSES >= 2) ? 128 * 16 : 8];
    __shared__ __half BsL[(PASSES >= 3) ? 128 * 16 : 8];

    const int tid  = threadIdx.x;
    const int lane = tid & 31;
    const int warp = tid >> 5;
    const int wm   = warp >> 2;
    const int wn   = warp & 3;
    const int g    = lane >> 2;
    const int t4   = lane & 3;
    const int bm   = blockIdx.y * 128;
    const int bn   = blockIdx.x * 128;

    float acc[4][4][4];
#pragma unroll
    for (int i = 0; i < 4; i++)
#pragma unroll
        for (int j = 0; j < 4; j++)
#pragma unroll
            for (int q = 0; q < 4; q++) acc[i][j][q] = 0.f;

    float2 aR[4], bR[4];

    auto load_stage = [&](int k0) {
#pragma unroll
        for (int i = 0; i < 4; i++) {
            int gg = tid + i * 256;
            int m  = gg >> 3;
            int gk = k0 + ((gg & 7) << 1);
            int gm = bm + m;
            aR[i] = (gm < M && gk < K) ? *(const float2*)(A + (size_t)gm * K + gk)
                                       : make_float2(0.f, 0.f);
            int gn = bn + m;
            bR[i] = (gn < N && gk < K) ? *(const float2*)(W + (size_t)gn * K + gk)
                                       : make_float2(0.f, 0.f);
        }
    };

    auto store_stage = [&]() {
#pragma unroll
        for (int i = 0; i < 4; i++) {
            int gg = tid + i * 256;
            int m  = gg >> 3;
            int kp = gg & 7;
            {
                __half hx = __float2half_rn(aR[i].x);
                __half hy = __float2half_rn(aR[i].y);
                *(__half2*)&AsH[m * 16 + 2 * kp] = __halves2half2(hx, hy);
                if (PASSES >= 2) {
                    float lx = aR[i].x - __half2float(hx);
                    float ly = aR[i].y - __half2float(hy);
                    *(__half2*)&AsL[m * 16 + 2 * kp] =
                        __halves2half2(__float2half_rn(lx), __float2half_rn(ly));
                }
            }
            {
                __half hx = __float2half_rn(bR[i].x);
                __half hy = __float2half_rn(bR[i].y);
                *(__half2*)&BsH[m * 16 + 2 * kp] = __halves2half2(hx, hy);
                if (PASSES >= 3) {
                    float lx = bR[i].x - __half2float(hx);
                    float ly = bR[i].y - __half2float(hy);
                    *(__half2*)&BsL[m * 16 + 2 * kp] =
                        __halves2half2(__float2half_rn(lx), __float2half_rn(ly));
                }
            }
        }
    };

    load_stage(0);

    for (int k0 = 0; k0 < K; k0 += 16) {
        __syncthreads();
        store_stage();
        __syncthreads();
        if (k0 + 16 < K) load_stage(k0 + 16);

        uint32_t ah[4][4], al[4][4], bh[4][2], bl[4][2];
#pragma unroll
        for (int mt = 0; mt < 4; mt++) {
            int r0 = wm * 64 + mt * 16 + g;
            ah[mt][0] = *(const uint32_t*)&AsH[r0 * 16 + 2 * t4];
            ah[mt][1] = *(const uint32_t*)&AsH[(r0 + 8) * 16 + 2 * t4];
            ah[mt][2] = *(const uint32_t*)&AsH[r0 * 16 + 2 * t4 + 8];
            ah[mt][3] = *(const uint32_t*)&AsH[(r0 + 8) * 16 + 2 * t4 + 8];
            if (PASSES >= 2) {
                al[mt][0] = *(const uint32_t*)&AsL[r0 * 16 + 2 * t4];
                al[mt][1] = *(const uint32_t*)&AsL[(r0 + 8) * 16 + 2 * t4];
                al[mt][2] = *(const uint32_t*)&AsL[r0 * 16 + 2 * t4 + 8];
                al[mt][3] = *(const uint32_t*)&AsL[(r0 + 8) * 16 + 2 * t4 + 8];
            }
        }
#pragma unroll
        for (int nt = 0; nt < 4; nt++) {
            int n0 = wn * 32 + nt * 8 + g;
            bh[nt][0] = *(const uint32_t*)&BsH[n0 * 16 + 2 * t4];
            bh[nt][1] = *(const uint32_t*)&BsH[n0 * 16 + 2 * t4 + 8];
            if (PASSES >= 3) {
                bl[nt][0] = *(const uint32_t*)&BsL[n0 * 16 + 2 * t4];
                bl[nt][1] = *(const uint32_t*)&BsL[n0 * 16 + 2 * t4 + 8];
            }
        }
#pragma unroll
        for (int mt = 0; mt < 4; mt++)
#pragma unroll
            for (int nt = 0; nt < 4; nt++) {
                mma_f16(acc[mt][nt], ah[mt], bh[nt]);
                if (PASSES >= 2) mma_f16(acc[mt][nt], al[mt], bh[nt]);
                if (PASSES >= 3) mma_f16(acc[mt][nt], ah[mt], bl[nt]);
            }
    }

#pragma unroll
    for (int mt = 0; mt < 4; mt++) {
#pragma unroll
        for (int nt = 0; nt < 4; nt++) {
            int r0 = bm + wm * 64 + mt * 16 + g;
            int cc = bn + wn * 32 + nt * 8 + 2 * t4;
            if (cc >= N) continue;
            float bv0 = 0.f, bv1 = 0.f;
            if (bias0) { bv0 += bias0[cc]; bv1 += bias0[cc + 1]; }
            if (bias1) { bv0 += bias1[cc]; bv1 += bias1[cc + 1]; }
            if (r0 < M)
                *(float2*)(C + (size_t)r0 * N + cc) =
                    make_float2(acc[mt][nt][0] + bv0, acc[mt][nt][1] + bv1);
            if (r0 + 8 < M)
                *(float2*)(C + (size_t)(r0 + 8) * N + cc) =
                    make_float2(acc[mt][nt][2] + bv0, acc[mt][nt][3] + bv1);
        }
    }
}

// ============================================================================
// Persistent recurrent kernel — R8: 2-pass keep-W-exact (Ah.Bh + Ah.Bl).
// h read as fp16 hi plane only (halves L2 broadcast + cp.async volume).
// warps = 4 k-quarters x 2 row-halves, per-warp cp.async double buffering,
// smem atomicAdd combine, device-wide barrier between steps.
// ============================================================================
__device__ __forceinline__ float sigf(float x) { return 1.f / (1.f + expf(-x)); }

#define ASTR 24
#define AROWS 320
#define ABUF (AROWS*ASTR)

template<int MTW>
__device__ __forceinline__ void rec_step_gemm(
    const __half* __restrict__ hiR,
    const __half* Bh, const __half* Bl, __half* Ah, float* sg,
    int BSTR, int Kpad, int lane, int wq, int gRowBase, int rowBaseS)
{
    const int NC   = Kpad >> 4;
    const int ncq  = NC >> 2;
    const int cbeg = wq * ncq;

    float acc[MTW][4][4];
#pragma unroll
    for (int mt = 0; mt < MTW; mt++)
#pragma unroll
        for (int nt = 0; nt < 4; nt++)
#pragma unroll
            for (int q = 0; q < 4; q++) acc[mt][nt][q] = 0.f;

    auto issue = [&](int c, int buf) {
        // MTW*16 rows x 2 k-segments, hi plane only, 16B each
#pragma unroll
        for (int r = 0; r < MTW; r++) {
            int e   = lane + 32 * r;
            int row = e >> 1;
            int seg = e & 1;
            const __half* src = hiR + (size_t)(gRowBase + row) * Kpad + c * 16 + seg * 8;
            __half* dstp = Ah + buf * ABUF + (rowBaseS + row) * ASTR + seg * 8;
            cp_async16(smem_u32(dstp), src);
        }
    };

    issue(cbeg, 0);     cp_commit();
    issue(cbeg + 1, 1); cp_commit();

    for (int i = 0; i < ncq; i++) {
        const int c   = cbeg + i;
        const int buf = i & 1;
        cp_wait1();
        __syncwarp();

        uint32_t bh0[4], bh1[4], bl0[4], bl1[4];
        {
            int k0 = c * 16;
            ldsm4(bh0, smem_u32(Bh + (size_t)lane * BSTR + k0));
            ldsm4(bh1, smem_u32(Bh + (size_t)lane * BSTR + k0 + 8));
            ldsm4(bl0, smem_u32(Bl + (size_t)lane * BSTR + k0));
            ldsm4(bl1, smem_u32(Bl + (size_t)lane * BSTR + k0 + 8));
        }
        uint32_t ah[MTW][4];
        {
            int rA   = rowBaseS + (lane & 7) + ((lane >> 3) & 1) * 8;
            int kseg = (lane >> 4) * 8;
#pragma unroll
            for (int mt = 0; mt < MTW; mt++)
                ldsm4(ah[mt], smem_u32(Ah + buf * ABUF + (rA + mt * 16) * ASTR + kseg));
        }
        if (i + 2 < ncq) issue(c + 2, buf);
        cp_commit();

#pragma unroll
        for (int mt = 0; mt < MTW; mt++)
#pragma unroll
            for (int nt = 0; nt < 4; nt++) {
                uint32_t bb[2]  = { bh0[nt], bh1[nt] };
                uint32_t bbl[2] = { bl0[nt], bl1[nt] };
                mma_f16(acc[mt][nt], ah[mt], bb);
                mma_f16(acc[mt][nt], ah[mt], bbl);
            }
    }

    const int gq = lane >> 2;
    const int t4 = lane & 3;
#pragma unroll
    for (int mt = 0; mt < MTW; mt++)
#pragma unroll
        for (int nt = 0; nt < 4; nt++) {
            int row = gRowBase + mt * 16 + gq;
            int col = nt * 8 + 2 * t4;
            atomicAdd(&sg[row * 33 + col],           acc[mt][nt][0]);
            atomicAdd(&sg[row * 33 + col + 1],       acc[mt][nt][1]);
            atomicAdd(&sg[(row + 8) * 33 + col],     acc[mt][nt][2]);
            atomicAdd(&sg[(row + 8) * 33 + col + 1], acc[mt][nt][3]);
        }
}

__global__ __launch_bounds__(256, 1)
void rec_persist(const float* __restrict__ Whh, const float* __restrict__ xw,
                 float* __restrict__ cst,
                 __half* __restrict__ hi0, __half* __restrict__ hi1,
                 float* __restrict__ ys, int H, int Kpad, int NJ)
{
    extern __shared__ char sraw[];
    const int BSTR = Kpad + 8;
    __half* Bh = (__half*)sraw;              // [32][BSTR]
    __half* Bl = Bh + 32 * BSTR;
    __half* Ah = Bl + 32 * BSTR;             // [2][AROWS][ASTR]
    float*  sg = (float*)(Ah + 2 * ABUF);    // [80][33]

    const int tid  = threadIdx.x;
    const int lane = tid & 31;
    const int warp = tid >> 5;
    const int wq   = warp & 3;
    const int wm   = warp >> 2;
    const int gRowBase = wm * 48;
    const int rowBaseS = wq * 80 + wm * 48;
    const int j0   = blockIdx.x * 8;

    // prologue: this CTA's 32 Whh rows -> resident smem (fp16 hi/lo, W exact)
    {
        int Kh = Kpad >> 1;
        for (int idx = tid; idx < 32 * Kh; idx += 256) {
            int r  = idx / Kh;
            int kp = idx - r * Kh;
            int k  = 2 * kp;
            int gate = r >> 3, jj = r & 7;
            int j = j0 + jj;
            float x = 0.f, y = 0.f;
            if (j < H) {
                const float* wp = Whh + (size_t)(gate * H + j) * H;
                if (k < H)     x = wp[k];
                if (k + 1 < H) y = wp[k + 1];
            }
            __half hx = __float2half_rn(x);
            __half hy = __float2half_rn(y);
            *(__half2*)&Bh[r * BSTR + k] = __halves2half2(hx, hy);
            *(__half2*)&Bl[r * BSTR + k] =
                __halves2half2(__float2half_rn(x - __half2float(hx)),
                               __float2half_rn(y - __half2float(hy)));
        }
    }
    __syncthreads();

    for (int t = 0; t < Tt; t++) {
        const __half* hiR = (t & 1) ? hi1 : hi0;
        __half* hiW = (t & 1) ? hi0 : hi1;
        const float* xw_t = xw + (size_t)t * Bb * 4 * H;

        for (int i = tid; i < 80 * 33; i += 256) sg[i] = 0.f;
        __syncthreads();

        if (wm == 0)
            rec_step_gemm<3>(hiR, Bh, Bl, Ah, sg,
                             BSTR, Kpad, lane, wq, gRowBase, rowBaseS);
        else
            rec_step_gemm<2>(hiR, Bh, Bl, Ah, sg,
                             BSTR, Kpad, lane, wq, gRowBase, rowBaseS);
        __syncthreads();

        // LSTM cell
        for (int e = tid; e < Bb * 8; e += 256) {
            int row = e >> 3, jj = e & 7;
            int j = j0 + jj;
            if (j >= H) continue;
            const float* xr = xw_t + (size_t)row * 4 * H;
            float gi = sg[row * 33 + jj]      + xr[j];
            float gf = sg[row * 33 + 8 + jj]  + xr[H + j];
            float gg = sg[row * 33 + 16 + jj] + xr[2 * H + j];
            float go = sg[row * 33 + 24 + jj] + xr[3 * H + j];
            float cv = cst[(size_t)row * H + j];
            float cn = sigf(gf) * cv + sigf(gi) * tanhf(gg);
            float hn = sigf(go) * tanhf(cn);
            cst[(size_t)row * H + j] = cn;
            ys[(size_t)t * Bb * H + (size_t)row * H + j] = hn;
            hiW[(size_t)row * Kpad + j] = __float2half_rn(hn);
        }

        // device-wide barrier (monotonic counter)
        __syncthreads();
        if (tid == 0) {
            __threadfence();
            atomicAdd(&g_bar, 1u);
            unsigned target = (unsigned)NJ * (unsigned)(t + 1);
            while (*(volatile unsigned*)&g_bar < target) { }
            __threadfence();
        }
        __syncthreads();
    }
}

// ---------------- prep: h0 -> hi plane, zero pong buf, zero barrier ----
__global__ void prep_h_kernel(const float* __restrict__ h0,
                              __half* __restrict__ hHi0, __half* __restrict__ hHi1,
                              int H, int Kpad)
{
    int idx = blockIdx.x * blockDim.x + threadIdx.x;
    if (idx == 0) g_bar = 0;
    if (idx >= Bb * Kpad) return;
    int row = idx / Kpad, j = idx - row * Kpad;
    float v = (j < H) ? h0[(size_t)row * H + j] : 0.f;
    hHi0[idx] = __float2half_rn(v);
    hHi1[idx] = __ushort_as_half(0);
}

__global__ void copy_f32(float* __restrict__ dst, const float* __restrict__ src, int n) {
    int i = blockIdx.x * blockDim.x + threadIdx.x;
    if (i < n) dst[i] = src[i];
}

// ---------------- host orchestration ----------------
static inline int ceil_div(int a, int b) { return (a + b - 1) / b; }

extern "C" void kernel_launch(void* const* d_in, const int* in_sizes, int n_in,
                              void* d_out, int out_size)
{
    const int*   tokens = (const int*)d_in[0];
    const float* emb_W  = (const float*)d_in[1];
    const float* dec_W  = (const float*)d_in[2];
    const float* dec_b  = (const float*)d_in[3];

    const float *Wih[3], *Whh[3], *bih[3], *bhh[3], *h0[3], *c0[3];
    for (int l = 0; l < 3; l++) {
        int base = 4 + l * 6;
        Wih[l] = (const float*)d_in[base + 0];
        Whh[l] = (const float*)d_in[base + 1];
        bih[l] = (const float*)d_in[base + 2];
        bhh[l] = (const float*)d_in[base + 3];
        h0[l]  = (const float*)d_in[base + 4];
        c0[l]  = (const float*)d_in[base + 5];
    }

    float *pX0, *pX1, *pXW, *pc;
    __half *pHi;
    cudaGetSymbolAddress((void**)&pX0, g_X0);
    cudaGetSymbolAddress((void**)&pX1, g_X1);
    cudaGetSymbolAddress((void**)&pXW, g_XW);
    cudaGetSymbolAddress((void**)&pc,  g_c);
    cudaGetSymbolAddress((void**)&pHi, g_hHi);

    float* out = (float*)d_out;

    // opt-in smem for the persistent kernel
    {
        int recBytes = (2 * 32 * (KPAD_MAX + 8) + 2 * ABUF) * 2 + 80 * 33 * 4;
        cudaFuncSetAttribute(rec_persist,
                             cudaFuncAttributeMaxDynamicSharedMemorySize, recBytes);
    }

    // 1) embedding
    {
        int n = TB * Ee;
        embed_kernel<<<ceil_div(n, 256), 256>>>(tokens, emb_W, pX0, n);
    }

    const int In[3] = {Ee, Hh, Hh};
    const int Hd[3] = {Hh, Hh, Ee};
    const int Kp[3] = {1152, 1152, 448};
    float* xin  = pX0;
    float* xout = pX1;
    size_t out_off = (size_t)TB * Vv;

    for (int l = 0; l < 3; l++) {
        int I = In[l], H = Hd[l], N4 = 4 * H, Kpad = Kp[l];

        // xW = x @ Wih^T + bih + bhh  — 2-pass fp16 split (A error-free)
        {
            dim3 grid(ceil_div(N4, 128), ceil_div(TB, 128));
            hgemm_nt_bias<2><<<grid, 256>>>(xin, Wih[l], bih[l], bhh[l], pXW, TB, N4, I);
        }

        // init h plane + barrier + c
        {
            int n = Bb * Kpad;
            prep_h_kernel<<<ceil_div(n, 256), 256>>>(
                h0[l], pHi, pHi + Bb * KPAD_MAX, H, Kpad);
            copy_f32<<<ceil_div(Bb * H, 256), 256>>>(pc, c0[l], Bb * H);
        }

        // persistent recurrent kernel (all Tt steps)
        {
            int NJ = ceil_div(H, 8);
            int smemBytes = (2 * 32 * (Kpad + 8) + 2 * ABUF) * 2 + 80 * 33 * 4;
            rec_persist<<<NJ, 256, smemBytes>>>(
                Whh[l], pXW, pc,
                pHi, pHi + Bb * KPAD_MAX,
                xout, H, Kpad, NJ);
        }

        copy_f32<<<ceil_div(Bb * H, 256), 256>>>(
            out + out_off, xout + (size_t)(Tt - 1) * Bb * H, Bb * H);
        out_off += (size_t)Bb * H;
        copy_f32<<<ceil_div(Bb * H, 256), 256>>>(out + out_off, pc, Bb * H);
        out_off += (size_t)Bb * H;

        float* tmp = xin; xin = xout; xout = tmp;
    }

    // 2) decoder: decoded = ys @ dec_W^T + dec_b — 1-pass fp16
    {
        dim3 grid(ceil_div(Vv, 128), ceil_div(TB, 128));
        hgemm_nt_bias<1><<<grid, 256>>>(xin, dec_W, dec_b, nullptr, out, TB, Vv, Ee);
    }
}

// round 9
// speedup vs baseline: 4.4809x; 1.0545x over previous
#include <cuda_runtime.h>
#include <cuda_fp16.h>
#include <math.h>
#include <stdint.h>

// Problem constants
#define Tt 70
#define Bb 80
#define Vv 33278
#define Ee 400
#define Hh 1150
#define TB (Tt*Bb)          // 5600
#define KPAD_MAX 1152

// ---------------- scratch (device globals; no allocation) ----------------
__device__ float  g_hT[Bb * Hh];                       // last-step h (f32)
__device__ float  g_XW[(size_t)TB * 4 * Hh];
__device__ float  g_c[Bb * Hh];
__device__ __half g_hHi[2][Bb * KPAD_MAX];
__device__ unsigned g_bar;
// fp16 activation planes (ping/pong), stride up to 1152
__device__ __align__(128) __half g_Ahi[2][(size_t)TB * KPAD_MAX];
__device__ __align__(128) __half g_Alo[2][(size_t)TB * KPAD_MAX];
// fp16 weight hi plane (max: dec_W 33278x400 = 13.4M)
__device__ __align__(128) __half g_Whi[(size_t)13600000];

// ---------------- ptx helpers ----------------
__device__ __forceinline__ void mma_f16(float* c, const uint32_t* a, const uint32_t* b) {
    asm volatile(
        "mma.sync.aligned.m16n8k16.row.col.f32.f16.f16.f32 "
        "{%0,%1,%2,%3}, {%4,%5,%6,%7}, {%8,%9}, {%0,%1,%2,%3};"
        : "+f"(c[0]), "+f"(c[1]), "+f"(c[2]), "+f"(c[3])
        : "r"(a[0]), "r"(a[1]), "r"(a[2]), "r"(a[3]), "r"(b[0]), "r"(b[1]));
}
__device__ __forceinline__ uint32_t smem_u32(const void* p) {
    return (uint32_t)__cvta_generic_to_shared(p);
}
__device__ __forceinline__ void ldsm4(uint32_t* r, uint32_t addr) {
    asm volatile("ldmatrix.sync.aligned.m8n8.x4.shared.b16 {%0,%1,%2,%3}, [%4];"
                 : "=r"(r[0]), "=r"(r[1]), "=r"(r[2]), "=r"(r[3]) : "r"(addr));
}
__device__ __forceinline__ void cp_async16(uint32_t dst, const void* src) {
    asm volatile("cp.async.cg.shared.global [%0], [%1], 16;" :: "r"(dst), "l"(src));
}
__device__ __forceinline__ void cp_commit() {
    asm volatile("cp.async.commit_group;" ::: "memory");
}
__device__ __forceinline__ void cp_wait1() {
    asm volatile("cp.async.wait_group 1;" ::: "memory");
}
__device__ __forceinline__ void cp_wait2() {
    asm volatile("cp.async.wait_group 2;" ::: "memory");
}

// ---------------- embedding gather -> fp16 hi/lo planes ----------------
__global__ void embed_planes(const int* __restrict__ tokens,
                             const float* __restrict__ emb,
                             __half* __restrict__ Ah, __half* __restrict__ Al, int n) {
    int idx = blockIdx.x * blockDim.x + threadIdx.x;
    if (idx >= n) return;
    int tb = idx / Ee;
    int e  = idx - tb * Ee;
    float v = emb[(size_t)tokens[tb] * Ee + e];
    __half hh = __float2half_rn(v);
    Ah[idx] = hh;
    Al[idx] = __float2half_rn(v - __half2float(hh));
}

// ---------------- weight split: f32 [rows][K] -> fp16 hi [rows][Kpad] ------
__global__ void splitW_kernel(const float* __restrict__ W, __half* __restrict__ Wh,
                              int rows, int K, int Kpad) {
    int idx = blockIdx.x * blockDim.x + threadIdx.x;
    if (idx >= rows * Kpad) return;
    int r = idx / Kpad, k = idx - r * Kpad;
    Wh[idx] = (k < K) ? __float2half_rn(W[(size_t)r * K + k]) : __ushort_as_half(0);
}

// ============================================================================
// fp16-plane GEMM: C[M,N] = (Ah + Al)[M,K] * Wh[N,K]^T + bias0 + bias1
// PASSES=1: Ah only.  PASSES=2: Ah.Wh + Al.Wh (A error-free split).
// CTA 128x128, 8 warps 2(m)x4(n), warp 64x32, BK=16, 4-stage cp.async.
// ============================================================================
template<int PASSES>
__global__ __launch_bounds__(256)
void hgemm_f16(const __half* __restrict__ Ah, const __half* __restrict__ Al,
               const __half* __restrict__ Wh,
               const float* __restrict__ bias0, const float* __restrict__ bias1,
               float* __restrict__ C, int M, int N, int K, int lda, int ldw)
{
    extern __shared__ __half smem[];
    const int NT  = (PASSES == 2) ? 3 : 2;   // tiles per stage
    const int TPS = 128 * 16 * NT;           // halves per stage

    const int tid  = threadIdx.x;
    const int lane = tid & 31;
    const int warp = tid >> 5;
    const int wm   = warp >> 2;
    const int wn   = warp & 3;
    const int g    = lane >> 2;
    const int t4   = lane & 3;
    const int bm   = blockIdx.y * 128;
    const int bn   = blockIdx.x * 128;

    float acc[4][4][4];
#pragma unroll
    for (int i = 0; i < 4; i++)
#pragma unroll
        for (int j = 0; j < 4; j++)
#pragma unroll
            for (int q = 0; q < 4; q++) acc[i][j][q] = 0.f;

    const int row = tid >> 1;        // 0..127
    const int seg = tid & 1;         // 16B granule within 32B row

    auto issue = [&](int c, int s) {
        __half* st = smem + s * TPS;
        const int koff = c * 16 + seg * 8;
        // A hi tile
        {
            uint32_t dst = smem_u32(st + row * 16 + seg * 8);
            int gm = bm + row;
            if (gm < M) cp_async16(dst, Ah + (size_t)gm * lda + koff);
            else        *(float4*)(st + row * 16 + seg * 8) = make_float4(0.f,0.f,0.f,0.f);
        }
        // A lo tile
        if (PASSES == 2) {
            uint32_t dst = smem_u32(st + 2048 + row * 16 + seg * 8);
            int gm = bm + row;
            if (gm < M) cp_async16(dst, Al + (size_t)gm * lda + koff);
            else        *(float4*)(st + 2048 + row * 16 + seg * 8) = make_float4(0.f,0.f,0.f,0.f);
        }
        // W hi tile
        {
            __half* bt = st + (NT - 1) * 2048;
            uint32_t dst = smem_u32(bt + row * 16 + seg * 8);
            int gn = bn + row;
            if (gn < N) cp_async16(dst, Wh + (size_t)gn * ldw + koff);
            else        *(float4*)(bt + row * 16 + seg * 8) = make_float4(0.f,0.f,0.f,0.f);
        }
    };

    const int NCH = K >> 4;
    issue(0, 0); cp_commit();
    issue(1, 1); cp_commit();
    issue(2, 2); cp_commit();

    for (int c = 0; c < NCH; c++) {
        cp_wait2();
        __syncthreads();
        __half* st  = smem + (c & 3) * TPS;
        __half* AsH = st;
        __half* AsL = st + 2048;
        __half* BsH = st + (NT - 1) * 2048;

        uint32_t ah[4][4], al[4][4], bh[4][2];
#pragma unroll
        for (int mt = 0; mt < 4; mt++) {
            int r0 = wm * 64 + mt * 16 + g;
            ah[mt][0] = *(const uint32_t*)&AsH[r0 * 16 + 2 * t4];
            ah[mt][1] = *(const uint32_t*)&AsH[(r0 + 8) * 16 + 2 * t4];
            ah[mt][2] = *(const uint32_t*)&AsH[r0 * 16 + 2 * t4 + 8];
            ah[mt][3] = *(const uint32_t*)&AsH[(r0 + 8) * 16 + 2 * t4 + 8];
            if (PASSES == 2) {
                al[mt][0] = *(const uint32_t*)&AsL[r0 * 16 + 2 * t4];
                al[mt][1] = *(const uint32_t*)&AsL[(r0 + 8) * 16 + 2 * t4];
                al[mt][2] = *(const uint32_t*)&AsL[r0 * 16 + 2 * t4 + 8];
                al[mt][3] = *(const uint32_t*)&AsL[(r0 + 8) * 16 + 2 * t4 + 8];
            }
        }
#pragma unroll
        for (int nt = 0; nt < 4; nt++) {
            int n0 = wn * 32 + nt * 8 + g;
            bh[nt][0] = *(const uint32_t*)&BsH[n0 * 16 + 2 * t4];
            bh[nt][1] = *(const uint32_t*)&BsH[n0 * 16 + 2 * t4 + 8];
        }

        // prefetch stage c+3 (its buffer was last read at c-1; the sync above
        // guarantees every warp is past its c-1 fragment loads)
        if (c + 3 < NCH) issue(c + 3, (c + 3) & 3);
        cp_commit();

#pragma unroll
        for (int mt = 0; mt < 4; mt++)
#pragma unroll
            for (int nt = 0; nt < 4; nt++) {
                mma_f16(acc[mt][nt], ah[mt], bh[nt]);
                if (PASSES == 2) mma_f16(acc[mt][nt], al[mt], bh[nt]);
            }
    }

#pragma unroll
    for (int mt = 0; mt < 4; mt++) {
#pragma unroll
        for (int nt = 0; nt < 4; nt++) {
            int r0 = bm + wm * 64 + mt * 16 + g;
            int cc = bn + wn * 32 + nt * 8 + 2 * t4;
            if (cc >= N) continue;
            float bv0 = 0.f, bv1 = 0.f;
            if (bias0) { bv0 += bias0[cc]; bv1 += bias0[cc + 1]; }
            if (bias1) { bv0 += bias1[cc]; bv1 += bias1[cc + 1]; }
            if (r0 < M)
                *(float2*)(C + (size_t)r0 * N + cc) =
                    make_float2(acc[mt][nt][0] + bv0, acc[mt][nt][1] + bv1);
            if (r0 + 8 < M)
                *(float2*)(C + (size_t)(r0 + 8) * N + cc) =
                    make_float2(acc[mt][nt][2] + bv0, acc[mt][nt][3] + bv1);
        }
    }
}

// ============================================================================
// Persistent recurrent kernel (R8 proven) + writes ys hi/lo planes for the
// next consumer (next layer GEMM / decoder) and f32 h only at the last step.
// ============================================================================
__device__ __forceinline__ float sigf(float x) { return 1.f / (1.f + expf(-x)); }

#define ASTR 24
#define AROWS 320
#define ABUF (AROWS*ASTR)

template<int MTW>
__device__ __forceinline__ void rec_step_gemm(
    const __half* __restrict__ hiR,
    const __half* Bh, const __half* Bl, __half* Ah, float* sg,
    int BSTR, int Kpad, int lane, int wq, int gRowBase, int rowBaseS)
{
    const int NC   = Kpad >> 4;
    const int ncq  = NC >> 2;
    const int cbeg = wq * ncq;

    float acc[MTW][4][4];
#pragma unroll
    for (int mt = 0; mt < MTW; mt++)
#pragma unroll
        for (int nt = 0; nt < 4; nt++)
#pragma unroll
            for (int q = 0; q < 4; q++) acc[mt][nt][q] = 0.f;

    auto issue = [&](int c, int buf) {
#pragma unroll
        for (int r = 0; r < MTW; r++) {
            int e   = lane + 32 * r;
            int row = e >> 1;
            int seg = e & 1;
            const __half* src = hiR + (size_t)(gRowBase + row) * Kpad + c * 16 + seg * 8;
            __half* dstp = Ah + buf * ABUF + (rowBaseS + row) * ASTR + seg * 8;
            cp_async16(smem_u32(dstp), src);
        }
    };

    issue(cbeg, 0);     cp_commit();
    issue(cbeg + 1, 1); cp_commit();

    for (int i = 0; i < ncq; i++) {
        const int c   = cbeg + i;
        const int buf = i & 1;
        cp_wait1();
        __syncwarp();

        uint32_t bh0[4], bh1[4], bl0[4], bl1[4];
        {
            int k0 = c * 16;
            ldsm4(bh0, smem_u32(Bh + (size_t)lane * BSTR + k0));
            ldsm4(bh1, smem_u32(Bh + (size_t)lane * BSTR + k0 + 8));
            ldsm4(bl0, smem_u32(Bl + (size_t)lane * BSTR + k0));
            ldsm4(bl1, smem_u32(Bl + (size_t)lane * BSTR + k0 + 8));
        }
        uint32_t ah[MTW][4];
        {
            int rA   = rowBaseS + (lane & 7) + ((lane >> 3) & 1) * 8;
            int kseg = (lane >> 4) * 8;
#pragma unroll
            for (int mt = 0; mt < MTW; mt++)
                ldsm4(ah[mt], smem_u32(Ah + buf * ABUF + (rA + mt * 16) * ASTR + kseg));
        }
        if (i + 2 < ncq) issue(c + 2, buf);
        cp_commit();

#pragma unroll
        for (int mt = 0; mt < MTW; mt++)
#pragma unroll
            for (int nt = 0; nt < 4; nt++) {
                uint32_t bb[2]  = { bh0[nt], bh1[nt] };
                uint32_t bbl[2] = { bl0[nt], bl1[nt] };
                mma_f16(acc[mt][nt], ah[mt], bb);
                mma_f16(acc[mt][nt], ah[mt], bbl);
            }
    }

    const int gq = lane >> 2;
    const int t4 = lane & 3;
#pragma unroll
    for (int mt = 0; mt < MTW; mt++)
#pragma unroll
        for (int nt = 0; nt < 4; nt++) {
            int row = gRowBase + mt * 16 + gq;
            int col = nt * 8 + 2 * t4;
            atomicAdd(&sg[row * 33 + col],           acc[mt][nt][0]);
            atomicAdd(&sg[row * 33 + col + 1],       acc[mt][nt][1]);
            atomicAdd(&sg[(row + 8) * 33 + col],     acc[mt][nt][2]);
            atomicAdd(&sg[(row + 8) * 33 + col + 1], acc[mt][nt][3]);
        }
}

__global__ __launch_bounds__(256, 1)
void rec_persist(const float* __restrict__ Whh, const float* __restrict__ xw,
                 float* __restrict__ cst,
                 __half* __restrict__ hi0, __half* __restrict__ hi1,
                 __half* __restrict__ ysAh, __half* __restrict__ ysAl,
                 float* __restrict__ hT, int H, int Kpad, int NJ)
{
    extern __shared__ char sraw[];
    const int BSTR = Kpad + 8;
    __half* Bh = (__half*)sraw;
    __half* Bl = Bh + 32 * BSTR;
    __half* Ah = Bl + 32 * BSTR;
    float*  sg = (float*)(Ah + 2 * ABUF);

    const int tid  = threadIdx.x;
    const int lane = tid & 31;
    const int warp = tid >> 5;
    const int wq   = warp & 3;
    const int wm   = warp >> 2;
    const int gRowBase = wm * 48;
    const int rowBaseS = wq * 80 + wm * 48;
    const int j0   = blockIdx.x * 8;

    // prologue: this CTA's 32 Whh rows -> resident smem (fp16 hi/lo, W exact)
    {
        int Kh = Kpad >> 1;
        for (int idx = tid; idx < 32 * Kh; idx += 256) {
            int r  = idx / Kh;
            int kp = idx - r * Kh;
            int k  = 2 * kp;
            int gate = r >> 3, jj = r & 7;
            int j = j0 + jj;
            float x = 0.f, y = 0.f;
            if (j < H) {
                const float* wp = Whh + (size_t)(gate * H + j) * H;
                if (k < H)     x = wp[k];
                if (k + 1 < H) y = wp[k + 1];
            }
            __half hx = __float2half_rn(x);
            __half hy = __float2half_rn(y);
            *(__half2*)&Bh[r * BSTR + k] = __halves2half2(hx, hy);
            *(__half2*)&Bl[r * BSTR + k] =
                __halves2half2(__float2half_rn(x - __half2float(hx)),
                               __float2half_rn(y - __half2float(hy)));
        }
    }
    __syncthreads();

    for (int t = 0; t < Tt; t++) {
        const __half* hiR = (t & 1) ? hi1 : hi0;
        __half* hiW = (t & 1) ? hi0 : hi1;
        const float* xw_t = xw + (size_t)t * Bb * 4 * H;

        for (int i = tid; i < 80 * 33; i += 256) sg[i] = 0.f;
        __syncthreads();

        if (wm == 0)
            rec_step_gemm<3>(hiR, Bh, Bl, Ah, sg,
                             BSTR, Kpad, lane, wq, gRowBase, rowBaseS);
        else
            rec_step_gemm<2>(hiR, Bh, Bl, Ah, sg,
                             BSTR, Kpad, lane, wq, gRowBase, rowBaseS);
        __syncthreads();

        // LSTM cell + plane writes
        for (int e = tid; e < Bb * 8; e += 256) {
            int row = e >> 3, jj = e & 7;
            int j = j0 + jj;
            if (j >= H) continue;
            const float* xr = xw_t + (size_t)row * 4 * H;
            float gi = sg[row * 33 + jj]      + xr[j];
            float gf = sg[row * 33 + 8 + jj]  + xr[H + j];
            float gg = sg[row * 33 + 16 + jj] + xr[2 * H + j];
            float go = sg[row * 33 + 24 + jj] + xr[3 * H + j];
            float cv = cst[(size_t)row * H + j];
            float cn = sigf(gf) * cv + sigf(gi) * tanhf(gg);
            float hn = sigf(go) * tanhf(cn);
            cst[(size_t)row * H + j] = cn;
            __half hh = __float2half_rn(hn);
            __half hl = __float2half_rn(hn - __half2float(hh));
            hiW[(size_t)row * Kpad + j] = hh;
            size_t yoff = ((size_t)t * Bb + row) * Kpad + j;
            ysAh[yoff] = hh;
            ysAl[yoff] = hl;
            if (t == Tt - 1) hT[(size_t)row * H + j] = hn;
        }

        // device-wide barrier (monotonic counter)
        __syncthreads();
        if (tid == 0) {
            __threadfence();
            atomicAdd(&g_bar, 1u);
            unsigned target = (unsigned)NJ * (unsigned)(t + 1);
            while (*(volatile unsigned*)&g_bar < target) { }
            __threadfence();
        }
        __syncthreads();
    }
}

// ---------------- prep: h0 -> hi plane, zero pong buf, zero barrier ----
__global__ void prep_h_kernel(const float* __restrict__ h0,
                              __half* __restrict__ hHi0, __half* __restrict__ hHi1,
                              int H, int Kpad)
{
    int idx = blockIdx.x * blockDim.x + threadIdx.x;
    if (idx == 0) g_bar = 0;
    if (idx >= Bb * Kpad) return;
    int row = idx / Kpad, j = idx - row * Kpad;
    float v = (j < H) ? h0[(size_t)row * H + j] : 0.f;
    hHi0[idx] = __float2half_rn(v);
    hHi1[idx] = __ushort_as_half(0);
}

__global__ void copy_f32(float* __restrict__ dst, const float* __restrict__ src, int n) {
    int i = blockIdx.x * blockDim.x + threadIdx.x;
    if (i < n) dst[i] = src[i];
}

// ---------------- host orchestration ----------------
static inline int ceil_div(int a, int b) { return (a + b - 1) / b; }

extern "C" void kernel_launch(void* const* d_in, const int* in_sizes, int n_in,
                              void* d_out, int out_size)
{
    const int*   tokens = (const int*)d_in[0];
    const float* emb_W  = (const float*)d_in[1];
    const float* dec_W  = (const float*)d_in[2];
    const float* dec_b  = (const float*)d_in[3];

    const float *Wih[3], *Whh[3], *bih[3], *bhh[3], *h0[3], *c0[3];
    for (int l = 0; l < 3; l++) {
        int base = 4 + l * 6;
        Wih[l] = (const float*)d_in[base + 0];
        Whh[l] = (const float*)d_in[base + 1];
        bih[l] = (const float*)d_in[base + 2];
        bhh[l] = (const float*)d_in[base + 3];
        h0[l]  = (const float*)d_in[base + 4];
        c0[l]  = (const float*)d_in[base + 5];
    }

    float *pXW, *pc, *phT;
    __half *pHi, *pAh0, *pAl0, *pAh1, *pAl1, *pWh;
    cudaGetSymbolAddress((void**)&pXW, g_XW);
    cudaGetSymbolAddress((void**)&pc,  g_c);
    cudaGetSymbolAddress((void**)&phT, g_hT);
    cudaGetSymbolAddress((void**)&pHi, g_hHi);
    cudaGetSymbolAddress((void**)&pAh0, g_Ahi);
    cudaGetSymbolAddress((void**)&pAl0, g_Alo);
    cudaGetSymbolAddress((void**)&pWh,  g_Whi);
    pAh1 = pAh0 + (size_t)TB * KPAD_MAX;
    pAl1 = pAl0 + (size_t)TB * KPAD_MAX;

    float* out = (float*)d_out;

    // opt-in smem
    {
        int recBytes = (2 * 32 * (KPAD_MAX + 8) + 2 * ABUF) * 2 + 80 * 33 * 4;
        cudaFuncSetAttribute(rec_persist,
                             cudaFuncAttributeMaxDynamicSharedMemorySize, recBytes);
        cudaFuncSetAttribute(hgemm_f16<2>,
                             cudaFuncAttributeMaxDynamicSharedMemorySize, 4 * 3 * 4096);
        cudaFuncSetAttribute(hgemm_f16<1>,
                             cudaFuncAttributeMaxDynamicSharedMemorySize, 4 * 2 * 4096);
    }

    // 1) embedding -> A planes (ping buffer), stride Ee=400
    {
        int n = TB * Ee;
        embed_planes<<<ceil_div(n, 256), 256>>>(tokens, emb_W, pAh0, pAl0, n);
    }

    const int Hd[3]  = {Hh, Hh, Ee};      // hidden size per layer
    const int KpI[3] = {400, 1152, 1152}; // input-GEMM K (= padded input width)
    const int KpR[3] = {1152, 1152, 448}; // recurrence Kpad = ys-plane stride
    __half *aHin = pAh0, *aLin = pAl0;
    __half *aHout = pAh1, *aLout = pAl1;
    size_t out_off = (size_t)TB * Vv;

    for (int l = 0; l < 3; l++) {
        int H = Hd[l], N4 = 4 * H;
        int KI = KpI[l];

        // weight hi plane (zero-padded to KI)
        splitW_kernel<<<ceil_div(N4 * KI, 256), 256>>>(Wih[l], pWh, N4, (l == 0) ? Ee : Hh, KI);

        // xW = (Ah+Al) @ Wh^T + bih + bhh  — 2-pass fp16 planes
        {
            dim3 grid(ceil_div(N4, 128), ceil_div(TB, 128));
            hgemm_f16<2><<<grid, 256, 4 * 3 * 4096>>>(
                aHin, aLin, pWh, bih[l], bhh[l], pXW, TB, N4, KI, KI, KI);
        }

        // init h plane + barrier + c
        {
            int n = Bb * KpR[l];
            prep_h_kernel<<<ceil_div(n, 256), 256>>>(
                h0[l], pHi, pHi + Bb * KPAD_MAX, H, KpR[l]);
            copy_f32<<<ceil_div(Bb * H, 256), 256>>>(pc, c0[l], Bb * H);
        }

        // persistent recurrent kernel (writes ys planes into the out buffers)
        {
            int NJ = ceil_div(H, 8);
            int smemBytes = (2 * 32 * (KpR[l] + 8) + 2 * ABUF) * 2 + 80 * 33 * 4;
            rec_persist<<<NJ, 256, smemBytes>>>(
                Whh[l], pXW, pc,
                pHi, pHi + Bb * KPAD_MAX,
                aHout, aLout, phT, H, KpR[l], NJ);
        }

        copy_f32<<<ceil_div(Bb * H, 256), 256>>>(out + out_off, phT, Bb * H);
        out_off += (size_t)Bb * H;
        copy_f32<<<ceil_div(Bb * H, 256), 256>>>(out + out_off, pc, Bb * H);
        out_off += (size_t)Bb * H;

        // swap plane buffers
        __half* th = aHin; aHin = aHout; aHout = th;
        __half* tl = aLin; aLin = aLout; aLout = tl;
    }

    // 2) decoder: decoded = ysHi @ dec_Wh^T + dec_b — 1-pass fp16 planes
    //    ys planes of layer 3 have stride 448; K=400 so padding is never read.
    {
        splitW_kernel<<<ceil_div(Vv * Ee, 256), 256>>>(dec_W, pWh, Vv, Ee, Ee);
        dim3 grid(ceil_div(Vv, 128), ceil_div(TB, 128));
        hgemm_f16<1><<<grid, 256, 4 * 2 * 4096>>>(
            aHin, nullptr, pWh, dec_b, nullptr, out, TB, Vv, Ee, 448, Ee);
    }
}

// round 10
// speedup vs baseline: 4.9265x; 1.0994x over previous
#include <cuda_runtime.h>
#include <cuda_fp16.h>
#include <math.h>
#include <stdint.h>

// Problem constants
#define Tt 70
#define Bb 80
#define Vv 33278
#define Ee 400
#define Hh 1150
#define TB (Tt*Bb)          // 5600
#define KPAD_MAX 1152

// ---------------- scratch (device globals; no allocation) ----------------
__device__ float  g_hT[Bb * Hh];
__device__ float  g_XW[(size_t)TB * 4 * Hh + 32];   // +pad for 8B prefetch overshoot
__device__ float  g_c[Bb * Hh];
__device__ __half g_h0p[Bb * KPAD_MAX];             // h0 plane
__device__ unsigned g_bar;
// fp16 activation hi planes (ping/pong), stride up to 1152
__device__ __align__(128) __half g_Ahi[2][(size_t)TB * KPAD_MAX];
// fp16 weight hi plane (max: Wih 4600x1152 = 5.3M / dec_W 33278x400 = 13.4M)
__device__ __align__(128) __half g_Whi[(size_t)13600000];

// ---------------- ptx helpers ----------------
__device__ __forceinline__ void mma_f16(float* c, const uint32_t* a, const uint32_t* b) {
    asm volatile(
        "mma.sync.aligned.m16n8k16.row.col.f32.f16.f16.f32 "
        "{%0,%1,%2,%3}, {%4,%5,%6,%7}, {%8,%9}, {%0,%1,%2,%3};"
        : "+f"(c[0]), "+f"(c[1]), "+f"(c[2]), "+f"(c[3])
        : "r"(a[0]), "r"(a[1]), "r"(a[2]), "r"(a[3]), "r"(b[0]), "r"(b[1]));
}
__device__ __forceinline__ uint32_t smem_u32(const void* p) {
    return (uint32_t)__cvta_generic_to_shared(p);
}
__device__ __forceinline__ void ldsm4(uint32_t* r, uint32_t addr) {
    asm volatile("ldmatrix.sync.aligned.m8n8.x4.shared.b16 {%0,%1,%2,%3}, [%4];"
                 : "=r"(r[0]), "=r"(r[1]), "=r"(r[2]), "=r"(r[3]) : "r"(addr));
}
__device__ __forceinline__ void cp_async16(uint32_t dst, const void* src) {
    asm volatile("cp.async.cg.shared.global [%0], [%1], 16;" :: "r"(dst), "l"(src));
}
__device__ __forceinline__ void cp_async8(uint32_t dst, const void* src) {
    asm volatile("cp.async.ca.shared.global [%0], [%1], 8;" :: "r"(dst), "l"(src));
}
__device__ __forceinline__ void cp_commit() {
    asm volatile("cp.async.commit_group;" ::: "memory");
}
__device__ __forceinline__ void cp_wait1() {
    asm volatile("cp.async.wait_group 1;" ::: "memory");
}
__device__ __forceinline__ void cp_wait2() {
    asm volatile("cp.async.wait_group 2;" ::: "memory");
}
__device__ __forceinline__ void cp_wait0() {
    asm volatile("cp.async.wait_group 0;" ::: "memory");
}

// ---------------- embedding gather -> fp16 hi plane ----------------
__global__ void embed_hi(const int* __restrict__ tokens,
                         const float* __restrict__ emb,
                         __half* __restrict__ Ah, int n) {
    int idx = blockIdx.x * blockDim.x + threadIdx.x;
    if (idx >= n) return;
    int tb = idx / Ee;
    int e  = idx - tb * Ee;
    Ah[idx] = __float2half_rn(emb[(size_t)tokens[tb] * Ee + e]);
}

// ---------------- weight split: f32 [rows][K] -> fp16 hi [rows][Kpad] ------
__global__ void splitW_kernel(const float* __restrict__ W, __half* __restrict__ Wh,
                              int rows, int K, int Kpad) {
    int idx = blockIdx.x * blockDim.x + threadIdx.x;
    if (idx >= rows * Kpad) return;
    int r = idx / Kpad, k = idx - r * Kpad;
    Wh[idx] = (k < K) ? __float2half_rn(W[(size_t)r * K + k]) : __ushort_as_half(0);
}

// ============================================================================
// 1-pass fp16-plane GEMM: C[M,N] = Ah[M,K] * Wh[N,K]^T + bias
// CTA 128x128, 8 warps 2(m)x4(n), warp 64x32, BK=16, 4-stage cp.async.
// ============================================================================
__global__ __launch_bounds__(256)
void hgemm_f16(const __half* __restrict__ Ah, const __half* __restrict__ Wh,
               const float* __restrict__ bias0, const float* __restrict__ bias1,
               float* __restrict__ C, int M, int N, int K, int lda, int ldw)
{
    extern __shared__ __half smem[];
    const int TPS = 128 * 16 * 2;    // halves per stage (A tile + W tile)

    const int tid  = threadIdx.x;
    const int lane = tid & 31;
    const int warp = tid >> 5;
    const int wm   = warp >> 2;
    const int wn   = warp & 3;
    const int g    = lane >> 2;
    const int t4   = lane & 3;
    const int bm   = blockIdx.y * 128;
    const int bn   = blockIdx.x * 128;

    float acc[4][4][4];
#pragma unroll
    for (int i = 0; i < 4; i++)
#pragma unroll
        for (int j = 0; j < 4; j++)
#pragma unroll
            for (int q = 0; q < 4; q++) acc[i][j][q] = 0.f;

    const int row = tid >> 1;
    const int seg = tid & 1;

    auto issue = [&](int c, int s) {
        __half* st = smem + s * TPS;
        const int koff = c * 16 + seg * 8;
        {
            uint32_t dst = smem_u32(st + row * 16 + seg * 8);
            int gm = bm + row;
            if (gm < M) cp_async16(dst, Ah + (size_t)gm * lda + koff);
            else        *(float4*)(st + row * 16 + seg * 8) = make_float4(0.f,0.f,0.f,0.f);
        }
        {
            __half* bt = st + 2048;
            uint32_t dst = smem_u32(bt + row * 16 + seg * 8);
            int gn = bn + row;
            if (gn < N) cp_async16(dst, Wh + (size_t)gn * ldw + koff);
            else        *(float4*)(bt + row * 16 + seg * 8) = make_float4(0.f,0.f,0.f,0.f);
        }
    };

    const int NCH = K >> 4;
    issue(0, 0); cp_commit();
    issue(1, 1); cp_commit();
    issue(2, 2); cp_commit();

    for (int c = 0; c < NCH; c++) {
        cp_wait2();
        __syncthreads();
        __half* st  = smem + (c & 3) * TPS;
        __half* AsH = st;
        __half* BsH = st + 2048;

        uint32_t ah[4][4], bh[4][2];
#pragma unroll
        for (int mt = 0; mt < 4; mt++) {
            int r0 = wm * 64 + mt * 16 + g;
            ah[mt][0] = *(const uint32_t*)&AsH[r0 * 16 + 2 * t4];
            ah[mt][1] = *(const uint32_t*)&AsH[(r0 + 8) * 16 + 2 * t4];
            ah[mt][2] = *(const uint32_t*)&AsH[r0 * 16 + 2 * t4 + 8];
            ah[mt][3] = *(const uint32_t*)&AsH[(r0 + 8) * 16 + 2 * t4 + 8];
        }
#pragma unroll
        for (int nt = 0; nt < 4; nt++) {
            int n0 = wn * 32 + nt * 8 + g;
            bh[nt][0] = *(const uint32_t*)&BsH[n0 * 16 + 2 * t4];
            bh[nt][1] = *(const uint32_t*)&BsH[n0 * 16 + 2 * t4 + 8];
        }

        if (c + 3 < NCH) issue(c + 3, (c + 3) & 3);
        cp_commit();

#pragma unroll
        for (int mt = 0; mt < 4; mt++)
#pragma unroll
            for (int nt = 0; nt < 4; nt++)
                mma_f16(acc[mt][nt], ah[mt], bh[nt]);
    }

#pragma unroll
    for (int mt = 0; mt < 4; mt++) {
#pragma unroll
        for (int nt = 0; nt < 4; nt++) {
            int r0 = bm + wm * 64 + mt * 16 + g;
            int cc = bn + wn * 32 + nt * 8 + 2 * t4;
            if (cc >= N) continue;
            float bv0 = 0.f, bv1 = 0.f;
            if (bias0) { bv0 += bias0[cc]; bv1 += bias0[cc + 1]; }
            if (bias1) { bv0 += bias1[cc]; bv1 += bias1[cc + 1]; }
            if (r0 < M)
                *(float2*)(C + (size_t)r0 * N + cc) =
                    make_float2(acc[mt][nt][0] + bv0, acc[mt][nt][1] + bv1);
            if (r0 + 8 < M)
                *(float2*)(C + (size_t)(r0 + 8) * N + cc) =
                    make_float2(acc[mt][nt][2] + bv0, acc[mt][nt][3] + bv1);
        }
    }
}

// ============================================================================
// Persistent recurrent kernel — R10:
//  * c state in registers for all 70 steps (written out once at the end)
//  * xw_t prefetched to smem via cp.async, overlapped with the step GEMM
//  * h read directly from ys plane of step t-1 (no ping-pong h buffers)
//  * GEMM: 2-pass keep-W-exact (Ah.Bh + Ah.Bl), W resident in smem
// ============================================================================
__device__ __forceinline__ float sigf(float x) { return 1.f / (1.f + expf(-x)); }

#define ASTR 24
#define AROWS 320
#define ABUF (AROWS*ASTR)
#define XWSTR 36     // sxw row stride (floats)

template<int MTW>
__device__ __forceinline__ void rec_step_gemm(
    const __half* __restrict__ hiR,
    const __half* Bh, const __half* Bl, __half* Ah, float* sg,
    int BSTR, int Kpad, int lane, int wq, int gRowBase, int rowBaseS)
{
    const int NC   = Kpad >> 4;
    const int ncq  = NC >> 2;
    const int cbeg = wq * ncq;

    float acc[MTW][4][4];
#pragma unroll
    for (int mt = 0; mt < MTW; mt++)
#pragma unroll
        for (int nt = 0; nt < 4; nt++)
#pragma unroll
            for (int q = 0; q < 4; q++) acc[mt][nt][q] = 0.f;

    auto issue = [&](int c, int buf) {
#pragma unroll
        for (int r = 0; r < MTW; r++) {
            int e   = lane + 32 * r;
            int row = e >> 1;
            int seg = e & 1;
            const __half* src = hiR + (size_t)(gRowBase + row) * Kpad + c * 16 + seg * 8;
            __half* dstp = Ah + buf * ABUF + (rowBaseS + row) * ASTR + seg * 8;
            cp_async16(smem_u32(dstp), src);
        }
    };

    issue(cbeg, 0);     cp_commit();
    issue(cbeg + 1, 1); cp_commit();

    for (int i = 0; i < ncq; i++) {
        const int c   = cbeg + i;
        const int buf = i & 1;
        cp_wait1();
        __syncwarp();

        uint32_t bh0[4], bh1[4], bl0[4], bl1[4];
        {
            int k0 = c * 16;
            ldsm4(bh0, smem_u32(Bh + (size_t)lane * BSTR + k0));
            ldsm4(bh1, smem_u32(Bh + (size_t)lane * BSTR + k0 + 8));
            ldsm4(bl0, smem_u32(Bl + (size_t)lane * BSTR + k0));
            ldsm4(bl1, smem_u32(Bl + (size_t)lane * BSTR + k0 + 8));
        }
        uint32_t ah[MTW][4];
        {
            int rA   = rowBaseS + (lane & 7) + ((lane >> 3) & 1) * 8;
            int kseg = (lane >> 4) * 8;
#pragma unroll
            for (int mt = 0; mt < MTW; mt++)
                ldsm4(ah[mt], smem_u32(Ah + buf * ABUF + (rA + mt * 16) * ASTR + kseg));
        }
        if (i + 2 < ncq) issue(c + 2, buf);
        cp_commit();

#pragma unroll
        for (int mt = 0; mt < MTW; mt++)
#pragma unroll
            for (int nt = 0; nt < 4; nt++) {
                uint32_t bb[2]  = { bh0[nt], bh1[nt] };
                uint32_t bbl[2] = { bl0[nt], bl1[nt] };
                mma_f16(acc[mt][nt], ah[mt], bb);
                mma_f16(acc[mt][nt], ah[mt], bbl);
            }
    }

    const int gq = lane >> 2;
    const int t4 = lane & 3;
#pragma unroll
    for (int mt = 0; mt < MTW; mt++)
#pragma unroll
        for (int nt = 0; nt < 4; nt++) {
            int row = gRowBase + mt * 16 + gq;
            int col = nt * 8 + 2 * t4;
            atomicAdd(&sg[row * 33 + col],           acc[mt][nt][0]);
            atomicAdd(&sg[row * 33 + col + 1],       acc[mt][nt][1]);
            atomicAdd(&sg[(row + 8) * 33 + col],     acc[mt][nt][2]);
            atomicAdd(&sg[(row + 8) * 33 + col + 1], acc[mt][nt][3]);
        }
}

__global__ __launch_bounds__(256, 1)
void rec_persist(const float* __restrict__ Whh, const float* __restrict__ xw,
                 const float* __restrict__ c0, float* __restrict__ cOut,
                 const __half* __restrict__ h0p,
                 __half* __restrict__ ysAh,
                 float* __restrict__ hT, int H, int Kpad, int NJ)
{
    extern __shared__ char sraw[];
    const int BSTR = Kpad + 8;
    __half* Bh  = (__half*)sraw;               // [32][BSTR]
    __half* Bl  = Bh + 32 * BSTR;
    __half* Ah  = Bl + 32 * BSTR;              // [2][AROWS][ASTR]
    float*  sg  = (float*)(Ah + 2 * ABUF);     // [80][33]
    float*  sxw = sg + 80 * 33;                // [80][XWSTR]

    const int tid  = threadIdx.x;
    const int lane = tid & 31;
    const int warp = tid >> 5;
    const int wq   = warp & 3;
    const int wm   = warp >> 2;
    const int gRowBase = wm * 48;
    const int rowBaseS = wq * 80 + wm * 48;
    const int j0   = blockIdx.x * 8;
    const int N4   = 4 * H;

    // prologue: this CTA's 32 Whh rows -> resident smem (fp16 hi/lo, W exact)
    {
        int Kh = Kpad >> 1;
        for (int idx = tid; idx < 32 * Kh; idx += 256) {
            int r  = idx / Kh;
            int kp = idx - r * Kh;
            int k  = 2 * kp;
            int gate = r >> 3, jj = r & 7;
            int j = j0 + jj;
            float x = 0.f, y = 0.f;
            if (j < H) {
                const float* wp = Whh + (size_t)(gate * H + j) * H;
                if (k < H)     x = wp[k];
                if (k + 1 < H) y = wp[k + 1];
            }
            __half hx = __float2half_rn(x);
            __half hy = __float2half_rn(y);
            *(__half2*)&Bh[r * BSTR + k] = __halves2half2(hx, hy);
            *(__half2*)&Bl[r * BSTR + k] =
                __halves2half2(__float2half_rn(x - __half2float(hx)),
                               __float2half_rn(y - __half2float(hy)));
        }
    }

    // c state -> registers (each thread owns up to 3 cells for all steps)
    float creg[3] = {0.f, 0.f, 0.f};
#pragma unroll
    for (int q = 0; q < 3; q++) {
        int e = tid + q * 256;
        if (e < Bb * 8) {
            int row = e >> 3, jj = e & 7;
            int j = j0 + jj;
            if (j < H) creg[q] = c0[(size_t)row * H + j];
        }
    }
    __syncthreads();

    for (int t = 0; t < Tt; t++) {
        const __half* hiR = (t == 0) ? h0p : ysAh + (size_t)(t - 1) * Bb * Kpad;
        const float* xw_t = xw + (size_t)t * Bb * N4;

        // zero gate tile
        for (int i = tid; i < 80 * 33; i += 256) sg[i] = 0.f;

        // prefetch xw tile (80 rows x 4 gates x 8 floats) via cp.async, 8B units
        {
#pragma unroll
            for (int q = 0; q < 5; q++) {
                int u = tid + q * 256;            // 0..1279
                int row  = u >> 4;
                int v    = u & 15;
                int gate = v >> 2;
                int pr   = v & 3;                 // pair index (2 floats)
                const float* src = xw_t + (size_t)row * N4 + gate * H + j0 + 2 * pr;
                float* dst = sxw + row * XWSTR + gate * 8 + 2 * pr;
                cp_async8(smem_u32(dst), src);
            }
            cp_commit();
        }
        __syncthreads();   // sg zero visible before atomic combines

        if (wm == 0)
            rec_step_gemm<3>(hiR, Bh, Bl, Ah, sg,
                             BSTR, Kpad, lane, wq, gRowBase, rowBaseS);
        else
            rec_step_gemm<2>(hiR, Bh, Bl, Ah, sg,
                             BSTR, Kpad, lane, wq, gRowBase, rowBaseS);
        cp_wait0();
        __syncthreads();

        // LSTM cell — gates from sg + sxw (both smem), c in registers
#pragma unroll
        for (int q = 0; q < 3; q++) {
            int e = tid + q * 256;
            if (e >= Bb * 8) break;
            int row = e >> 3, jj = e & 7;
            int j = j0 + jj;
            if (j >= H) continue;
            const float* xr = sxw + row * XWSTR;
            float gi = sg[row * 33 + jj]      + xr[jj];
            float gf = sg[row * 33 + 8 + jj]  + xr[8 + jj];
            float gg = sg[row * 33 + 16 + jj] + xr[16 + jj];
            float go = sg[row * 33 + 24 + jj] + xr[24 + jj];
            float cn = sigf(gf) * creg[q] + sigf(gi) * tanhf(gg);
            float hn = sigf(go) * tanhf(cn);
            creg[q] = cn;
            ysAh[((size_t)t * Bb + row) * Kpad + j] = __float2half_rn(hn);
            if (t == Tt - 1) {
                hT[(size_t)row * H + j]   = hn;
                cOut[(size_t)row * H + j] = cn;
            }
        }

        // device-wide barrier (monotonic counter)
        __syncthreads();
        if (tid == 0) {
            __threadfence();
            atomicAdd(&g_bar, 1u);
            unsigned target = (unsigned)NJ * (unsigned)(t + 1);
            while (*(volatile unsigned*)&g_bar < target) { }
            __threadfence();
        }
        __syncthreads();
    }
}

// ---------------- prep: h0 -> hi plane, zero barrier ----
__global__ void prep_h_kernel(const float* __restrict__ h0,
                              __half* __restrict__ h0p, int H, int Kpad)
{
    int idx = blockIdx.x * blockDim.x + threadIdx.x;
    if (idx == 0) g_bar = 0;
    if (idx >= Bb * Kpad) return;
    int row = idx / Kpad, j = idx - row * Kpad;
    h0p[idx] = (j < H) ? __float2half_rn(h0[(size_t)row * H + j]) : __ushort_as_half(0);
}

__global__ void copy_f32(float* __restrict__ dst, const float* __restrict__ src, int n) {
    int i = blockIdx.x * blockDim.x + threadIdx.x;
    if (i < n) dst[i] = src[i];
}

// ---------------- host orchestration ----------------
static inline int ceil_div(int a, int b) { return (a + b - 1) / b; }

extern "C" void kernel_launch(void* const* d_in, const int* in_sizes, int n_in,
                              void* d_out, int out_size)
{
    const int*   tokens = (const int*)d_in[0];
    const float* emb_W  = (const float*)d_in[1];
    const float* dec_W  = (const float*)d_in[2];
    const float* dec_b  = (const float*)d_in[3];

    const float *Wih[3], *Whh[3], *bih[3], *bhh[3], *h0[3], *c0[3];
    for (int l = 0; l < 3; l++) {
        int base = 4 + l * 6;
        Wih[l] = (const float*)d_in[base + 0];
        Whh[l] = (const float*)d_in[base + 1];
        bih[l] = (const float*)d_in[base + 2];
        bhh[l] = (const float*)d_in[base + 3];
        h0[l]  = (const float*)d_in[base + 4];
        c0[l]  = (const float*)d_in[base + 5];
    }

    float *pXW, *pc, *phT;
    __half *pH0p, *pAh0, *pAh1, *pWh;
    cudaGetSymbolAddress((void**)&pXW, g_XW);
    cudaGetSymbolAddress((void**)&pc,  g_c);
    cudaGetSymbolAddress((void**)&phT, g_hT);
    cudaGetSymbolAddress((void**)&pH0p, g_h0p);
    cudaGetSymbolAddress((void**)&pAh0, g_Ahi);
    cudaGetSymbolAddress((void**)&pWh,  g_Whi);
    pAh1 = pAh0 + (size_t)TB * KPAD_MAX;

    float* out = (float*)d_out;

    // opt-in smem
    {
        int recBytes = 2 * 32 * (KPAD_MAX + 8) * 2 + 2 * ABUF * 2
                     + 80 * 33 * 4 + 80 * XWSTR * 4;
        cudaFuncSetAttribute(rec_persist,
                             cudaFuncAttributeMaxDynamicSharedMemorySize, recBytes);
        cudaFuncSetAttribute(hgemm_f16,
                             cudaFuncAttributeMaxDynamicSharedMemorySize, 4 * 2 * 4096);
    }

    // 1) embedding -> hi plane (ping), stride Ee=400
    {
        int n = TB * Ee;
        embed_hi<<<ceil_div(n, 256), 256>>>(tokens, emb_W, pAh0, n);
    }

    const int Hd[3]  = {Hh, Hh, Ee};      // hidden size per layer
    const int KpI[3] = {400, 1152, 1152}; // input-GEMM K / A stride
    const int KpR[3] = {1152, 1152, 448}; // recurrence Kpad = ys stride
    const int Wk[3]  = {Ee, Hh, Hh};      // true input width (W K)
    __half *aHin = pAh0, *aHout = pAh1;
    size_t out_off = (size_t)TB * Vv;

    for (int l = 0; l < 3; l++) {
        int H = Hd[l], N4 = 4 * H;
        int KI = KpI[l];

        // weight hi plane (zero-padded to KI)
        splitW_kernel<<<ceil_div(N4 * KI, 256), 256>>>(Wih[l], pWh, N4, Wk[l], KI);

        // xW = Ah @ Wh^T + bih + bhh  — 1-pass fp16 planes
        {
            dim3 grid(ceil_div(N4, 128), ceil_div(TB, 128));
            hgemm_f16<<<grid, 256, 4 * 2 * 4096>>>(
                aHin, pWh, bih[l], bhh[l], pXW, TB, N4, KI, KI, KI);
        }

        // init h0 plane + barrier
        {
            int n = Bb * KpR[l];
            prep_h_kernel<<<ceil_div(n, 256), 256>>>(h0[l], pH0p, H, KpR[l]);
        }

        // persistent recurrent kernel (writes ys hi plane into aHout)
        {
            int NJ = ceil_div(H, 8);
            int smemBytes = 2 * 32 * (KpR[l] + 8) * 2 + 2 * ABUF * 2
                          + 80 * 33 * 4 + 80 * XWSTR * 4;
            rec_persist<<<NJ, 256, smemBytes>>>(
                Whh[l], pXW, c0[l], pc, pH0p, aHout, phT, H, KpR[l], NJ);
        }

        copy_f32<<<ceil_div(Bb * H, 256), 256>>>(out + out_off, phT, Bb * H);
        out_off += (size_t)Bb * H;
        copy_f32<<<ceil_div(Bb * H, 256), 256>>>(out + out_off, pc, Bb * H);
        out_off += (size_t)Bb * H;

        __half* th = aHin; aHin = aHout; aHout = th;
    }

    // 2) decoder: decoded = ysHi @ dec_Wh^T + dec_b — 1-pass fp16 planes
    //    layer-3 ys stride 448, K=400 (padding cols are never read: K=400<448? 
    //    NCH=25 covers k<400 only)
    {
        splitW_kernel<<<ceil_div(Vv * Ee, 256), 256>>>(dec_W, pWh, Vv, Ee, Ee);
        dim3 grid(ceil_div(Vv, 128), ceil_div(TB, 128));
        hgemm_f16<<<grid, 256, 4 * 2 * 4096>>>(
            aHin, pWh, dec_b, nullptr, out, TB, Vv, Ee, 448, Ee);
    }
}

// round 11
// speedup vs baseline: 5.3389x; 1.0837x over previous
#include <cuda_runtime.h>
#include <cuda_fp16.h>
#include <math.h>
#include <stdint.h>

// Problem constants
#define Tt 70
#define Bb 80
#define Vv 33278
#define Ee 400
#define Hh 1150
#define TB (Tt*Bb)          // 5600
#define KPAD_MAX 1152

// ---------------- scratch (device globals; no allocation) ----------------
__device__ float  g_hT[Bb * Hh];
__device__ float  g_XW[(size_t)TB * 4 * Hh + 32];
__device__ float  g_c[Bb * Hh];
__device__ __half g_h0p[Bb * KPAD_MAX];
__device__ unsigned g_bar;
__device__ __align__(128) __half g_Ahi[2][(size_t)TB * KPAD_MAX];
__device__ __align__(128) __half g_Whi[(size_t)13600000];

// ---------------- ptx helpers ----------------
__device__ __forceinline__ void mma_f16(float* c, const uint32_t* a, const uint32_t* b) {
    asm volatile(
        "mma.sync.aligned.m16n8k16.row.col.f32.f16.f16.f32 "
        "{%0,%1,%2,%3}, {%4,%5,%6,%7}, {%8,%9}, {%0,%1,%2,%3};"
        : "+f"(c[0]), "+f"(c[1]), "+f"(c[2]), "+f"(c[3])
        : "r"(a[0]), "r"(a[1]), "r"(a[2]), "r"(a[3]), "r"(b[0]), "r"(b[1]));
}
__device__ __forceinline__ uint32_t smem_u32(const void* p) {
    return (uint32_t)__cvta_generic_to_shared(p);
}
__device__ __forceinline__ void ldsm4(uint32_t* r, uint32_t addr) {
    asm volatile("ldmatrix.sync.aligned.m8n8.x4.shared.b16 {%0,%1,%2,%3}, [%4];"
                 : "=r"(r[0]), "=r"(r[1]), "=r"(r[2]), "=r"(r[3]) : "r"(addr));
}
__device__ __forceinline__ void cp_async16(uint32_t dst, const void* src) {
    asm volatile("cp.async.cg.shared.global [%0], [%1], 16;" :: "r"(dst), "l"(src));
}
__device__ __forceinline__ void cp_async8(uint32_t dst, const void* src) {
    asm volatile("cp.async.ca.shared.global [%0], [%1], 8;" :: "r"(dst), "l"(src));
}
__device__ __forceinline__ void cp_commit() {
    asm volatile("cp.async.commit_group;" ::: "memory");
}
__device__ __forceinline__ void cp_wait2() {
    asm volatile("cp.async.wait_group 2;" ::: "memory");
}
__device__ __forceinline__ void cp_wait0() {
    asm volatile("cp.async.wait_group 0;" ::: "memory");
}

// ---------------- embedding gather -> fp16 hi plane ----------------
__global__ void embed_hi(const int* __restrict__ tokens,
                         const float* __restrict__ emb,
                         __half* __restrict__ Ah, int n) {
    int idx = blockIdx.x * blockDim.x + threadIdx.x;
    if (idx >= n) return;
    int tb = idx / Ee;
    int e  = idx - tb * Ee;
    Ah[idx] = __float2half_rn(emb[(size_t)tokens[tb] * Ee + e]);
}

// ---------------- weight split ----------------
__global__ void splitW_kernel(const float* __restrict__ W, __half* __restrict__ Wh,
                              int rows, int K, int Kpad) {
    int idx = blockIdx.x * blockDim.x + threadIdx.x;
    if (idx >= rows * Kpad) return;
    int r = idx / Kpad, k = idx - r * Kpad;
    Wh[idx] = (k < K) ? __float2half_rn(W[(size_t)r * K + k]) : __ushort_as_half(0);
}

// ============================================================================
// 1-pass fp16-plane GEMM (proven R10): C = Ah * Wh^T + bias, 4-stage cp.async
// ============================================================================
__global__ __launch_bounds__(256)
void hgemm_f16(const __half* __restrict__ Ah, const __half* __restrict__ Wh,
               const float* __restrict__ bias0, const float* __restrict__ bias1,
               float* __restrict__ C, int M, int N, int K, int lda, int ldw)
{
    extern __shared__ __half smem[];
    const int TPS = 128 * 16 * 2;

    const int tid  = threadIdx.x;
    const int lane = tid & 31;
    const int warp = tid >> 5;
    const int wm   = warp >> 2;
    const int wn   = warp & 3;
    const int g    = lane >> 2;
    const int t4   = lane & 3;
    const int bm   = blockIdx.y * 128;
    const int bn   = blockIdx.x * 128;

    float acc[4][4][4];
#pragma unroll
    for (int i = 0; i < 4; i++)
#pragma unroll
        for (int j = 0; j < 4; j++)
#pragma unroll
            for (int q = 0; q < 4; q++) acc[i][j][q] = 0.f;

    const int row = tid >> 1;
    const int seg = tid & 1;

    auto issue = [&](int c, int s) {
        __half* st = smem + s * TPS;
        const int koff = c * 16 + seg * 8;
        {
            uint32_t dst = smem_u32(st + row * 16 + seg * 8);
            int gm = bm + row;
            if (gm < M) cp_async16(dst, Ah + (size_t)gm * lda + koff);
            else        *(float4*)(st + row * 16 + seg * 8) = make_float4(0.f,0.f,0.f,0.f);
        }
        {
            __half* bt = st + 2048;
            uint32_t dst = smem_u32(bt + row * 16 + seg * 8);
            int gn = bn + row;
            if (gn < N) cp_async16(dst, Wh + (size_t)gn * ldw + koff);
            else        *(float4*)(bt + row * 16 + seg * 8) = make_float4(0.f,0.f,0.f,0.f);
        }
    };

    const int NCH = K >> 4;
    issue(0, 0); cp_commit();
    issue(1, 1); cp_commit();
    issue(2, 2); cp_commit();

    for (int c = 0; c < NCH; c++) {
        cp_wait2();
        __syncthreads();
        __half* st  = smem + (c & 3) * TPS;
        __half* AsH = st;
        __half* BsH = st + 2048;

        uint32_t ah[4][4], bh[4][2];
#pragma unroll
        for (int mt = 0; mt < 4; mt++) {
            int r0 = wm * 64 + mt * 16 + g;
            ah[mt][0] = *(const uint32_t*)&AsH[r0 * 16 + 2 * t4];
            ah[mt][1] = *(const uint32_t*)&AsH[(r0 + 8) * 16 + 2 * t4];
            ah[mt][2] = *(const uint32_t*)&AsH[r0 * 16 + 2 * t4 + 8];
            ah[mt][3] = *(const uint32_t*)&AsH[(r0 + 8) * 16 + 2 * t4 + 8];
        }
#pragma unroll
        for (int nt = 0; nt < 4; nt++) {
            int n0 = wn * 32 + nt * 8 + g;
            bh[nt][0] = *(const uint32_t*)&BsH[n0 * 16 + 2 * t4];
            bh[nt][1] = *(const uint32_t*)&BsH[n0 * 16 + 2 * t4 + 8];
        }

        if (c + 3 < NCH) issue(c + 3, (c + 3) & 3);
        cp_commit();

#pragma unroll
        for (int mt = 0; mt < 4; mt++)
#pragma unroll
            for (int nt = 0; nt < 4; nt++)
                mma_f16(acc[mt][nt], ah[mt], bh[nt]);
    }

#pragma unroll
    for (int mt = 0; mt < 4; mt++) {
#pragma unroll
        for (int nt = 0; nt < 4; nt++) {
            int r0 = bm + wm * 64 + mt * 16 + g;
            int cc = bn + wn * 32 + nt * 8 + 2 * t4;
            if (cc >= N) continue;
            float bv0 = 0.f, bv1 = 0.f;
            if (bias0) { bv0 += bias0[cc]; bv1 += bias0[cc + 1]; }
            if (bias1) { bv0 += bias1[cc]; bv1 += bias1[cc + 1]; }
            if (r0 < M)
                *(float2*)(C + (size_t)r0 * N + cc) =
                    make_float2(acc[mt][nt][0] + bv0, acc[mt][nt][1] + bv1);
            if (r0 + 8 < M)
                *(float2*)(C + (size_t)(r0 + 8) * N + cc) =
                    make_float2(acc[mt][nt][2] + bv0, acc[mt][nt][3] + bv1);
        }
    }
}

// ============================================================================
// Persistent recurrent kernel — R11:
//  * 1-pass fp16 GEMM (W hi plane only; damped-error regime, R8-calibrated)
//  * 4-stage warp-private cp.async A pipeline (wait_group 2)
//  * split device barrier: arrive -> (zero sg + prefetch xw t+1) -> spin
//  * c in registers, h read from ys plane of t-1
// ============================================================================
__device__ __forceinline__ float sigf(float x) { return 1.f / (1.f + expf(-x)); }

#define ASTR 24
#define AROWS 320
#define ABUF (AROWS*ASTR)
#define XWSTR 36

template<int MTW>
__device__ __forceinline__ void rec_step_gemm(
    const __half* __restrict__ hiR,
    const __half* Bh, __half* Ah, float* sg,
    int BSTR, int Kpad, int lane, int wq, int gRowBase, int rowBaseS)
{
    const int NC   = Kpad >> 4;
    const int ncq  = NC >> 2;
    const int cbeg = wq * ncq;

    float acc[MTW][4][4];
#pragma unroll
    for (int mt = 0; mt < MTW; mt++)
#pragma unroll
        for (int nt = 0; nt < 4; nt++)
#pragma unroll
            for (int q = 0; q < 4; q++) acc[mt][nt][q] = 0.f;

    auto issue = [&](int c, int buf) {
#pragma unroll
        for (int r = 0; r < MTW; r++) {
            int e   = lane + 32 * r;
            int row = e >> 1;
            int seg = e & 1;
            const __half* src = hiR + (size_t)(gRowBase + row) * Kpad + c * 16 + seg * 8;
            __half* dstp = Ah + buf * ABUF + (rowBaseS + row) * ASTR + seg * 8;
            cp_async16(smem_u32(dstp), src);
        }
    };

    issue(cbeg, 0);     cp_commit();
    issue(cbeg + 1, 1); cp_commit();
    issue(cbeg + 2, 2); cp_commit();

    for (int i = 0; i < ncq; i++) {
        const int c   = cbeg + i;
        const int buf = i & 3;
        cp_wait2();
        __syncwarp();

        uint32_t bh0[4], bh1[4];
        {
            int k0 = c * 16;
            ldsm4(bh0, smem_u32(Bh + (size_t)lane * BSTR + k0));
            ldsm4(bh1, smem_u32(Bh + (size_t)lane * BSTR + k0 + 8));
        }
        uint32_t ah[MTW][4];
        {
            int rA   = rowBaseS + (lane & 7) + ((lane >> 3) & 1) * 8;
            int kseg = (lane >> 4) * 8;
#pragma unroll
            for (int mt = 0; mt < MTW; mt++)
                ldsm4(ah[mt], smem_u32(Ah + buf * ABUF + (rA + mt * 16) * ASTR + kseg));
        }
        if (i + 3 < ncq) issue(c + 3, (i + 3) & 3);
        cp_commit();

#pragma unroll
        for (int mt = 0; mt < MTW; mt++)
#pragma unroll
            for (int nt = 0; nt < 4; nt++) {
                uint32_t bb[2] = { bh0[nt], bh1[nt] };
                mma_f16(acc[mt][nt], ah[mt], bb);
            }
    }

    const int gq = lane >> 2;
    const int t4 = lane & 3;
#pragma unroll
    for (int mt = 0; mt < MTW; mt++)
#pragma unroll
        for (int nt = 0; nt < 4; nt++) {
            int row = gRowBase + mt * 16 + gq;
            int col = nt * 8 + 2 * t4;
            atomicAdd(&sg[row * 33 + col],           acc[mt][nt][0]);
            atomicAdd(&sg[row * 33 + col + 1],       acc[mt][nt][1]);
            atomicAdd(&sg[(row + 8) * 33 + col],     acc[mt][nt][2]);
            atomicAdd(&sg[(row + 8) * 33 + col + 1], acc[mt][nt][3]);
        }
}

__global__ __launch_bounds__(256, 1)
void rec_persist(const float* __restrict__ Whh, const float* __restrict__ xw,
                 const float* __restrict__ c0, float* __restrict__ cOut,
                 const __half* __restrict__ h0p,
                 __half* __restrict__ ysAh,
                 float* __restrict__ hT, int H, int Kpad, int NJ)
{
    extern __shared__ char sraw[];
    const int BSTR = Kpad + 8;
    __half* Bh  = (__half*)sraw;               // [32][BSTR]
    __half* Ah  = Bh + 32 * BSTR;              // [4][AROWS][ASTR]
    float*  sg  = (float*)(Ah + 4 * ABUF);     // [80][33]
    float*  sxw = sg + 80 * 33;                // [80][XWSTR]

    const int tid  = threadIdx.x;
    const int lane = tid & 31;
    const int warp = tid >> 5;
    const int wq   = warp & 3;
    const int wm   = warp >> 2;
    const int gRowBase = wm * 48;
    const int rowBaseS = wq * 80 + wm * 48;
    const int j0   = blockIdx.x * 8;
    const int N4   = 4 * H;

    auto issue_xw = [&](int t) {
        const float* xw_t = xw + (size_t)t * Bb * N4;
#pragma unroll
        for (int q = 0; q < 5; q++) {
            int u = tid + q * 256;
            int row  = u >> 4;
            int v    = u & 15;
            int gate = v >> 2;
            int pr   = v & 3;
            const float* src = xw_t + (size_t)row * N4 + gate * H + j0 + 2 * pr;
            float* dst = sxw + row * XWSTR + gate * 8 + 2 * pr;
            cp_async8(smem_u32(dst), src);
        }
        cp_commit();
    };

    // prologue: Whh rows -> smem (fp16 hi only)
    {
        int Kh = Kpad >> 1;
        for (int idx = tid; idx < 32 * Kh; idx += 256) {
            int r  = idx / Kh;
            int kp = idx - r * Kh;
            int k  = 2 * kp;
            int gate = r >> 3, jj = r & 7;
            int j = j0 + jj;
            float x = 0.f, y = 0.f;
            if (j < H) {
                const float* wp = Whh + (size_t)(gate * H + j) * H;
                if (k < H)     x = wp[k];
                if (k + 1 < H) y = wp[k + 1];
            }
            *(__half2*)&Bh[r * BSTR + k] =
                __halves2half2(__float2half_rn(x), __float2half_rn(y));
        }
    }

    // c state -> registers
    float creg[3] = {0.f, 0.f, 0.f};
#pragma unroll
    for (int q = 0; q < 3; q++) {
        int e = tid + q * 256;
        if (e < Bb * 8) {
            int row = e >> 3, jj = e & 7;
            int j = j0 + jj;
            if (j < H) creg[q] = c0[(size_t)row * H + j];
        }
    }

    // first step's setup
    for (int i = tid; i < 80 * 33; i += 256) sg[i] = 0.f;
    issue_xw(0);
    __syncthreads();

    for (int t = 0; t < Tt; t++) {
        const __half* hiR = (t == 0) ? h0p : ysAh + (size_t)(t - 1) * Bb * Kpad;

        if (wm == 0)
            rec_step_gemm<3>(hiR, Bh, Ah, sg,
                             BSTR, Kpad, lane, wq, gRowBase, rowBaseS);
        else
            rec_step_gemm<2>(hiR, Bh, Ah, sg,
                             BSTR, Kpad, lane, wq, gRowBase, rowBaseS);
        cp_wait0();
        __syncthreads();

        // LSTM cell
#pragma unroll
        for (int q = 0; q < 3; q++) {
            int e = tid + q * 256;
            if (e >= Bb * 8) break;
            int row = e >> 3, jj = e & 7;
            int j = j0 + jj;
            if (j >= H) continue;
            const float* xr = sxw + row * XWSTR;
            float gi = sg[row * 33 + jj]      + xr[jj];
            float gf = sg[row * 33 + 8 + jj]  + xr[8 + jj];
            float gg = sg[row * 33 + 16 + jj] + xr[16 + jj];
            float go = sg[row * 33 + 24 + jj] + xr[24 + jj];
            float cn = sigf(gf) * creg[q] + sigf(gi) * tanhf(gg);
            float hn = sigf(go) * tanhf(cn);
            creg[q] = cn;
            ysAh[((size_t)t * Bb + row) * Kpad + j] = __float2half_rn(hn);
            if (t == Tt - 1) {
                hT[(size_t)row * H + j]   = hn;
                cOut[(size_t)row * H + j] = cn;
            }
        }
        __syncthreads();

        // split barrier: arrive, overlap next-step setup, then wait
        if (tid == 0) {
            __threadfence();
            atomicAdd(&g_bar, 1u);
        }
        for (int i = tid; i < 80 * 33; i += 256) sg[i] = 0.f;
        if (t + 1 < Tt) issue_xw(t + 1);
        if (tid == 0) {
            unsigned target = (unsigned)NJ * (unsigned)(t + 1);
            while (*(volatile unsigned*)&g_bar < target) { }
            __threadfence();
        }
        __syncthreads();
    }
}

// ---------------- prep: h0 -> hi plane, zero barrier ----
__global__ void prep_h_kernel(const float* __restrict__ h0,
                              __half* __restrict__ h0p, int H, int Kpad)
{
    int idx = blockIdx.x * blockDim.x + threadIdx.x;
    if (idx == 0) g_bar = 0;
    if (idx >= Bb * Kpad) return;
    int row = idx / Kpad, j = idx - row * Kpad;
    h0p[idx] = (j < H) ? __float2half_rn(h0[(size_t)row * H + j]) : __ushort_as_half(0);
}

__global__ void copy_f32(float* __restrict__ dst, const float* __restrict__ src, int n) {
    int i = blockIdx.x * blockDim.x + threadIdx.x;
    if (i < n) dst[i] = src[i];
}

// ---------------- host orchestration ----------------
static inline int ceil_div(int a, int b) { return (a + b - 1) / b; }

extern "C" void kernel_launch(void* const* d_in, const int* in_sizes, int n_in,
                              void* d_out, int out_size)
{
    const int*   tokens = (const int*)d_in[0];
    const float* emb_W  = (const float*)d_in[1];
    const float* dec_W  = (const float*)d_in[2];
    const float* dec_b  = (const float*)d_in[3];

    const float *Wih[3], *Whh[3], *bih[3], *bhh[3], *h0[3], *c0[3];
    for (int l = 0; l < 3; l++) {
        int base = 4 + l * 6;
        Wih[l] = (const float*)d_in[base + 0];
        Whh[l] = (const float*)d_in[base + 1];
        bih[l] = (const float*)d_in[base + 2];
        bhh[l] = (const float*)d_in[base + 3];
        h0[l]  = (const float*)d_in[base + 4];
        c0[l]  = (const float*)d_in[base + 5];
    }

    float *pXW, *pc, *phT;
    __half *pH0p, *pAh0, *pAh1, *pWh;
    cudaGetSymbolAddress((void**)&pXW, g_XW);
    cudaGetSymbolAddress((void**)&pc,  g_c);
    cudaGetSymbolAddress((void**)&phT, g_hT);
    cudaGetSymbolAddress((void**)&pH0p, g_h0p);
    cudaGetSymbolAddress((void**)&pAh0, g_Ahi);
    cudaGetSymbolAddress((void**)&pWh,  g_Whi);
    pAh1 = pAh0 + (size_t)TB * KPAD_MAX;

    float* out = (float*)d_out;

    // opt-in smem
    {
        int recBytes = 32 * (KPAD_MAX + 8) * 2 + 4 * ABUF * 2
                     + 80 * 33 * 4 + 80 * XWSTR * 4;
        cudaFuncSetAttribute(rec_persist,
                             cudaFuncAttributeMaxDynamicSharedMemorySize, recBytes);
        cudaFuncSetAttribute(hgemm_f16,
                             cudaFuncAttributeMaxDynamicSharedMemorySize, 4 * 2 * 4096);
    }

    // 1) embedding -> hi plane (ping), stride Ee=400
    {
        int n = TB * Ee;
        embed_hi<<<ceil_div(n, 256), 256>>>(tokens, emb_W, pAh0, n);
    }

    const int Hd[3]  = {Hh, Hh, Ee};
    const int KpI[3] = {400, 1152, 1152};
    const int KpR[3] = {1152, 1152, 448};
    const int Wk[3]  = {Ee, Hh, Hh};
    __half *aHin = pAh0, *aHout = pAh1;
    size_t out_off = (size_t)TB * Vv;

    for (int l = 0; l < 3; l++) {
        int H = Hd[l], N4 = 4 * H;
        int KI = KpI[l];

        splitW_kernel<<<ceil_div(N4 * KI, 256), 256>>>(Wih[l], pWh, N4, Wk[l], KI);

        // xW = Ah @ Wh^T + bih + bhh
        {
            dim3 grid(ceil_div(N4, 128), ceil_div(TB, 128));
            hgemm_f16<<<grid, 256, 4 * 2 * 4096>>>(
                aHin, pWh, bih[l], bhh[l], pXW, TB, N4, KI, KI, KI);
        }

        // init h0 plane + barrier
        {
            int n = Bb * KpR[l];
            prep_h_kernel<<<ceil_div(n, 256), 256>>>(h0[l], pH0p, H, KpR[l]);
        }

        // persistent recurrent kernel
        {
            int NJ = ceil_div(H, 8);
            int smemBytes = 32 * (KpR[l] + 8) * 2 + 4 * ABUF * 2
                          + 80 * 33 * 4 + 80 * XWSTR * 4;
            rec_persist<<<NJ, 256, smemBytes>>>(
                Whh[l], pXW, c0[l], pc, pH0p, aHout, phT, H, KpR[l], NJ);
        }

        copy_f32<<<ceil_div(Bb * H, 256), 256>>>(out + out_off, phT, Bb * H);
        out_off += (size_t)Bb * H;
        copy_f32<<<ceil_div(Bb * H, 256), 256>>>(out + out_off, pc, Bb * H);
        out_off += (size_t)Bb * H;

        __half* th = aHin; aHin = aHout; aHout = th;
    }

    // 2) decoder: decoded = ysHi @ dec_Wh^T + dec_b
    {
        splitW_kernel<<<ceil_div(Vv * Ee, 256), 256>>>(dec_W, pWh, Vv, Ee, Ee);
        dim3 grid(ceil_div(Vv, 128), ceil_div(TB, 128));
        hgemm_f16<<<grid, 256, 4 * 2 * 4096>>>(
            aHin, pWh, dec_b, nullptr, out, TB, Vv, Ee, 448, Ee);
    }
}

// round 12
// speedup vs baseline: 5.5841x; 1.0459x over previous
#include <cuda_runtime.h>
#include <cuda_fp16.h>
#include <math.h>
#include <stdint.h>

// Problem constants
#define Tt 70
#define Bb 80
#define Vv 33278
#define Ee 400
#define Hh 1150
#define TB (Tt*Bb)          // 5600
#define KPAD_MAX 1152

// ---------------- scratch (device globals; no allocation) ----------------
__device__ float  g_XW[(size_t)TB * 4 * Hh + 32];
__device__ __half g_h0p[Bb * KPAD_MAX];
__device__ unsigned g_bar;
__device__ __align__(128) __half g_Ahi[2][(size_t)TB * KPAD_MAX];
__device__ __align__(128) __half g_Whi[(size_t)13600000];

// ---------------- ptx helpers ----------------
__device__ __forceinline__ void mma_f16(float* c, const uint32_t* a, const uint32_t* b) {
    asm volatile(
        "mma.sync.aligned.m16n8k16.row.col.f32.f16.f16.f32 "
        "{%0,%1,%2,%3}, {%4,%5,%6,%7}, {%8,%9}, {%0,%1,%2,%3};"
        : "+f"(c[0]), "+f"(c[1]), "+f"(c[2]), "+f"(c[3])
        : "r"(a[0]), "r"(a[1]), "r"(a[2]), "r"(a[3]), "r"(b[0]), "r"(b[1]));
}
__device__ __forceinline__ uint32_t smem_u32(const void* p) {
    return (uint32_t)__cvta_generic_to_shared(p);
}
__device__ __forceinline__ void ldsm4(uint32_t* r, uint32_t addr) {
    asm volatile("ldmatrix.sync.aligned.m8n8.x4.shared.b16 {%0,%1,%2,%3}, [%4];"
                 : "=r"(r[0]), "=r"(r[1]), "=r"(r[2]), "=r"(r[3]) : "r"(addr));
}
__device__ __forceinline__ void cp_async16(uint32_t dst, const void* src) {
    asm volatile("cp.async.cg.shared.global [%0], [%1], 16;" :: "r"(dst), "l"(src));
}
__device__ __forceinline__ void cp_async8(uint32_t dst, const void* src) {
    asm volatile("cp.async.ca.shared.global [%0], [%1], 8;" :: "r"(dst), "l"(src));
}
__device__ __forceinline__ void cp_commit() {
    asm volatile("cp.async.commit_group;" ::: "memory");
}
__device__ __forceinline__ void cp_wait2() {
    asm volatile("cp.async.wait_group 2;" ::: "memory");
}
__device__ __forceinline__ void cp_wait0() {
    asm volatile("cp.async.wait_group 0;" ::: "memory");
}

// ---------------- embedding gather -> fp16 hi plane ----------------
__global__ void embed_hi(const int* __restrict__ tokens,
                         const float* __restrict__ emb,
                         __half* __restrict__ Ah, int n) {
    int idx = blockIdx.x * blockDim.x + threadIdx.x;
    if (idx >= n) return;
    int tb = idx / Ee;
    int e  = idx - tb * Ee;
    Ah[idx] = __float2half_rn(emb[(size_t)tokens[tb] * Ee + e]);
}

// ---------------- weight split ----------------
__global__ void splitW_kernel(const float* __restrict__ W, __half* __restrict__ Wh,
                              int rows, int K, int Kpad) {
    int idx = blockIdx.x * blockDim.x + threadIdx.x;
    if (idx >= rows * Kpad) return;
    int r = idx / Kpad, k = idx - r * Kpad;
    Wh[idx] = (k < K) ? __float2half_rn(W[(size_t)r * K + k]) : __ushort_as_half(0);
}

// ============================================================================
// 1-pass fp16-plane GEMM: C = Ah * Wh^T + bias
// CTA 128x128, 8 warps 2(m)x4(n), BK=16, 4-stage cp.async.
// R12: 24-half (48B) smem row stride — conflict-free STS + ldmatrix loads;
//      fragments via 6 ldsm4/chunk (was 24 scalar LDS with 2-way conflicts).
// ============================================================================
#define GSTR 24
#define GTPS (128 * GSTR * 2)    // halves per stage (A tile + B tile)

__global__ __launch_bounds__(256)
void hgemm_f16(const __half* __restrict__ Ah, const __half* __restrict__ Wh,
               const float* __restrict__ bias0, const float* __restrict__ bias1,
               float* __restrict__ C, int M, int N, int K, int lda, int ldw)
{
    extern __shared__ __half smem[];

    const int tid  = threadIdx.x;
    const int lane = tid & 31;
    const int warp = tid >> 5;
    const int wm   = warp >> 2;
    const int wn   = warp & 3;
    const int g    = lane >> 2;
    const int t4   = lane & 3;
    const int bm   = blockIdx.y * 128;
    const int bn   = blockIdx.x * 128;

    float acc[4][4][4];
#pragma unroll
    for (int i = 0; i < 4; i++)
#pragma unroll
        for (int j = 0; j < 4; j++)
#pragma unroll
            for (int q = 0; q < 4; q++) acc[i][j][q] = 0.f;

    const int row = tid >> 1;
    const int seg = tid & 1;

    auto issue = [&](int c, int s) {
        __half* st = smem + s * GTPS;
        const int koff = c * 16 + seg * 8;
        {
            uint32_t dst = smem_u32(st + row * GSTR + seg * 8);
            int gm = bm + row;
            if (gm < M) cp_async16(dst, Ah + (size_t)gm * lda + koff);
            else        *(float4*)(st + row * GSTR + seg * 8) = make_float4(0.f,0.f,0.f,0.f);
        }
        {
            __half* bt = st + 128 * GSTR;
            uint32_t dst = smem_u32(bt + row * GSTR + seg * 8);
            int gn = bn + row;
            if (gn < N) cp_async16(dst, Wh + (size_t)gn * ldw + koff);
            else        *(float4*)(bt + row * GSTR + seg * 8) = make_float4(0.f,0.f,0.f,0.f);
        }
    };

    // ldmatrix lane addressing (constant across chunks)
    const int rA   = wm * 64 + (lane & 7) + ((lane >> 3) & 1) * 8;  // A row within tile
    const int ksA  = (lane >> 4) * 8;                               // A k-segment
    const int matB = lane >> 3;                                     // B: 4 lane-groups
    const int rB   = lane & 7;
    const int ntqB = matB >> 1;
    const int ksB  = (matB & 1) * 8;
    const int bRow = wn * 32 + ntqB * 8 + rB;                       // B row within tile

    const int NCH = K >> 4;
    issue(0, 0); cp_commit();
    issue(1, 1); cp_commit();
    issue(2, 2); cp_commit();

    for (int c = 0; c < NCH; c++) {
        cp_wait2();
        __syncthreads();
        __half* st  = smem + (c & 3) * GTPS;
        __half* AsH = st;
        __half* BsH = st + 128 * GSTR;

        uint32_t ah[4][4], bf[8];
#pragma unroll
        for (int mt = 0; mt < 4; mt++)
            ldsm4(ah[mt], smem_u32(AsH + (rA + mt * 16) * GSTR + ksA));
        {
            uint32_t b0 = smem_u32(BsH + bRow * GSTR + ksB);
            ldsm4(bf,     b0);
            ldsm4(bf + 4, b0 + 16 * GSTR * 2);   // +16 rows (nt 2,3)
        }

        if (c + 3 < NCH) issue(c + 3, (c + 3) & 3);
        cp_commit();

#pragma unroll
        for (int mt = 0; mt < 4; mt++)
#pragma unroll
            for (int nt = 0; nt < 4; nt++)
                mma_f16(acc[mt][nt], ah[mt], &bf[nt * 2]);
    }

#pragma unroll
    for (int mt = 0; mt < 4; mt++) {
#pragma unroll
        for (int nt = 0; nt < 4; nt++) {
            int r0 = bm + wm * 64 + mt * 16 + g;
            int cc = bn + wn * 32 + nt * 8 + 2 * t4;
            if (cc >= N) continue;
            float bv0 = 0.f, bv1 = 0.f;
            if (bias0) { bv0 += bias0[cc]; bv1 += bias0[cc + 1]; }
            if (bias1) { bv0 += bias1[cc]; bv1 += bias1[cc + 1]; }
            if (r0 < M)
                *(float2*)(C + (size_t)r0 * N + cc) =
                    make_float2(acc[mt][nt][0] + bv0, acc[mt][nt][1] + bv1);
            if (r0 + 8 < M)
                *(float2*)(C + (size_t)(r0 + 8) * N + cc) =
                    make_float2(acc[mt][nt][2] + bv0, acc[mt][nt][3] + bv1);
        }
    }
}

// ============================================================================
// Persistent recurrent kernel (R11 proven): 1-pass fp16, 4-stage A pipeline,
// split device barrier, c in registers; hT/cT written directly to d_out.
// ============================================================================
__device__ __forceinline__ float sigf(float x) { return 1.f / (1.f + expf(-x)); }

#define ASTR 24
#define AROWS 320
#define ABUF (AROWS*ASTR)
#define XWSTR 36

template<int MTW>
__device__ __forceinline__ void rec_step_gemm(
    const __half* __restrict__ hiR,
    const __half* Bh, __half* Ah, float* sg,
    int BSTR, int Kpad, int lane, int wq, int gRowBase, int rowBaseS)
{
    const int NC   = Kpad >> 4;
    const int ncq  = NC >> 2;
    const int cbeg = wq * ncq;

    float acc[MTW][4][4];
#pragma unroll
    for (int mt = 0; mt < MTW; mt++)
#pragma unroll
        for (int nt = 0; nt < 4; nt++)
#pragma unroll
            for (int q = 0; q < 4; q++) acc[mt][nt][q] = 0.f;

    auto issue = [&](int c, int buf) {
#pragma unroll
        for (int r = 0; r < MTW; r++) {
            int e   = lane + 32 * r;
            int row = e >> 1;
            int seg = e & 1;
            const __half* src = hiR + (size_t)(gRowBase + row) * Kpad + c * 16 + seg * 8;
            __half* dstp = Ah + buf * ABUF + (rowBaseS + row) * ASTR + seg * 8;
            cp_async16(smem_u32(dstp), src);
        }
    };

    issue(cbeg, 0);     cp_commit();
    issue(cbeg + 1, 1); cp_commit();
    issue(cbeg + 2, 2); cp_commit();

    for (int i = 0; i < ncq; i++) {
        const int c   = cbeg + i;
        const int buf = i & 3;
        cp_wait2();
        __syncwarp();

        uint32_t bh0[4], bh1[4];
        {
            int k0 = c * 16;
            ldsm4(bh0, smem_u32(Bh + (size_t)lane * BSTR + k0));
            ldsm4(bh1, smem_u32(Bh + (size_t)lane * BSTR + k0 + 8));
        }
        uint32_t ah[MTW][4];
        {
            int rAr  = rowBaseS + (lane & 7) + ((lane >> 3) & 1) * 8;
            int kseg = (lane >> 4) * 8;
#pragma unroll
            for (int mt = 0; mt < MTW; mt++)
                ldsm4(ah[mt], smem_u32(Ah + buf * ABUF + (rAr + mt * 16) * ASTR + kseg));
        }
        if (i + 3 < ncq) issue(c + 3, (i + 3) & 3);
        cp_commit();

#pragma unroll
        for (int mt = 0; mt < MTW; mt++)
#pragma unroll
            for (int nt = 0; nt < 4; nt++) {
                uint32_t bb[2] = { bh0[nt], bh1[nt] };
                mma_f16(acc[mt][nt], ah[mt], bb);
            }
    }

    const int gq = lane >> 2;
    const int t4 = lane & 3;
#pragma unroll
    for (int mt = 0; mt < MTW; mt++)
#pragma unroll
        for (int nt = 0; nt < 4; nt++) {
            int row = gRowBase + mt * 16 + gq;
            int col = nt * 8 + 2 * t4;
            atomicAdd(&sg[row * 33 + col],           acc[mt][nt][0]);
            atomicAdd(&sg[row * 33 + col + 1],       acc[mt][nt][1]);
            atomicAdd(&sg[(row + 8) * 33 + col],     acc[mt][nt][2]);
            atomicAdd(&sg[(row + 8) * 33 + col + 1], acc[mt][nt][3]);
        }
}

__global__ __launch_bounds__(256, 1)
void rec_persist(const float* __restrict__ Whh, const float* __restrict__ xw,
                 const float* __restrict__ c0, float* __restrict__ cOut,
                 const __half* __restrict__ h0p,
                 __half* __restrict__ ysAh,
                 float* __restrict__ hT, int H, int Kpad, int NJ)
{
    extern __shared__ char sraw[];
    const int BSTR = Kpad + 8;
    __half* Bh  = (__half*)sraw;
    __half* Ah  = Bh + 32 * BSTR;
    float*  sg  = (float*)(Ah + 4 * ABUF);
    float*  sxw = sg + 80 * 33;

    const int tid  = threadIdx.x;
    const int lane = tid & 31;
    const int warp = tid >> 5;
    const int wq   = warp & 3;
    const int wm   = warp >> 2;
    const int gRowBase = wm * 48;
    const int rowBaseS = wq * 80 + wm * 48;
    const int j0   = blockIdx.x * 8;
    const int N4   = 4 * H;

    auto issue_xw = [&](int t) {
        const float* xw_t = xw + (size_t)t * Bb * N4;
#pragma unroll
        for (int q = 0; q < 5; q++) {
            int u = tid + q * 256;
            int r2  = u >> 4;
            int v    = u & 15;
            int gate = v >> 2;
            int pr   = v & 3;
            const float* src = xw_t + (size_t)r2 * N4 + gate * H + j0 + 2 * pr;
            float* dst = sxw + r2 * XWSTR + gate * 8 + 2 * pr;
            cp_async8(smem_u32(dst), src);
        }
        cp_commit();
    };

    // prologue: Whh rows -> smem (fp16 hi)
    {
        int Kh = Kpad >> 1;
        for (int idx = tid; idx < 32 * Kh; idx += 256) {
            int r  = idx / Kh;
            int kp = idx - r * Kh;
            int k  = 2 * kp;
            int gate = r >> 3, jj = r & 7;
            int j = j0 + jj;
            float x = 0.f, y = 0.f;
            if (j < H) {
                const float* wp = Whh + (size_t)(gate * H + j) * H;
                if (k < H)     x = wp[k];
                if (k + 1 < H) y = wp[k + 1];
            }
            *(__half2*)&Bh[r * BSTR + k] =
                __halves2half2(__float2half_rn(x), __float2half_rn(y));
        }
    }

    float creg[3] = {0.f, 0.f, 0.f};
#pragma unroll
    for (int q = 0; q < 3; q++) {
        int e = tid + q * 256;
        if (e < Bb * 8) {
            int r2 = e >> 3, jj = e & 7;
            int j = j0 + jj;
            if (j < H) creg[q] = c0[(size_t)r2 * H + j];
        }
    }

    for (int i = tid; i < 80 * 33; i += 256) sg[i] = 0.f;
    issue_xw(0);
    __syncthreads();

    for (int t = 0; t < Tt; t++) {
        const __half* hiR = (t == 0) ? h0p : ysAh + (size_t)(t - 1) * Bb * Kpad;

        if (wm == 0)
            rec_step_gemm<3>(hiR, Bh, Ah, sg,
                             BSTR, Kpad, lane, wq, gRowBase, rowBaseS);
        else
            rec_step_gemm<2>(hiR, Bh, Ah, sg,
                             BSTR, Kpad, lane, wq, gRowBase, rowBaseS);
        cp_wait0();
        __syncthreads();

#pragma unroll
        for (int q = 0; q < 3; q++) {
            int e = tid + q * 256;
            if (e >= Bb * 8) break;
            int r2 = e >> 3, jj = e & 7;
            int j = j0 + jj;
            if (j >= H) continue;
            const float* xr = sxw + r2 * XWSTR;
            float gi = sg[r2 * 33 + jj]      + xr[jj];
            float gf = sg[r2 * 33 + 8 + jj]  + xr[8 + jj];
            float gg = sg[r2 * 33 + 16 + jj] + xr[16 + jj];
            float go = sg[r2 * 33 + 24 + jj] + xr[24 + jj];
            float cn = sigf(gf) * creg[q] + sigf(gi) * tanhf(gg);
            float hn = sigf(go) * tanhf(cn);
            creg[q] = cn;
            ysAh[((size_t)t * Bb + r2) * Kpad + j] = __float2half_rn(hn);
            if (t == Tt - 1) {
                hT[(size_t)r2 * H + j]   = hn;
                cOut[(size_t)r2 * H + j] = cn;
            }
        }
        __syncthreads();

        if (tid == 0) {
            __threadfence();
            atomicAdd(&g_bar, 1u);
        }
        for (int i = tid; i < 80 * 33; i += 256) sg[i] = 0.f;
        if (t + 1 < Tt) issue_xw(t + 1);
        if (tid == 0) {
            unsigned target = (unsigned)NJ * (unsigned)(t + 1);
            while (*(volatile unsigned*)&g_bar < target) { }
            __threadfence();
        }
        __syncthreads();
    }
}

// ---------------- prep: h0 -> hi plane, zero barrier ----
__global__ void prep_h_kernel(const float* __restrict__ h0,
                              __half* __restrict__ h0p, int H, int Kpad)
{
    int idx = blockIdx.x * blockDim.x + threadIdx.x;
    if (idx == 0) g_bar = 0;
    if (idx >= Bb * Kpad) return;
    int row = idx / Kpad, j = idx - row * Kpad;
    h0p[idx] = (j < H) ? __float2half_rn(h0[(size_t)row * H + j]) : __ushort_as_half(0);
}

// ---------------- host orchestration ----------------
static inline int ceil_div(int a, int b) { return (a + b - 1) / b; }

extern "C" void kernel_launch(void* const* d_in, const int* in_sizes, int n_in,
                              void* d_out, int out_size)
{
    const int*   tokens = (const int*)d_in[0];
    const float* emb_W  = (const float*)d_in[1];
    const float* dec_W  = (const float*)d_in[2];
    const float* dec_b  = (const float*)d_in[3];

    const float *Wih[3], *Whh[3], *bih[3], *bhh[3], *h0[3], *c0[3];
    for (int l = 0; l < 3; l++) {
        int base = 4 + l * 6;
        Wih[l] = (const float*)d_in[base + 0];
        Whh[l] = (const float*)d_in[base + 1];
        bih[l] = (const float*)d_in[base + 2];
        bhh[l] = (const float*)d_in[base + 3];
        h0[l]  = (const float*)d_in[base + 4];
        c0[l]  = (const float*)d_in[base + 5];
    }

    float *pXW;
    __half *pH0p, *pAh0, *pAh1, *pWh;
    cudaGetSymbolAddress((void**)&pXW, g_XW);
    cudaGetSymbolAddress((void**)&pH0p, g_h0p);
    cudaGetSymbolAddress((void**)&pAh0, g_Ahi);
    cudaGetSymbolAddress((void**)&pWh,  g_Whi);
    pAh1 = pAh0 + (size_t)TB * KPAD_MAX;

    float* out = (float*)d_out;

    // opt-in smem
    {
        int recBytes = 32 * (KPAD_MAX + 8) * 2 + 4 * ABUF * 2
                     + 80 * 33 * 4 + 80 * XWSTR * 4;
        cudaFuncSetAttribute(rec_persist,
                             cudaFuncAttributeMaxDynamicSharedMemorySize, recBytes);
        cudaFuncSetAttribute(hgemm_f16,
                             cudaFuncAttributeMaxDynamicSharedMemorySize, 4 * GTPS * 2);
    }

    // 1) embedding -> hi plane (ping), stride Ee=400
    {
        int n = TB * Ee;
        embed_hi<<<ceil_div(n, 256), 256>>>(tokens, emb_W, pAh0, n);
    }

    const int Hd[3]  = {Hh, Hh, Ee};
    const int KpI[3] = {400, 1152, 1152};
    const int KpR[3] = {1152, 1152, 448};
    const int Wk[3]  = {Ee, Hh, Hh};
    __half *aHin = pAh0, *aHout = pAh1;
    size_t out_off = (size_t)TB * Vv;

    for (int l = 0; l < 3; l++) {
        int H = Hd[l], N4 = 4 * H;
        int KI = KpI[l];

        splitW_kernel<<<ceil_div(N4 * KI, 256), 256>>>(Wih[l], pWh, N4, Wk[l], KI);

        // xW = Ah @ Wh^T + bih + bhh
        {
            dim3 grid(ceil_div(N4, 128), ceil_div(TB, 128));
            hgemm_f16<<<grid, 256, 4 * GTPS * 2>>>(
                aHin, pWh, bih[l], bhh[l], pXW, TB, N4, KI, KI, KI);
        }

        // init h0 plane + barrier
        {
            int n = Bb * KpR[l];
            prep_h_kernel<<<ceil_div(n, 256), 256>>>(h0[l], pH0p, H, KpR[l]);
        }

        // persistent recurrent kernel; hT/cT go straight into d_out
        {
            int NJ = ceil_div(H, 8);
            int smemBytes = 32 * (KpR[l] + 8) * 2 + 4 * ABUF * 2
                          + 80 * 33 * 4 + 80 * XWSTR * 4;
            rec_persist<<<NJ, 256, smemBytes>>>(
                Whh[l], pXW, c0[l], out + out_off + (size_t)Bb * H,
                pH0p, aHout, out + out_off, H, KpR[l], NJ);
        }
        out_off += 2 * (size_t)Bb * H;

        __half* th = aHin; aHin = aHout; aHout = th;
    }

    // 2) decoder: decoded = ysHi @ dec_Wh^T + dec_b
    {
        splitW_kernel<<<ceil_div(Vv * Ee, 256), 256>>>(dec_W, pWh, Vv, Ee, Ee);
        dim3 grid(ceil_div(Vv, 128), ceil_div(TB, 128));
        hgemm_f16<<<grid, 256, 4 * GTPS * 2>>>(
            aHin, pWh, dec_b, nullptr, out, TB, Vv, Ee, 448, Ee);
    }
}

// round 13
// speedup vs baseline: 5.7384x; 1.0276x over previous
#include <cuda_runtime.h>
#include <cuda_fp16.h>
#include <math.h>
#include <stdint.h>

// Problem constants
#define Tt 70
#define Bb 80
#define Vv 33278
#define Ee 400
#define Hh 1150
#define TB (Tt*Bb)          // 5600
#define KPAD_MAX 1152

// ---------------- scratch (device globals; no allocation) ----------------
__device__ float  g_XW[(size_t)TB * 4 * Hh + 32];
__device__ __half g_h0p[Bb * KPAD_MAX];
__device__ unsigned g_bar;
__device__ __align__(128) __half g_Ahi[2][(size_t)TB * KPAD_MAX];
__device__ __align__(128) __half g_Whi[(size_t)13600000];

// ---------------- ptx helpers ----------------
__device__ __forceinline__ void mma_f16(float* c, const uint32_t* a, const uint32_t* b) {
    asm volatile(
        "mma.sync.aligned.m16n8k16.row.col.f32.f16.f16.f32 "
        "{%0,%1,%2,%3}, {%4,%5,%6,%7}, {%8,%9}, {%0,%1,%2,%3};"
        : "+f"(c[0]), "+f"(c[1]), "+f"(c[2]), "+f"(c[3])
        : "r"(a[0]), "r"(a[1]), "r"(a[2]), "r"(a[3]), "r"(b[0]), "r"(b[1]));
}
__device__ __forceinline__ uint32_t smem_u32(const void* p) {
    return (uint32_t)__cvta_generic_to_shared(p);
}
__device__ __forceinline__ void ldsm4(uint32_t* r, uint32_t addr) {
    asm volatile("ldmatrix.sync.aligned.m8n8.x4.shared.b16 {%0,%1,%2,%3}, [%4];"
                 : "=r"(r[0]), "=r"(r[1]), "=r"(r[2]), "=r"(r[3]) : "r"(addr));
}
__device__ __forceinline__ void cp_async16(uint32_t dst, const void* src) {
    asm volatile("cp.async.cg.shared.global [%0], [%1], 16;" :: "r"(dst), "l"(src));
}
__device__ __forceinline__ void cp_async8(uint32_t dst, const void* src) {
    asm volatile("cp.async.ca.shared.global [%0], [%1], 8;" :: "r"(dst), "l"(src));
}
__device__ __forceinline__ void cp_commit() {
    asm volatile("cp.async.commit_group;" ::: "memory");
}
__device__ __forceinline__ void cp_wait2() {
    asm volatile("cp.async.wait_group 2;" ::: "memory");
}
__device__ __forceinline__ void cp_wait0() {
    asm volatile("cp.async.wait_group 0;" ::: "memory");
}

// ---------------- fast transcendentals (MUFU-based, ~2 ulp) ----------------
__device__ __forceinline__ float sig_fast(float x) {
    float xc = fminf(fmaxf(x, -30.f), 30.f);
    return __fdividef(1.f, 1.f + __expf(-xc));
}
__device__ __forceinline__ float tanh_fast(float x) {
    float x2 = fminf(fmaxf(2.f * x, -30.f), 30.f);
    float e  = __expf(x2);
    return __fdividef(e - 1.f, e + 1.f);
}

// ---------------- embedding gather -> fp16 hi plane ----------------
__global__ void embed_hi(const int* __restrict__ tokens,
                         const float* __restrict__ emb,
                         __half* __restrict__ Ah, int n) {
    int idx = blockIdx.x * blockDim.x + threadIdx.x;
    if (idx >= n) return;
    int tb = idx / Ee;
    int e  = idx - tb * Ee;
    Ah[idx] = __float2half_rn(emb[(size_t)tokens[tb] * Ee + e]);
}

// ---------------- weight split ----------------
__global__ void splitW_kernel(const float* __restrict__ W, __half* __restrict__ Wh,
                              int rows, int K, int Kpad) {
    int idx = blockIdx.x * blockDim.x + threadIdx.x;
    if (idx >= rows * Kpad) return;
    int r = idx / Kpad, k = idx - r * Kpad;
    Wh[idx] = (k < K) ? __float2half_rn(W[(size_t)r * K + k]) : __ushort_as_half(0);
}

// ============================================================================
// 1-pass fp16-plane GEMM (R12 proven): C = Ah * Wh^T + bias
// CTA 128x128, 8 warps 2(m)x4(n), BK=16, 4-stage cp.async, 48B-stride smem,
// fragments via 6 ldsm4/chunk.
// ============================================================================
#define GSTR 24
#define GTPS (128 * GSTR * 2)

__global__ __launch_bounds__(256)
void hgemm_f16(const __half* __restrict__ Ah, const __half* __restrict__ Wh,
               const float* __restrict__ bias0, const float* __restrict__ bias1,
               float* __restrict__ C, int M, int N, int K, int lda, int ldw)
{
    extern __shared__ __half smem[];

    const int tid  = threadIdx.x;
    const int lane = tid & 31;
    const int warp = tid >> 5;
    const int wm   = warp >> 2;
    const int wn   = warp & 3;
    const int g    = lane >> 2;
    const int t4   = lane & 3;
    const int bm   = blockIdx.y * 128;
    const int bn   = blockIdx.x * 128;

    float acc[4][4][4];
#pragma unroll
    for (int i = 0; i < 4; i++)
#pragma unroll
        for (int j = 0; j < 4; j++)
#pragma unroll
            for (int q = 0; q < 4; q++) acc[i][j][q] = 0.f;

    const int row = tid >> 1;
    const int seg = tid & 1;

    auto issue = [&](int c, int s) {
        __half* st = smem + s * GTPS;
        const int koff = c * 16 + seg * 8;
        {
            uint32_t dst = smem_u32(st + row * GSTR + seg * 8);
            int gm = bm + row;
            if (gm < M) cp_async16(dst, Ah + (size_t)gm * lda + koff);
            else        *(float4*)(st + row * GSTR + seg * 8) = make_float4(0.f,0.f,0.f,0.f);
        }
        {
            __half* bt = st + 128 * GSTR;
            uint32_t dst = smem_u32(bt + row * GSTR + seg * 8);
            int gn = bn + row;
            if (gn < N) cp_async16(dst, Wh + (size_t)gn * ldw + koff);
            else        *(float4*)(bt + row * GSTR + seg * 8) = make_float4(0.f,0.f,0.f,0.f);
        }
    };

    const int rA   = wm * 64 + (lane & 7) + ((lane >> 3) & 1) * 8;
    const int ksA  = (lane >> 4) * 8;
    const int matB = lane >> 3;
    const int rB   = lane & 7;
    const int ntqB = matB >> 1;
    const int ksB  = (matB & 1) * 8;
    const int bRow = wn * 32 + ntqB * 8 + rB;

    const int NCH = K >> 4;
    issue(0, 0); cp_commit();
    issue(1, 1); cp_commit();
    issue(2, 2); cp_commit();

    for (int c = 0; c < NCH; c++) {
        cp_wait2();
        __syncthreads();
        __half* st  = smem + (c & 3) * GTPS;
        __half* AsH = st;
        __half* BsH = st + 128 * GSTR;

        uint32_t ah[4][4], bf[8];
#pragma unroll
        for (int mt = 0; mt < 4; mt++)
            ldsm4(ah[mt], smem_u32(AsH + (rA + mt * 16) * GSTR + ksA));
        {
            uint32_t b0 = smem_u32(BsH + bRow * GSTR + ksB);
            ldsm4(bf,     b0);
            ldsm4(bf + 4, b0 + 16 * GSTR * 2);
        }

        if (c + 3 < NCH) issue(c + 3, (c + 3) & 3);
        cp_commit();

#pragma unroll
        for (int mt = 0; mt < 4; mt++)
#pragma unroll
            for (int nt = 0; nt < 4; nt++)
                mma_f16(acc[mt][nt], ah[mt], &bf[nt * 2]);
    }

#pragma unroll
    for (int mt = 0; mt < 4; mt++) {
#pragma unroll
        for (int nt = 0; nt < 4; nt++) {
            int r0 = bm + wm * 64 + mt * 16 + g;
            int cc = bn + wn * 32 + nt * 8 + 2 * t4;
            if (cc >= N) continue;
            float bv0 = 0.f, bv1 = 0.f;
            if (bias0) { bv0 += bias0[cc]; bv1 += bias0[cc + 1]; }
            if (bias1) { bv0 += bias1[cc]; bv1 += bias1[cc + 1]; }
            if (r0 < M)
                *(float2*)(C + (size_t)r0 * N + cc) =
                    make_float2(acc[mt][nt][0] + bv0, acc[mt][nt][1] + bv1);
            if (r0 + 8 < M)
                *(float2*)(C + (size_t)(r0 + 8) * N + cc) =
                    make_float2(acc[mt][nt][2] + bv0, acc[mt][nt][3] + bv1);
        }
    }
}

// ============================================================================
// Persistent recurrent kernel (R12 proven) — R13: fast-math LSTM cell.
// ============================================================================
#define ASTR 24
#define AROWS 320
#define ABUF (AROWS*ASTR)
#define XWSTR 36

template<int MTW>
__device__ __forceinline__ void rec_step_gemm(
    const __half* __restrict__ hiR,
    const __half* Bh, __half* Ah, float* sg,
    int BSTR, int Kpad, int lane, int wq, int gRowBase, int rowBaseS)
{
    const int NC   = Kpad >> 4;
    const int ncq  = NC >> 2;
    const int cbeg = wq * ncq;

    float acc[MTW][4][4];
#pragma unroll
    for (int mt = 0; mt < MTW; mt++)
#pragma unroll
        for (int nt = 0; nt < 4; nt++)
#pragma unroll
            for (int q = 0; q < 4; q++) acc[mt][nt][q] = 0.f;

    auto issue = [&](int c, int buf) {
#pragma unroll
        for (int r = 0; r < MTW; r++) {
            int e   = lane + 32 * r;
            int row = e >> 1;
            int seg = e & 1;
            const __half* src = hiR + (size_t)(gRowBase + row) * Kpad + c * 16 + seg * 8;
            __half* dstp = Ah + buf * ABUF + (rowBaseS + row) * ASTR + seg * 8;
            cp_async16(smem_u32(dstp), src);
        }
    };

    issue(cbeg, 0);     cp_commit();
    issue(cbeg + 1, 1); cp_commit();
    issue(cbeg + 2, 2); cp_commit();

    for (int i = 0; i < ncq; i++) {
        const int c   = cbeg + i;
        const int buf = i & 3;
        cp_wait2();
        __syncwarp();

        uint32_t bh0[4], bh1[4];
        {
            int k0 = c * 16;
            ldsm4(bh0, smem_u32(Bh + (size_t)lane * BSTR + k0));
            ldsm4(bh1, smem_u32(Bh + (size_t)lane * BSTR + k0 + 8));
        }
        uint32_t ah[MTW][4];
        {
            int rAr  = rowBaseS + (lane & 7) + ((lane >> 3) & 1) * 8;
            int kseg = (lane >> 4) * 8;
#pragma unroll
            for (int mt = 0; mt < MTW; mt++)
                ldsm4(ah[mt], smem_u32(Ah + buf * ABUF + (rAr + mt * 16) * ASTR + kseg));
        }
        if (i + 3 < ncq) issue(c + 3, (i + 3) & 3);
        cp_commit();

#pragma unroll
        for (int mt = 0; mt < MTW; mt++)
#pragma unroll
            for (int nt = 0; nt < 4; nt++) {
                uint32_t bb[2] = { bh0[nt], bh1[nt] };
                mma_f16(acc[mt][nt], ah[mt], bb);
            }
    }

    const int gq = lane >> 2;
    const int t4 = lane & 3;
#pragma unroll
    for (int mt = 0; mt < MTW; mt++)
#pragma unroll
        for (int nt = 0; nt < 4; nt++) {
            int row = gRowBase + mt * 16 + gq;
            int col = nt * 8 + 2 * t4;
            atomicAdd(&sg[row * 33 + col],           acc[mt][nt][0]);
            atomicAdd(&sg[row * 33 + col + 1],       acc[mt][nt][1]);
            atomicAdd(&sg[(row + 8) * 33 + col],     acc[mt][nt][2]);
            atomicAdd(&sg[(row + 8) * 33 + col + 1], acc[mt][nt][3]);
        }
}

__global__ __launch_bounds__(256, 1)
void rec_persist(const float* __restrict__ Whh, const float* __restrict__ xw,
                 const float* __restrict__ c0, float* __restrict__ cOut,
                 const __half* __restrict__ h0p,
                 __half* __restrict__ ysAh,
                 float* __restrict__ hT, int H, int Kpad, int NJ)
{
    extern __shared__ char sraw[];
    const int BSTR = Kpad + 8;
    __half* Bh  = (__half*)sraw;
    __half* Ah  = Bh + 32 * BSTR;
    float*  sg  = (float*)(Ah + 4 * ABUF);
    float*  sxw = sg + 80 * 33;

    const int tid  = threadIdx.x;
    const int lane = tid & 31;
    const int warp = tid >> 5;
    const int wq   = warp & 3;
    const int wm   = warp >> 2;
    const int gRowBase = wm * 48;
    const int rowBaseS = wq * 80 + wm * 48;
    const int j0   = blockIdx.x * 8;
    const int N4   = 4 * H;

    auto issue_xw = [&](int t) {
        const float* xw_t = xw + (size_t)t * Bb * N4;
#pragma unroll
        for (int q = 0; q < 5; q++) {
            int u = tid + q * 256;
            int r2  = u >> 4;
            int v    = u & 15;
            int gate = v >> 2;
            int pr   = v & 3;
            const float* src = xw_t + (size_t)r2 * N4 + gate * H + j0 + 2 * pr;
            float* dst = sxw + r2 * XWSTR + gate * 8 + 2 * pr;
            cp_async8(smem_u32(dst), src);
        }
        cp_commit();
    };

    // prologue: Whh rows -> smem (fp16 hi)
    {
        int Kh = Kpad >> 1;
        for (int idx = tid; idx < 32 * Kh; idx += 256) {
            int r  = idx / Kh;
            int kp = idx - r * Kh;
            int k  = 2 * kp;
            int gate = r >> 3, jj = r & 7;
            int j = j0 + jj;
            float x = 0.f, y = 0.f;
            if (j < H) {
                const float* wp = Whh + (size_t)(gate * H + j) * H;
                if (k < H)     x = wp[k];
                if (k + 1 < H) y = wp[k + 1];
            }
            *(__half2*)&Bh[r * BSTR + k] =
                __halves2half2(__float2half_rn(x), __float2half_rn(y));
        }
    }

    float creg[3] = {0.f, 0.f, 0.f};
#pragma unroll
    for (int q = 0; q < 3; q++) {
        int e = tid + q * 256;
        if (e < Bb * 8) {
            int r2 = e >> 3, jj = e & 7;
            int j = j0 + jj;
            if (j < H) creg[q] = c0[(size_t)r2 * H + j];
        }
    }

    for (int i = tid; i < 80 * 33; i += 256) sg[i] = 0.f;
    issue_xw(0);
    __syncthreads();

    for (int t = 0; t < Tt; t++) {
        const __half* hiR = (t == 0) ? h0p : ysAh + (size_t)(t - 1) * Bb * Kpad;

        if (wm == 0)
            rec_step_gemm<3>(hiR, Bh, Ah, sg,
                             BSTR, Kpad, lane, wq, gRowBase, rowBaseS);
        else
            rec_step_gemm<2>(hiR, Bh, Ah, sg,
                             BSTR, Kpad, lane, wq, gRowBase, rowBaseS);
        cp_wait0();
        __syncthreads();

#pragma unroll
        for (int q = 0; q < 3; q++) {
            int e = tid + q * 256;
            if (e >= Bb * 8) break;
            int r2 = e >> 3, jj = e & 7;
            int j = j0 + jj;
            if (j >= H) continue;
            const float* xr = sxw + r2 * XWSTR;
            float gi = sg[r2 * 33 + jj]      + xr[jj];
            float gf = sg[r2 * 33 + 8 + jj]  + xr[8 + jj];
            float gg = sg[r2 * 33 + 16 + jj] + xr[16 + jj];
            float go = sg[r2 * 33 + 24 + jj] + xr[24 + jj];
            float cn = sig_fast(gf) * creg[q] + sig_fast(gi) * tanh_fast(gg);
            float hn = sig_fast(go) * tanh_fast(cn);
            creg[q] = cn;
            ysAh[((size_t)t * Bb + r2) * Kpad + j] = __float2half_rn(hn);
            if (t == Tt - 1) {
                hT[(size_t)r2 * H + j]   = hn;
                cOut[(size_t)r2 * H + j] = cn;
            }
        }
        __syncthreads();

        if (tid == 0) {
            __threadfence();
            atomicAdd(&g_bar, 1u);
        }
        for (int i = tid; i < 80 * 33; i += 256) sg[i] = 0.f;
        if (t + 1 < Tt) issue_xw(t + 1);
        if (tid == 0) {
            unsigned target = (unsigned)NJ * (unsigned)(t + 1);
            while (*(volatile unsigned*)&g_bar < target) { }
            __threadfence();
        }
        __syncthreads();
    }
}

// ---------------- prep: h0 -> hi plane, zero barrier ----
__global__ void prep_h_kernel(const float* __restrict__ h0,
                              __half* __restrict__ h0p, int H, int Kpad)
{
    int idx = blockIdx.x * blockDim.x + threadIdx.x;
    if (idx == 0) g_bar = 0;
    if (idx >= Bb * Kpad) return;
    int row = idx / Kpad, j = idx - row * Kpad;
    h0p[idx] = (j < H) ? __float2half_rn(h0[(size_t)row * H + j]) : __ushort_as_half(0);
}

// ---------------- host orchestration ----------------
static inline int ceil_div(int a, int b) { return (a + b - 1) / b; }

extern "C" void kernel_launch(void* const* d_in, const int* in_sizes, int n_in,
                              void* d_out, int out_size)
{
    const int*   tokens = (const int*)d_in[0];
    const float* emb_W  = (const float*)d_in[1];
    const float* dec_W  = (const float*)d_in[2];
    const float* dec_b  = (const float*)d_in[3];

    const float *Wih[3], *Whh[3], *bih[3], *bhh[3], *h0[3], *c0[3];
    for (int l = 0; l < 3; l++) {
        int base = 4 + l * 6;
        Wih[l] = (const float*)d_in[base + 0];
        Whh[l] = (const float*)d_in[base + 1];
        bih[l] = (const float*)d_in[base + 2];
        bhh[l] = (const float*)d_in[base + 3];
        h0[l]  = (const float*)d_in[base + 4];
        c0[l]  = (const float*)d_in[base + 5];
    }

    float *pXW;
    __half *pH0p, *pAh0, *pAh1, *pWh;
    cudaGetSymbolAddress((void**)&pXW, g_XW);
    cudaGetSymbolAddress((void**)&pH0p, g_h0p);
    cudaGetSymbolAddress((void**)&pAh0, g_Ahi);
    cudaGetSymbolAddress((void**)&pWh,  g_Whi);
    pAh1 = pAh0 + (size_t)TB * KPAD_MAX;

    float* out = (float*)d_out;

    // opt-in smem
    {
        int recBytes = 32 * (KPAD_MAX + 8) * 2 + 4 * ABUF * 2
                     + 80 * 33 * 4 + 80 * XWSTR * 4;
        cudaFuncSetAttribute(rec_persist,
                             cudaFuncAttributeMaxDynamicSharedMemorySize, recBytes);
        cudaFuncSetAttribute(hgemm_f16,
                             cudaFuncAttributeMaxDynamicSharedMemorySize, 4 * GTPS * 2);
    }

    // 1) embedding -> hi plane (ping), stride Ee=400
    {
        int n = TB * Ee;
        embed_hi<<<ceil_div(n, 256), 256>>>(tokens, emb_W, pAh0, n);
    }

    const int Hd[3]  = {Hh, Hh, Ee};
    const int KpI[3] = {400, 1152, 1152};
    const int KpR[3] = {1152, 1152, 448};
    const int Wk[3]  = {Ee, Hh, Hh};
    __half *aHin = pAh0, *aHout = pAh1;
    size_t out_off = (size_t)TB * Vv;

    for (int l = 0; l < 3; l++) {
        int H = Hd[l], N4 = 4 * H;
        int KI = KpI[l];

        splitW_kernel<<<ceil_div(N4 * KI, 256), 256>>>(Wih[l], pWh, N4, Wk[l], KI);

        // xW = Ah @ Wh^T + bih + bhh
        {
            dim3 grid(ceil_div(N4, 128), ceil_div(TB, 128));
            hgemm_f16<<<grid, 256, 4 * GTPS * 2>>>(
                aHin, pWh, bih[l], bhh[l], pXW, TB, N4, KI, KI, KI);
        }

        // init h0 plane + barrier
        {
            int n = Bb * KpR[l];
            prep_h_kernel<<<ceil_div(n, 256), 256>>>(h0[l], pH0p, H, KpR[l]);
        }

        // persistent recurrent kernel; hT/cT go straight into d_out
        {
            int NJ = ceil_div(H, 8);
            int smemBytes = 32 * (KpR[l] + 8) * 2 + 4 * ABUF * 2
                          + 80 * 33 * 4 + 80 * XWSTR * 4;
            rec_persist<<<NJ, 256, smemBytes>>>(
                Whh[l], pXW, c0[l], out + out_off + (size_t)Bb * H,
                pH0p, aHout, out + out_off, H, KpR[l], NJ);
        }
        out_off += 2 * (size_t)Bb * H;

        __half* th = aHin; aHin = aHout; aHout = th;
    }

    // 2) decoder: decoded = ysHi @ dec_Wh^T + dec_b
    {
        splitW_kernel<<<ceil_div(Vv * Ee, 256), 256>>>(dec_W, pWh, Vv, Ee, Ee);
        dim3 grid(ceil_div(Vv, 128), ceil_div(TB, 128));
        hgemm_f16<<<grid, 256, 4 * GTPS * 2>>>(
            aHin, pWh, dec_b, nullptr, out, TB, Vv, Ee, 448, Ee);
    }
}

// round 15
// speedup vs baseline: 6.0015x; 1.0458x over previous
#include <cuda_runtime.h>
#include <cuda_fp16.h>
#include <math.h>
#include <stdint.h>

// Problem constants
#define Tt 70
#define Bb 80
#define Vv 33278
#define Ee 400
#define Hh 1150
#define TB (Tt*Bb)          // 5600
#define KPAD_MAX 1152

// ---------------- scratch (device globals; no allocation) ----------------
__device__ float  g_XW[(size_t)TB * 4 * Hh + 32];
__device__ __half g_h0p[3][Bb * KPAD_MAX];
__device__ unsigned g_bars[4];
__device__ __align__(128) __half g_Ahi[2][(size_t)TB * KPAD_MAX];
__device__ __align__(128) __half g_Whi[(size_t)22400000];   // all 4 weight planes

// weight plane offsets (halves) — Wih0 is [4*1150, 400]!
#define WOFF0 0                            // Wih0: 4600 x 400
#define WOFF1 (WOFF0 + 4600*400)           // Wih1: 4600 x 1152
#define WOFF2 (WOFF1 + 4600*1152)          // Wih2: 1600 x 1152
#define WOFFD (WOFF2 + 1600*1152)          // dec:  33278 x 400
// total = 1,840,000 + 5,299,200 + 1,843,200 + 13,311,200 = 22,293,600 < 22,400,000

// ---------------- ptx helpers ----------------
__device__ __forceinline__ void mma_f16(float* c, const uint32_t* a, const uint32_t* b) {
    asm volatile(
        "mma.sync.aligned.m16n8k16.row.col.f32.f16.f16.f32 "
        "{%0,%1,%2,%3}, {%4,%5,%6,%7}, {%8,%9}, {%0,%1,%2,%3};"
        : "+f"(c[0]), "+f"(c[1]), "+f"(c[2]), "+f"(c[3])
        : "r"(a[0]), "r"(a[1]), "r"(a[2]), "r"(a[3]), "r"(b[0]), "r"(b[1]));
}
__device__ __forceinline__ uint32_t smem_u32(const void* p) {
    return (uint32_t)__cvta_generic_to_shared(p);
}
__device__ __forceinline__ void ldsm4(uint32_t* r, uint32_t addr) {
    asm volatile("ldmatrix.sync.aligned.m8n8.x4.shared.b16 {%0,%1,%2,%3}, [%4];"
                 : "=r"(r[0]), "=r"(r[1]), "=r"(r[2]), "=r"(r[3]) : "r"(addr));
}
__device__ __forceinline__ void cp_async16(uint32_t dst, const void* src) {
    asm volatile("cp.async.cg.shared.global [%0], [%1], 16;" :: "r"(dst), "l"(src));
}
__device__ __forceinline__ void cp_async8(uint32_t dst, const void* src) {
    asm volatile("cp.async.ca.shared.global [%0], [%1], 8;" :: "r"(dst), "l"(src));
}
__device__ __forceinline__ void cp_commit() {
    asm volatile("cp.async.commit_group;" ::: "memory");
}
__device__ __forceinline__ void cp_wait2() {
    asm volatile("cp.async.wait_group 2;" ::: "memory");
}
__device__ __forceinline__ void cp_wait0() {
    asm volatile("cp.async.wait_group 0;" ::: "memory");
}

// ---------------- fast transcendentals ----------------
__device__ __forceinline__ float sig_fast(float x) {
    float xc = fminf(fmaxf(x, -30.f), 30.f);
    return __fdividef(1.f, 1.f + __expf(-xc));
}
__device__ __forceinline__ float tanh_fast(float x) {
    float x2 = fminf(fmaxf(2.f * x, -30.f), 30.f);
    float e  = __expf(x2);
    return __fdividef(e - 1.f, e + 1.f);
}

// ============================================================================
// prepare_all: embed + 4 weight splits + 3 h0 planes + barrier zero, 1 launch
// ============================================================================
__global__ void prepare_all(const int* __restrict__ tokens,
                            const float* __restrict__ emb_W,
                            const float* __restrict__ Wih0, const float* __restrict__ Wih1,
                            const float* __restrict__ Wih2, const float* __restrict__ dec_W,
                            const float* __restrict__ h0_0, const float* __restrict__ h0_1,
                            const float* __restrict__ h0_2,
                            __half* __restrict__ Ah0, __half* __restrict__ Wh,
                            __half* __restrict__ h0p)
{
    const int stride = gridDim.x * blockDim.x;
    const int tid0 = blockIdx.x * blockDim.x + threadIdx.x;
    if (tid0 < 4) g_bars[tid0] = 0;

    // embedding -> fp16 plane
    for (int i = tid0; i < TB * Ee; i += stride) {
        int tb = i / Ee, e = i - tb * Ee;
        Ah0[i] = __float2half_rn(emb_W[(size_t)tokens[tb] * Ee + e]);
    }
    // Wih0: 4600 x 400 (no pad)
    for (int i = tid0; i < 4600 * 400; i += stride)
        Wh[WOFF0 + i] = __float2half_rn(Wih0[i]);
    // Wih1: 4600 x 1150 -> 1152
    for (int i = tid0; i < 4600 * 1152; i += stride) {
        int r = i / 1152, k = i - r * 1152;
        Wh[WOFF1 + i] = (k < 1150) ? __float2half_rn(Wih1[(size_t)r * 1150 + k])
                                   : __ushort_as_half(0);
    }
    // Wih2: 1600 x 1150 -> 1152
    for (int i = tid0; i < 1600 * 1152; i += stride) {
        int r = i / 1152, k = i - r * 1152;
        Wh[WOFF2 + i] = (k < 1150) ? __float2half_rn(Wih2[(size_t)r * 1150 + k])
                                   : __ushort_as_half(0);
    }
    // dec_W: 33278 x 400 (no pad)
    for (int i = tid0; i < Vv * 400; i += stride)
        Wh[WOFFD + i] = __float2half_rn(dec_W[i]);
    // h0 planes: l0/l1 Kpad=1152, l2 Kpad=448
    for (int i = tid0; i < Bb * 1152; i += stride) {
        int r = i / 1152, j = i - r * 1152;
        h0p[0 * Bb * KPAD_MAX + i] = (j < Hh) ? __float2half_rn(h0_0[(size_t)r * Hh + j]) : __ushort_as_half(0);
        h0p[1 * Bb * KPAD_MAX + i] = (j < Hh) ? __float2half_rn(h0_1[(size_t)r * Hh + j]) : __ushort_as_half(0);
    }
    for (int i = tid0; i < Bb * 448; i += stride) {
        int r = i / 448, j = i - r * 448;
        h0p[2 * Bb * KPAD_MAX + r * 448 + j] =
            (j < Ee) ? __float2half_rn(h0_2[(size_t)r * Ee + j]) : __ushort_as_half(0);
    }
}

// ============================================================================
// 1-pass fp16-plane GEMM (R12/13 proven)
// ============================================================================
#define GSTR 24
#define GTPS (128 * GSTR * 2)

__global__ __launch_bounds__(256)
void hgemm_f16(const __half* __restrict__ Ah, const __half* __restrict__ Wh,
               const float* __restrict__ bias0, const float* __restrict__ bias1,
               float* __restrict__ C, int M, int N, int K, int lda, int ldw)
{
    extern __shared__ __half smem[];

    const int tid  = threadIdx.x;
    const int lane = tid & 31;
    const int warp = tid >> 5;
    const int wm   = warp >> 2;
    const int wn   = warp & 3;
    const int g    = lane >> 2;
    const int t4   = lane & 3;
    const int bm   = blockIdx.y * 128;
    const int bn   = blockIdx.x * 128;

    float acc[4][4][4];
#pragma unroll
    for (int i = 0; i < 4; i++)
#pragma unroll
        for (int j = 0; j < 4; j++)
#pragma unroll
            for (int q = 0; q < 4; q++) acc[i][j][q] = 0.f;

    const int row = tid >> 1;
    const int seg = tid & 1;

    auto issue = [&](int c, int s) {
        __half* st = smem + s * GTPS;
        const int koff = c * 16 + seg * 8;
        {
            uint32_t dst = smem_u32(st + row * GSTR + seg * 8);
            int gm = bm + row;
            if (gm < M) cp_async16(dst, Ah + (size_t)gm * lda + koff);
            else        *(float4*)(st + row * GSTR + seg * 8) = make_float4(0.f,0.f,0.f,0.f);
        }
        {
            __half* bt = st + 128 * GSTR;
            uint32_t dst = smem_u32(bt + row * GSTR + seg * 8);
            int gn = bn + row;
            if (gn < N) cp_async16(dst, Wh + (size_t)gn * ldw + koff);
            else        *(float4*)(bt + row * GSTR + seg * 8) = make_float4(0.f,0.f,0.f,0.f);
        }
    };

    const int rA   = wm * 64 + (lane & 7) + ((lane >> 3) & 1) * 8;
    const int ksA  = (lane >> 4) * 8;
    const int matB = lane >> 3;
    const int rB   = lane & 7;
    const int ntqB = matB >> 1;
    const int ksB  = (matB & 1) * 8;
    const int bRow = wn * 32 + ntqB * 8 + rB;

    const int NCH = K >> 4;
    issue(0, 0); cp_commit();
    issue(1, 1); cp_commit();
    issue(2, 2); cp_commit();

    for (int c = 0; c < NCH; c++) {
        cp_wait2();
        __syncthreads();
        __half* st  = smem + (c & 3) * GTPS;
        __half* AsH = st;
        __half* BsH = st + 128 * GSTR;

        uint32_t ah[4][4], bf[8];
#pragma unroll
        for (int mt = 0; mt < 4; mt++)
            ldsm4(ah[mt], smem_u32(AsH + (rA + mt * 16) * GSTR + ksA));
        {
            uint32_t b0 = smem_u32(BsH + bRow * GSTR + ksB);
            ldsm4(bf,     b0);
            ldsm4(bf + 4, b0 + 16 * GSTR * 2);
        }

        if (c + 3 < NCH) issue(c + 3, (c + 3) & 3);
        cp_commit();

#pragma unroll
        for (int mt = 0; mt < 4; mt++)
#pragma unroll
            for (int nt = 0; nt < 4; nt++)
                mma_f16(acc[mt][nt], ah[mt], &bf[nt * 2]);
    }

#pragma unroll
    for (int mt = 0; mt < 4; mt++) {
#pragma unroll
        for (int nt = 0; nt < 4; nt++) {
            int r0 = bm + wm * 64 + mt * 16 + g;
            int cc = bn + wn * 32 + nt * 8 + 2 * t4;
            if (cc >= N) continue;
            float bv0 = 0.f, bv1 = 0.f;
            if (bias0) { bv0 += bias0[cc]; bv1 += bias0[cc + 1]; }
            if (bias1) { bv0 += bias1[cc]; bv1 += bias1[cc + 1]; }
            if (r0 < M)
                *(float2*)(C + (size_t)r0 * N + cc) =
                    make_float2(acc[mt][nt][0] + bv0, acc[mt][nt][1] + bv1);
            if (r0 + 8 < M)
                *(float2*)(C + (size_t)(r0 + 8) * N + cc) =
                    make_float2(acc[mt][nt][2] + bv0, acc[mt][nt][3] + bv1);
        }
    }
}

// ============================================================================
// Persistent recurrent kernel — templated on NT (B n-tiles = N/8).
// NT=4: j-tile 8 (L0/L1).  NT=2: j-tile 4 (L2, 100 CTAs).
// ============================================================================
#define ASTR 24
#define AROWS 320
#define ABUF (AROWS*ASTR)

template<int MTW, int NT>
__device__ __forceinline__ void rec_step_gemm(
    const __half* __restrict__ hiR,
    const __half* Bh, __half* Ah, float* sg,
    int BSTR, int Kpad, int lane, int wq, int gRowBase, int rowBaseS)
{
    const int SGS = NT * 8 + 1;
    const int NC   = Kpad >> 4;
    const int ncq  = NC >> 2;
    const int cbeg = wq * ncq;

    float acc[MTW][NT][4];
#pragma unroll
    for (int mt = 0; mt < MTW; mt++)
#pragma unroll
        for (int nt = 0; nt < NT; nt++)
#pragma unroll
            for (int q = 0; q < 4; q++) acc[mt][nt][q] = 0.f;

    auto issue = [&](int c, int buf) {
#pragma unroll
        for (int r = 0; r < MTW; r++) {
            int e   = lane + 32 * r;
            int row = e >> 1;
            int seg = e & 1;
            const __half* src = hiR + (size_t)(gRowBase + row) * Kpad + c * 16 + seg * 8;
            __half* dstp = Ah + buf * ABUF + (rowBaseS + row) * ASTR + seg * 8;
            cp_async16(smem_u32(dstp), src);
        }
    };

    issue(cbeg, 0);     cp_commit();
    issue(cbeg + 1, 1); cp_commit();
    issue(cbeg + 2, 2); cp_commit();

    for (int i = 0; i < ncq; i++) {
        const int c   = cbeg + i;
        const int buf = i & 3;
        cp_wait2();
        __syncwarp();

        uint32_t bfr[2 * NT];
        {
            int k0 = c * 16;
            if (NT == 4) {
                uint32_t bh0[4], bh1[4];
                ldsm4(bh0, smem_u32(Bh + (size_t)lane * BSTR + k0));
                ldsm4(bh1, smem_u32(Bh + (size_t)lane * BSTR + k0 + 8));
#pragma unroll
                for (int nt = 0; nt < 4; nt++) { bfr[2*nt] = bh0[nt]; bfr[2*nt+1] = bh1[nt]; }
            } else {
                uint32_t bx[4];
                uint32_t addr = smem_u32(Bh + (size_t)(lane & 15) * BSTR + k0 + ((lane >> 4) * 8));
                ldsm4(bx, addr);
                bfr[0] = bx[0]; bfr[1] = bx[2];
                bfr[2] = bx[1]; bfr[3] = bx[3];
            }
        }
        uint32_t ah[MTW][4];
        {
            int rAr  = rowBaseS + (lane & 7) + ((lane >> 3) & 1) * 8;
            int kseg = (lane >> 4) * 8;
#pragma unroll
            for (int mt = 0; mt < MTW; mt++)
                ldsm4(ah[mt], smem_u32(Ah + buf * ABUF + (rAr + mt * 16) * ASTR + kseg));
        }
        if (i + 3 < ncq) issue(c + 3, (i + 3) & 3);
        cp_commit();

#pragma unroll
        for (int mt = 0; mt < MTW; mt++)
#pragma unroll
            for (int nt = 0; nt < NT; nt++)
                mma_f16(acc[mt][nt], ah[mt], &bfr[2 * nt]);
    }

    const int gq = lane >> 2;
    const int t4 = lane & 3;
#pragma unroll
    for (int mt = 0; mt < MTW; mt++)
#pragma unroll
        for (int nt = 0; nt < NT; nt++) {
            int row = gRowBase + mt * 16 + gq;
            int col = nt * 8 + 2 * t4;
            atomicAdd(&sg[row * SGS + col],           acc[mt][nt][0]);
            atomicAdd(&sg[row * SGS + col + 1],       acc[mt][nt][1]);
            atomicAdd(&sg[(row + 8) * SGS + col],     acc[mt][nt][2]);
            atomicAdd(&sg[(row + 8) * SGS + col + 1], acc[mt][nt][3]);
        }
}

template<int NT>
__global__ __launch_bounds__(256, 1)
void rec_persist(const float* __restrict__ Whh, const float* __restrict__ xw,
                 const float* __restrict__ c0, float* __restrict__ cOut,
                 const __half* __restrict__ h0p,
                 __half* __restrict__ ysAh,
                 float* __restrict__ hT, int H, int Kpad, int NJ,
                 unsigned* __restrict__ barp)
{
    const int JT  = NT * 2;
    const int SGS = NT * 8 + 1;
    const int XWS = NT * 8 + 4;
    const int JSH = (NT == 4) ? 3 : 2;

    extern __shared__ char sraw[];
    const int BSTR = Kpad + 8;
    __half* Bh  = (__half*)sraw;            // [4*JT][BSTR]
    __half* Ah  = Bh + 4 * JT * BSTR;       // [4][AROWS][ASTR]
    float*  sg  = (float*)(Ah + 4 * ABUF);  // [96][SGS]
    float*  sxw = sg + 96 * SGS;            // [80][XWS]

    const int tid  = threadIdx.x;
    const int lane = tid & 31;
    const int warp = tid >> 5;
    const int wq   = warp & 3;
    const int wm   = warp >> 2;
    const int gRowBase = wm * 48;
    const int rowBaseS = wq * 80 + wm * 48;
    const int j0   = blockIdx.x * JT;
    const int N4   = 4 * H;

    auto issue_xw = [&](int t) {
        const float* xw_t = xw + (size_t)t * Bb * N4;
        const int upr = JT >> 1;
        const int total = 80 * 4 * upr;
        for (int u = tid; u < total; u += 256) {
            int r2   = u / (4 * upr);
            int v    = u - r2 * 4 * upr;
            int gate = v / upr;
            int pr   = v - gate * upr;
            const float* src = xw_t + (size_t)r2 * N4 + gate * H + j0 + 2 * pr;
            float* dst = sxw + r2 * XWS + gate * JT + 2 * pr;
            cp_async8(smem_u32(dst), src);
        }
        cp_commit();
    };

    // prologue: Whh rows -> smem (fp16)
    {
        int Kh = Kpad >> 1;
        for (int idx = tid; idx < 4 * JT * Kh; idx += 256) {
            int r  = idx / Kh;
            int kp = idx - r * Kh;
            int k  = 2 * kp;
            int gate = r / JT, jj = r - gate * JT;
            int j = j0 + jj;
            float x = 0.f, y = 0.f;
            if (j < H) {
                const float* wp = Whh + (size_t)(gate * H + j) * H;
                if (k < H)     x = wp[k];
                if (k + 1 < H) y = wp[k + 1];
            }
            *(__half2*)&Bh[r * BSTR + k] =
                __halves2half2(__float2half_rn(x), __float2half_rn(y));
        }
    }

    float creg[3] = {0.f, 0.f, 0.f};
#pragma unroll
    for (int q = 0; q < 3; q++) {
        int e = tid + q * 256;
        if (e < Bb * JT) {
            int r2 = e >> JSH, jj = e & (JT - 1);
            int j = j0 + jj;
            if (j < H) creg[q] = c0[(size_t)r2 * H + j];
        }
    }

    for (int i = tid; i < 96 * SGS; i += 256) sg[i] = 0.f;
    issue_xw(0);
    __syncthreads();

    for (int t = 0; t < Tt; t++) {
        const __half* hiR = (t == 0) ? h0p : ysAh + (size_t)(t - 1) * Bb * Kpad;

        if (wm == 0)
            rec_step_gemm<3, NT>(hiR, Bh, Ah, sg,
                                 BSTR, Kpad, lane, wq, gRowBase, rowBaseS);
        else
            rec_step_gemm<2, NT>(hiR, Bh, Ah, sg,
                                 BSTR, Kpad, lane, wq, gRowBase, rowBaseS);
        cp_wait0();
        __syncthreads();

#pragma unroll
        for (int q = 0; q < 3; q++) {
            int e = tid + q * 256;
            if (e >= Bb * JT) break;
            int r2 = e >> JSH, jj = e & (JT - 1);
            int j = j0 + jj;
            if (j >= H) continue;
            const float* xr = sxw + r2 * XWS;
            float gi = sg[r2 * SGS + jj]          + xr[jj];
            float gf = sg[r2 * SGS + JT + jj]     + xr[JT + jj];
            float gg = sg[r2 * SGS + 2 * JT + jj] + xr[2 * JT + jj];
            float go = sg[r2 * SGS + 3 * JT + jj] + xr[3 * JT + jj];
            float cn = sig_fast(gf) * creg[q] + sig_fast(gi) * tanh_fast(gg);
            float hn = sig_fast(go) * tanh_fast(cn);
            creg[q] = cn;
            ysAh[((size_t)t * Bb + r2) * Kpad + j] = __float2half_rn(hn);
            if (t == Tt - 1) {
                hT[(size_t)r2 * H + j]   = hn;
                cOut[(size_t)r2 * H + j] = cn;
            }
        }
        __syncthreads();

        if (tid == 0) {
            __threadfence();
            atomicAdd(barp, 1u);
        }
        for (int i = tid; i < 96 * SGS; i += 256) sg[i] = 0.f;
        if (t + 1 < Tt) issue_xw(t + 1);
        if (tid == 0) {
            unsigned target = (unsigned)NJ * (unsigned)(t + 1);
            while (*(volatile unsigned*)barp < target) { }
            __threadfence();
        }
        __syncthreads();
    }
}

// ---------------- host orchestration ----------------
static inline int ceil_div(int a, int b) { return (a + b - 1) / b; }

extern "C" void kernel_launch(void* const* d_in, const int* in_sizes, int n_in,
                              void* d_out, int out_size)
{
    const int*   tokens = (const int*)d_in[0];
    const float* emb_W  = (const float*)d_in[1];
    const float* dec_W  = (const float*)d_in[2];
    const float* dec_b  = (const float*)d_in[3];

    const float *Wih[3], *Whh[3], *bih[3], *bhh[3], *h0[3], *c0[3];
    for (int l = 0; l < 3; l++) {
        int base = 4 + l * 6;
        Wih[l] = (const float*)d_in[base + 0];
        Whh[l] = (const float*)d_in[base + 1];
        bih[l] = (const float*)d_in[base + 2];
        bhh[l] = (const float*)d_in[base + 3];
        h0[l]  = (const float*)d_in[base + 4];
        c0[l]  = (const float*)d_in[base + 5];
    }

    float *pXW;
    __half *pH0p, *pAh0, *pAh1, *pWh;
    unsigned* pBars;
    cudaGetSymbolAddress((void**)&pXW, g_XW);
    cudaGetSymbolAddress((void**)&pH0p, g_h0p);
    cudaGetSymbolAddress((void**)&pAh0, g_Ahi);
    cudaGetSymbolAddress((void**)&pWh,  g_Whi);
    cudaGetSymbolAddress((void**)&pBars, g_bars);
    pAh1 = pAh0 + (size_t)TB * KPAD_MAX;

    float* out = (float*)d_out;

    // opt-in smem
    {
        int rec4 = 32 * (KPAD_MAX + 8) * 2 + 4 * ABUF * 2 + 96 * 33 * 4 + 80 * 36 * 4;
        cudaFuncSetAttribute(rec_persist<4>,
                             cudaFuncAttributeMaxDynamicSharedMemorySize, rec4);
        int rec2 = 16 * (448 + 8) * 2 + 4 * ABUF * 2 + 96 * 17 * 4 + 80 * 20 * 4;
        cudaFuncSetAttribute(rec_persist<2>,
                             cudaFuncAttributeMaxDynamicSharedMemorySize, rec2);
        cudaFuncSetAttribute(hgemm_f16,
                             cudaFuncAttributeMaxDynamicSharedMemorySize, 4 * GTPS * 2);
    }

    // 1) all input prep in one launch
    prepare_all<<<2048, 256>>>(tokens, emb_W, Wih[0], Wih[1], Wih[2], dec_W,
                               h0[0], h0[1], h0[2], pAh0, pWh, pH0p);

    const int Hd[3]   = {Hh, Hh, Ee};
    const int KpI[3]  = {400, 1152, 1152};
    const int KpR[3]  = {1152, 1152, 448};
    const size_t WOf[3] = {WOFF0, WOFF1, WOFF2};
    __half *aHin = pAh0, *aHout = pAh1;
    size_t out_off = (size_t)TB * Vv;

    for (int l = 0; l < 3; l++) {
        int H = Hd[l], N4 = 4 * H;
        int KI = KpI[l];

        // xW = Ah @ Wh^T + bih + bhh
        {
            dim3 grid(ceil_div(N4, 128), ceil_div(TB, 128));
            hgemm_f16<<<grid, 256, 4 * GTPS * 2>>>(
                aHin, pWh + WOf[l], bih[l], bhh[l], pXW, TB, N4, KI, KI, KI);
        }

        // persistent recurrent kernel; hT/cT straight into d_out
        if (l < 2) {
            int NJ = ceil_div(H, 8);
            int smemBytes = 32 * (KpR[l] + 8) * 2 + 4 * ABUF * 2
                          + 96 * 33 * 4 + 80 * 36 * 4;
            rec_persist<4><<<NJ, 256, smemBytes>>>(
                Whh[l], pXW, c0[l], out + out_off + (size_t)Bb * H,
                pH0p + (size_t)l * Bb * KPAD_MAX, aHout, out + out_off,
                H, KpR[l], NJ, pBars + l);
        } else {
            int NJ = ceil_div(H, 4);   // 100 CTAs
            int smemBytes = 16 * (KpR[l] + 8) * 2 + 4 * ABUF * 2
                          + 96 * 17 * 4 + 80 * 20 * 4;
            rec_persist<2><<<NJ, 256, smemBytes>>>(
                Whh[l], pXW, c0[l], out + out_off + (size_t)Bb * H,
                pH0p + (size_t)l * Bb * KPAD_MAX, aHout, out + out_off,
                H, KpR[l], NJ, pBars + l);
        }
        out_off += 2 * (size_t)Bb * H;

        __half* th = aHin; aHin = aHout; aHout = th;
    }

    // 2) decoder
    {
        dim3 grid(ceil_div(Vv, 128), ceil_div(TB, 128));
        hgemm_f16<<<grid, 256, 4 * GTPS * 2>>>(
            aHin, pWh + WOFFD, dec_b, nullptr, out, TB, Vv, Ee, 448, Ee);
    }
}

// round 16
// speedup vs baseline: 6.3321x; 1.0551x over previous
#include <cuda_runtime.h>
#include <cuda_fp16.h>
#include <math.h>
#include <stdint.h>

// Problem constants
#define Tt 70
#define Bb 80
#define Vv 33278
#define Ee 400
#define Hh 1150
#define TB (Tt*Bb)          // 5600
#define KPAD_MAX 1152

// ---------------- scratch (device globals; no allocation) ----------------
__device__ float  g_XW[(size_t)TB * 4 * Hh + 32];
__device__ __half g_h0p[3][Bb * KPAD_MAX];
__device__ unsigned g_bars[4];
__device__ __align__(128) __half g_Ahi[2][(size_t)TB * KPAD_MAX];
__device__ __align__(128) __half g_Whi[(size_t)22400000];

// weight plane offsets (halves)
#define WOFF0 0                            // Wih0: 4600 x 400
#define WOFF1 (WOFF0 + 4600*400)           // Wih1: 4600 x 1152
#define WOFF2 (WOFF1 + 4600*1152)          // Wih2: 1600 x 1152
#define WOFFD (WOFF2 + 1600*1152)          // dec:  33278 x 400

// ---------------- ptx helpers ----------------
__device__ __forceinline__ void mma_f16(float* c, const uint32_t* a, const uint32_t* b) {
    asm volatile(
        "mma.sync.aligned.m16n8k16.row.col.f32.f16.f16.f32 "
        "{%0,%1,%2,%3}, {%4,%5,%6,%7}, {%8,%9}, {%0,%1,%2,%3};"
        : "+f"(c[0]), "+f"(c[1]), "+f"(c[2]), "+f"(c[3])
        : "r"(a[0]), "r"(a[1]), "r"(a[2]), "r"(a[3]), "r"(b[0]), "r"(b[1]));
}
__device__ __forceinline__ uint32_t smem_u32(const void* p) {
    return (uint32_t)__cvta_generic_to_shared(p);
}
__device__ __forceinline__ void ldsm4(uint32_t* r, uint32_t addr) {
    asm volatile("ldmatrix.sync.aligned.m8n8.x4.shared.b16 {%0,%1,%2,%3}, [%4];"
                 : "=r"(r[0]), "=r"(r[1]), "=r"(r[2]), "=r"(r[3]) : "r"(addr));
}
__device__ __forceinline__ void cp_async16(uint32_t dst, const void* src) {
    asm volatile("cp.async.cg.shared.global [%0], [%1], 16;" :: "r"(dst), "l"(src));
}
__device__ __forceinline__ void cp_async8(uint32_t dst, const void* src) {
    asm volatile("cp.async.ca.shared.global [%0], [%1], 8;" :: "r"(dst), "l"(src));
}
__device__ __forceinline__ void cp_commit() {
    asm volatile("cp.async.commit_group;" ::: "memory");
}
__device__ __forceinline__ void cp_wait1() {
    asm volatile("cp.async.wait_group 1;" ::: "memory");
}
__device__ __forceinline__ void cp_wait2() {
    asm volatile("cp.async.wait_group 2;" ::: "memory");
}
__device__ __forceinline__ void cp_wait0() {
    asm volatile("cp.async.wait_group 0;" ::: "memory");
}

// ---------------- fast transcendentals ----------------
__device__ __forceinline__ float sig_fast(float x) {
    float xc = fminf(fmaxf(x, -30.f), 30.f);
    return __fdividef(1.f, 1.f + __expf(-xc));
}
__device__ __forceinline__ float tanh_fast(float x) {
    float x2 = fminf(fmaxf(2.f * x, -30.f), 30.f);
    float e  = __expf(x2);
    return __fdividef(e - 1.f, e + 1.f);
}

// ============================================================================
// prepare_all (R15 proven)
// ============================================================================
__global__ void prepare_all(const int* __restrict__ tokens,
                            const float* __restrict__ emb_W,
                            const float* __restrict__ Wih0, const float* __restrict__ Wih1,
                            const float* __restrict__ Wih2, const float* __restrict__ dec_W,
                            const float* __restrict__ h0_0, const float* __restrict__ h0_1,
                            const float* __restrict__ h0_2,
                            __half* __restrict__ Ah0, __half* __restrict__ Wh,
                            __half* __restrict__ h0p)
{
    const int stride = gridDim.x * blockDim.x;
    const int tid0 = blockIdx.x * blockDim.x + threadIdx.x;
    if (tid0 < 4) g_bars[tid0] = 0;

    for (int i = tid0; i < TB * Ee; i += stride) {
        int tb = i / Ee, e = i - tb * Ee;
        Ah0[i] = __float2half_rn(emb_W[(size_t)tokens[tb] * Ee + e]);
    }
    for (int i = tid0; i < 4600 * 400; i += stride)
        Wh[WOFF0 + i] = __float2half_rn(Wih0[i]);
    for (int i = tid0; i < 4600 * 1152; i += stride) {
        int r = i / 1152, k = i - r * 1152;
        Wh[WOFF1 + i] = (k < 1150) ? __float2half_rn(Wih1[(size_t)r * 1150 + k])
                                   : __ushort_as_half(0);
    }
    for (int i = tid0; i < 1600 * 1152; i += stride) {
        int r = i / 1152, k = i - r * 1152;
        Wh[WOFF2 + i] = (k < 1150) ? __float2half_rn(Wih2[(size_t)r * 1150 + k])
                                   : __ushort_as_half(0);
    }
    for (int i = tid0; i < Vv * 400; i += stride)
        Wh[WOFFD + i] = __float2half_rn(dec_W[i]);
    for (int i = tid0; i < Bb * 1152; i += stride) {
        int r = i / 1152, j = i - r * 1152;
        h0p[0 * Bb * KPAD_MAX + i] = (j < Hh) ? __float2half_rn(h0_0[(size_t)r * Hh + j]) : __ushort_as_half(0);
        h0p[1 * Bb * KPAD_MAX + i] = (j < Hh) ? __float2half_rn(h0_1[(size_t)r * Hh + j]) : __ushort_as_half(0);
    }
    for (int i = tid0; i < Bb * 448; i += stride) {
        int r = i / 448, j = i - r * 448;
        h0p[2 * Bb * KPAD_MAX + r * 448 + j] =
            (j < Ee) ? __float2half_rn(h0_2[(size_t)r * Ee + j]) : __ushort_as_half(0);
    }
}

// ============================================================================
// fp16 GEMM — R16: BK=32, 3-stage cp.async (half the barriers per K).
// 48+32-half row stride (GSTR=40, 80B) — conflict-free for STS + ldmatrix:
// row addr/16 mod 8 = row*5 mod 8 -> distinct over any 8 consecutive rows.
// K%32==16 remainder handled by per-segment zero fill (K%8==0 guaranteed).
// ============================================================================
#define GSTR 40
#define GTPS (128 * GSTR * 2)   // halves per stage (A tile + B tile)

__global__ __launch_bounds__(256)
void hgemm_f16(const __half* __restrict__ Ah, const __half* __restrict__ Wh,
               const float* __restrict__ bias0, const float* __restrict__ bias1,
               float* __restrict__ C, int M, int N, int K, int lda, int ldw)
{
    extern __shared__ __half smem[];

    const int tid  = threadIdx.x;
    const int lane = tid & 31;
    const int warp = tid >> 5;
    const int wm   = warp >> 2;
    const int wn   = warp & 3;
    const int g    = lane >> 2;
    const int t4   = lane & 3;
    const int bm   = blockIdx.y * 128;
    const int bn   = blockIdx.x * 128;

    float acc[4][4][4];
#pragma unroll
    for (int i = 0; i < 4; i++)
#pragma unroll
        for (int j = 0; j < 4; j++)
#pragma unroll
            for (int q = 0; q < 4; q++) acc[i][j][q] = 0.f;

    auto issue = [&](int c, int s) {
        __half* st = smem + s * GTPS;
#pragma unroll
        for (int i = 0; i < 2; i++) {
            int e   = tid + i * 256;          // 0..511
            int row = e >> 2;
            int seg = e & 3;
            int koff = c * 32 + seg * 8;
            {
                __half* dst = st + row * GSTR + seg * 8;
                int gm = bm + row;
                if (gm < M && koff < K) cp_async16(smem_u32(dst), Ah + (size_t)gm * lda + koff);
                else                    *(float4*)dst = make_float4(0.f,0.f,0.f,0.f);
            }
            {
                __half* dst = st + 128 * GSTR + row * GSTR + seg * 8;
                int gn = bn + row;
                if (gn < N && koff < K) cp_async16(smem_u32(dst), Wh + (size_t)gn * ldw + koff);
                else                    *(float4*)dst = make_float4(0.f,0.f,0.f,0.f);
            }
        }
    };

    // ldmatrix lane addressing (constant across chunks); per-half k offset added
    const int rA   = wm * 64 + (lane & 7) + ((lane >> 3) & 1) * 8;
    const int ksA  = (lane >> 4) * 8;
    const int matB = lane >> 3;
    const int rB   = lane & 7;
    const int ntqB = matB >> 1;
    const int ksB  = (matB & 1) * 8;
    const int bRow = wn * 32 + ntqB * 8 + rB;

    const int NCH = (K + 31) >> 5;
    issue(0, 0); cp_commit();
    issue(1, 1); cp_commit();

    for (int c = 0; c < NCH; c++) {
        cp_wait1();
        __syncthreads();
        __half* st  = smem + (c % 3) * GTPS;
        __half* AsH = st;
        __half* BsH = st + 128 * GSTR;

        // ---- k-half 0 ----
        uint32_t ah[4][4], bf[8];
#pragma unroll
        for (int mt = 0; mt < 4; mt++)
            ldsm4(ah[mt], smem_u32(AsH + (rA + mt * 16) * GSTR + ksA));
        {
            uint32_t b0 = smem_u32(BsH + bRow * GSTR + ksB);
            ldsm4(bf,     b0);
            ldsm4(bf + 4, b0 + 16 * GSTR * 2);
        }
        if (c + 2 < NCH) issue(c + 2, (c + 2) % 3);
        cp_commit();
#pragma unroll
        for (int mt = 0; mt < 4; mt++)
#pragma unroll
            for (int nt = 0; nt < 4; nt++)
                mma_f16(acc[mt][nt], ah[mt], &bf[nt * 2]);

        // ---- k-half 1 ----
#pragma unroll
        for (int mt = 0; mt < 4; mt++)
            ldsm4(ah[mt], smem_u32(AsH + (rA + mt * 16) * GSTR + 16 + ksA));
        {
            uint32_t b0 = smem_u32(BsH + bRow * GSTR + 16 + ksB);
            ldsm4(bf,     b0);
            ldsm4(bf + 4, b0 + 16 * GSTR * 2);
        }
#pragma unroll
        for (int mt = 0; mt < 4; mt++)
#pragma unroll
            for (int nt = 0; nt < 4; nt++)
                mma_f16(acc[mt][nt], ah[mt], &bf[nt * 2]);
    }

#pragma unroll
    for (int mt = 0; mt < 4; mt++) {
#pragma unroll
        for (int nt = 0; nt < 4; nt++) {
            int r0 = bm + wm * 64 + mt * 16 + g;
            int cc = bn + wn * 32 + nt * 8 + 2 * t4;
            if (cc >= N) continue;
            float bv0 = 0.f, bv1 = 0.f;
            if (bias0) { bv0 += bias0[cc]; bv1 += bias0[cc + 1]; }
            if (bias1) { bv0 += bias1[cc]; bv1 += bias1[cc + 1]; }
            if (r0 < M)
                *(float2*)(C + (size_t)r0 * N + cc) =
                    make_float2(acc[mt][nt][0] + bv0, acc[mt][nt][1] + bv1);
            if (r0 + 8 < M)
                *(float2*)(C + (size_t)(r0 + 8) * N + cc) =
                    make_float2(acc[mt][nt][2] + bv0, acc[mt][nt][3] + bv1);
        }
    }
}

// ============================================================================
// Persistent recurrent kernel (R15 proven, NT-templated)
// ============================================================================
#define ASTR 24
#define AROWS 320
#define ABUF (AROWS*ASTR)

template<int MTW, int NT>
__device__ __forceinline__ void rec_step_gemm(
    const __half* __restrict__ hiR,
    const __half* Bh, __half* Ah, float* sg,
    int BSTR, int Kpad, int lane, int wq, int gRowBase, int rowBaseS)
{
    const int SGS = NT * 8 + 1;
    const int NC   = Kpad >> 4;
    const int ncq  = NC >> 2;
    const int cbeg = wq * ncq;

    float acc[MTW][NT][4];
#pragma unroll
    for (int mt = 0; mt < MTW; mt++)
#pragma unroll
        for (int nt = 0; nt < NT; nt++)
#pragma unroll
            for (int q = 0; q < 4; q++) acc[mt][nt][q] = 0.f;

    auto issue = [&](int c, int buf) {
#pragma unroll
        for (int r = 0; r < MTW; r++) {
            int e   = lane + 32 * r;
            int row = e >> 1;
            int seg = e & 1;
            const __half* src = hiR + (size_t)(gRowBase + row) * Kpad + c * 16 + seg * 8;
            __half* dstp = Ah + buf * ABUF + (rowBaseS + row) * ASTR + seg * 8;
            cp_async16(smem_u32(dstp), src);
        }
    };

    issue(cbeg, 0);     cp_commit();
    issue(cbeg + 1, 1); cp_commit();
    issue(cbeg + 2, 2); cp_commit();

    for (int i = 0; i < ncq; i++) {
        const int c   = cbeg + i;
        const int buf = i & 3;
        cp_wait2();
        __syncwarp();

        uint32_t bfr[2 * NT];
        {
            int k0 = c * 16;
            if (NT == 4) {
                uint32_t bh0[4], bh1[4];
                ldsm4(bh0, smem_u32(Bh + (size_t)lane * BSTR + k0));
                ldsm4(bh1, smem_u32(Bh + (size_t)lane * BSTR + k0 + 8));
#pragma unroll
                for (int nt = 0; nt < 4; nt++) { bfr[2*nt] = bh0[nt]; bfr[2*nt+1] = bh1[nt]; }
            } else {
                uint32_t bx[4];
                uint32_t addr = smem_u32(Bh + (size_t)(lane & 15) * BSTR + k0 + ((lane >> 4) * 8));
                ldsm4(bx, addr);
                bfr[0] = bx[0]; bfr[1] = bx[2];
                bfr[2] = bx[1]; bfr[3] = bx[3];
            }
        }
        uint32_t ah[MTW][4];
        {
            int rAr  = rowBaseS + (lane & 7) + ((lane >> 3) & 1) * 8;
            int kseg = (lane >> 4) * 8;
#pragma unroll
            for (int mt = 0; mt < MTW; mt++)
                ldsm4(ah[mt], smem_u32(Ah + buf * ABUF + (rAr + mt * 16) * ASTR + kseg));
        }
        if (i + 3 < ncq) issue(c + 3, (i + 3) & 3);
        cp_commit();

#pragma unroll
        for (int mt = 0; mt < MTW; mt++)
#pragma unroll
            for (int nt = 0; nt < NT; nt++)
                mma_f16(acc[mt][nt], ah[mt], &bfr[2 * nt]);
    }

    const int gq = lane >> 2;
    const int t4 = lane & 3;
#pragma unroll
    for (int mt = 0; mt < MTW; mt++)
#pragma unroll
        for (int nt = 0; nt < NT; nt++) {
            int row = gRowBase + mt * 16 + gq;
            int col = nt * 8 + 2 * t4;
            atomicAdd(&sg[row * SGS + col],           acc[mt][nt][0]);
            atomicAdd(&sg[row * SGS + col + 1],       acc[mt][nt][1]);
            atomicAdd(&sg[(row + 8) * SGS + col],     acc[mt][nt][2]);
            atomicAdd(&sg[(row + 8) * SGS + col + 1], acc[mt][nt][3]);
        }
}

template<int NT>
__global__ __launch_bounds__(256, 1)
void rec_persist(const float* __restrict__ Whh, const float* __restrict__ xw,
                 const float* __restrict__ c0, float* __restrict__ cOut,
                 const __half* __restrict__ h0p,
                 __half* __restrict__ ysAh,
                 float* __restrict__ hT, int H, int Kpad, int NJ,
                 unsigned* __restrict__ barp)
{
    const int JT  = NT * 2;
    const int SGS = NT * 8 + 1;
    const int XWS = NT * 8 + 4;
    const int JSH = (NT == 4) ? 3 : 2;

    extern __shared__ char sraw[];
    const int BSTR = Kpad + 8;
    __half* Bh  = (__half*)sraw;
    __half* Ah  = Bh + 4 * JT * BSTR;
    float*  sg  = (float*)(Ah + 4 * ABUF);
    float*  sxw = sg + 96 * SGS;

    const int tid  = threadIdx.x;
    const int lane = tid & 31;
    const int warp = tid >> 5;
    const int wq   = warp & 3;
    const int wm   = warp >> 2;
    const int gRowBase = wm * 48;
    const int rowBaseS = wq * 80 + wm * 48;
    const int j0   = blockIdx.x * JT;
    const int N4   = 4 * H;

    auto issue_xw = [&](int t) {
        const float* xw_t = xw + (size_t)t * Bb * N4;
        const int upr = JT >> 1;
        const int total = 80 * 4 * upr;
        for (int u = tid; u < total; u += 256) {
            int r2   = u / (4 * upr);
            int v    = u - r2 * 4 * upr;
            int gate = v / upr;
            int pr   = v - gate * upr;
            const float* src = xw_t + (size_t)r2 * N4 + gate * H + j0 + 2 * pr;
            float* dst = sxw + r2 * XWS + gate * JT + 2 * pr;
            cp_async8(smem_u32(dst), src);
        }
        cp_commit();
    };

    {
        int Kh = Kpad >> 1;
        for (int idx = tid; idx < 4 * JT * Kh; idx += 256) {
            int r  = idx / Kh;
            int kp = idx - r * Kh;
            int k  = 2 * kp;
            int gate = r / JT, jj = r - gate * JT;
            int j = j0 + jj;
            float x = 0.f, y = 0.f;
            if (j < H) {
                const float* wp = Whh + (size_t)(gate * H + j) * H;
                if (k < H)     x = wp[k];
                if (k + 1 < H) y = wp[k + 1];
            }
            *(__half2*)&Bh[r * BSTR + k] =
                __halves2half2(__float2half_rn(x), __float2half_rn(y));
        }
    }

    float creg[3] = {0.f, 0.f, 0.f};
#pragma unroll
    for (int q = 0; q < 3; q++) {
        int e = tid + q * 256;
        if (e < Bb * JT) {
            int r2 = e >> JSH, jj = e & (JT - 1);
            int j = j0 + jj;
            if (j < H) creg[q] = c0[(size_t)r2 * H + j];
        }
    }

    for (int i = tid; i < 96 * SGS; i += 256) sg[i] = 0.f;
    issue_xw(0);
    __syncthreads();

    for (int t = 0; t < Tt; t++) {
        const __half* hiR = (t == 0) ? h0p : ysAh + (size_t)(t - 1) * Bb * Kpad;

        if (wm == 0)
            rec_step_gemm<3, NT>(hiR, Bh, Ah, sg,
                                 BSTR, Kpad, lane, wq, gRowBase, rowBaseS);
        else
            rec_step_gemm<2, NT>(hiR, Bh, Ah, sg,
                                 BSTR, Kpad, lane, wq, gRowBase, rowBaseS);
        cp_wait0();
        __syncthreads();

#pragma unroll
        for (int q = 0; q < 3; q++) {
            int e = tid + q * 256;
            if (e >= Bb * JT) break;
            int r2 = e >> JSH, jj = e & (JT - 1);
            int j = j0 + jj;
            if (j >= H) continue;
            const float* xr = sxw + r2 * XWS;
            float gi = sg[r2 * SGS + jj]          + xr[jj];
            float gf = sg[r2 * SGS + JT + jj]     + xr[JT + jj];
            float gg = sg[r2 * SGS + 2 * JT + jj] + xr[2 * JT + jj];
            float go = sg[r2 * SGS + 3 * JT + jj] + xr[3 * JT + jj];
            float cn = sig_fast(gf) * creg[q] + sig_fast(gi) * tanh_fast(gg);
            float hn = sig_fast(go) * tanh_fast(cn);
            creg[q] = cn;
            ysAh[((size_t)t * Bb + r2) * Kpad + j] = __float2half_rn(hn);
            if (t == Tt - 1) {
                hT[(size_t)r2 * H + j]   = hn;
                cOut[(size_t)r2 * H + j] = cn;
            }
        }
        __syncthreads();

        if (tid == 0) {
            __threadfence();
            atomicAdd(barp, 1u);
        }
        for (int i = tid; i < 96 * SGS; i += 256) sg[i] = 0.f;
        if (t + 1 < Tt) issue_xw(t + 1);
        if (tid == 0) {
            unsigned target = (unsigned)NJ * (unsigned)(t + 1);
            while (*(volatile unsigned*)barp < target) { }
            __threadfence();
        }
        __syncthreads();
    }
}

// ---------------- host orchestration ----------------
static inline int ceil_div(int a, int b) { return (a + b - 1) / b; }

extern "C" void kernel_launch(void* const* d_in, const int* in_sizes, int n_in,
                              void* d_out, int out_size)
{
    const int*   tokens = (const int*)d_in[0];
    const float* emb_W  = (const float*)d_in[1];
    const float* dec_W  = (const float*)d_in[2];
    const float* dec_b  = (const float*)d_in[3];

    const float *Wih[3], *Whh[3], *bih[3], *bhh[3], *h0[3], *c0[3];
    for (int l = 0; l < 3; l++) {
        int base = 4 + l * 6;
        Wih[l] = (const float*)d_in[base + 0];
        Whh[l] = (const float*)d_in[base + 1];
        bih[l] = (const float*)d_in[base + 2];
        bhh[l] = (const float*)d_in[base + 3];
        h0[l]  = (const float*)d_in[base + 4];
        c0[l]  = (const float*)d_in[base + 5];
    }

    float *pXW;
    __half *pH0p, *pAh0, *pAh1, *pWh;
    unsigned* pBars;
    cudaGetSymbolAddress((void**)&pXW, g_XW);
    cudaGetSymbolAddress((void**)&pH0p, g_h0p);
    cudaGetSymbolAddress((void**)&pAh0, g_Ahi);
    cudaGetSymbolAddress((void**)&pWh,  g_Whi);
    cudaGetSymbolAddress((void**)&pBars, g_bars);
    pAh1 = pAh0 + (size_t)TB * KPAD_MAX;

    float* out = (float*)d_out;

    // opt-in smem
    {
        int rec4 = 32 * (KPAD_MAX + 8) * 2 + 4 * ABUF * 2 + 96 * 33 * 4 + 80 * 36 * 4;
        cudaFuncSetAttribute(rec_persist<4>,
                             cudaFuncAttributeMaxDynamicSharedMemorySize, rec4);
        int rec2 = 16 * (448 + 8) * 2 + 4 * ABUF * 2 + 96 * 17 * 4 + 80 * 20 * 4;
        cudaFuncSetAttribute(rec_persist<2>,
                             cudaFuncAttributeMaxDynamicSharedMemorySize, rec2);
        cudaFuncSetAttribute(hgemm_f16,
                             cudaFuncAttributeMaxDynamicSharedMemorySize, 3 * GTPS * 2);
    }

    // 1) all input prep in one launch
    prepare_all<<<2048, 256>>>(tokens, emb_W, Wih[0], Wih[1], Wih[2], dec_W,
                               h0[0], h0[1], h0[2], pAh0, pWh, pH0p);

    const int Hd[3]   = {Hh, Hh, Ee};
    const int KpI[3]  = {400, 1152, 1152};
    const int KpR[3]  = {1152, 1152, 448};
    const size_t WOf[3] = {WOFF0, WOFF1, WOFF2};
    __half *aHin = pAh0, *aHout = pAh1;
    size_t out_off = (size_t)TB * Vv;

    for (int l = 0; l < 3; l++) {
        int H = Hd[l], N4 = 4 * H;
        int KI = KpI[l];

        // xW = Ah @ Wh^T + bih + bhh
        {
            dim3 grid(ceil_div(N4, 128), ceil_div(TB, 128));
            hgemm_f16<<<grid, 256, 3 * GTPS * 2>>>(
                aHin, pWh + WOf[l], bih[l], bhh[l], pXW, TB, N4, KI, KI, KI);
        }

        // persistent recurrent kernel; hT/cT straight into d_out
        if (l < 2) {
            int NJ = ceil_div(H, 8);
            int smemBytes = 32 * (KpR[l] + 8) * 2 + 4 * ABUF * 2
                          + 96 * 33 * 4 + 80 * 36 * 4;
            rec_persist<4><<<NJ, 256, smemBytes>>>(
                Whh[l], pXW, c0[l], out + out_off + (size_t)Bb * H,
                pH0p + (size_t)l * Bb * KPAD_MAX, aHout, out + out_off,
                H, KpR[l], NJ, pBars + l);
        } else {
            int NJ = ceil_div(H, 4);
            int smemBytes = 16 * (KpR[l] + 8) * 2 + 4 * ABUF * 2
                          + 96 * 17 * 4 + 80 * 20 * 4;
            rec_persist<2><<<NJ, 256, smemBytes>>>(
                Whh[l], pXW, c0[l], out + out_off + (size_t)Bb * H,
                pH0p + (size_t)l * Bb * KPAD_MAX, aHout, out + out_off,
                H, KpR[l], NJ, pBars + l);
        }
        out_off += 2 * (size_t)Bb * H;

        __half* th = aHin; aHin = aHout; aHout = th;
    }

    // 2) decoder
    {
        dim3 grid(ceil_div(Vv, 128), ceil_div(TB, 128));
        hgemm_f16<<<grid, 256, 3 * GTPS * 2>>>(
            aHin, pWh + WOFFD, dec_b, nullptr, out, TB, Vv, Ee, 448, Ee);
    }
}

// round 17
// speedup vs baseline: 6.4403x; 1.0171x over previous
#include <cuda_runtime.h>
#include <cuda_fp16.h>
#include <math.h>
#include <stdint.h>

// Problem constants
#define Tt 70
#define Bb 80
#define Vv 33278
#define Ee 400
#define Hh 1150
#define TB (Tt*Bb)          // 5600
#define KPAD_MAX 1152

// ---------------- scratch (device globals; no allocation) ----------------
__device__ float  g_XW[(size_t)TB * 4 * Hh + 32];
__device__ __half g_h0p[3][Bb * KPAD_MAX];
__device__ unsigned g_bars[4];
__device__ __align__(128) __half g_Ahi[2][(size_t)TB * KPAD_MAX];
__device__ __align__(128) __half g_Whi[(size_t)22400000];

// weight plane offsets (halves)
#define WOFF0 0                            // Wih0: 4600 x 400
#define WOFF1 (WOFF0 + 4600*400)           // Wih1: 4600 x 1152
#define WOFF2 (WOFF1 + 4600*1152)          // Wih2: 1600 x 1152
#define WOFFD (WOFF2 + 1600*1152)          // dec:  33278 x 400

// ---------------- ptx helpers ----------------
__device__ __forceinline__ void mma_f16(float* c, const uint32_t* a, const uint32_t* b) {
    asm volatile(
        "mma.sync.aligned.m16n8k16.row.col.f32.f16.f16.f32 "
        "{%0,%1,%2,%3}, {%4,%5,%6,%7}, {%8,%9}, {%0,%1,%2,%3};"
        : "+f"(c[0]), "+f"(c[1]), "+f"(c[2]), "+f"(c[3])
        : "r"(a[0]), "r"(a[1]), "r"(a[2]), "r"(a[3]), "r"(b[0]), "r"(b[1]));
}
__device__ __forceinline__ uint32_t smem_u32(const void* p) {
    return (uint32_t)__cvta_generic_to_shared(p);
}
__device__ __forceinline__ void ldsm4(uint32_t* r, uint32_t addr) {
    asm volatile("ldmatrix.sync.aligned.m8n8.x4.shared.b16 {%0,%1,%2,%3}, [%4];"
                 : "=r"(r[0]), "=r"(r[1]), "=r"(r[2]), "=r"(r[3]) : "r"(addr));
}
__device__ __forceinline__ void cp_async16(uint32_t dst, const void* src) {
    asm volatile("cp.async.cg.shared.global [%0], [%1], 16;" :: "r"(dst), "l"(src));
}
__device__ __forceinline__ void cp_async8(uint32_t dst, const void* src) {
    asm volatile("cp.async.ca.shared.global [%0], [%1], 8;" :: "r"(dst), "l"(src));
}
__device__ __forceinline__ void cp_commit() {
    asm volatile("cp.async.commit_group;" ::: "memory");
}
__device__ __forceinline__ void cp_wait1() {
    asm volatile("cp.async.wait_group 1;" ::: "memory");
}
__device__ __forceinline__ void cp_wait2() {
    asm volatile("cp.async.wait_group 2;" ::: "memory");
}
__device__ __forceinline__ void cp_wait0() {
    asm volatile("cp.async.wait_group 0;" ::: "memory");
}

// ---------------- fast transcendentals ----------------
__device__ __forceinline__ float sig_fast(float x) {
    float xc = fminf(fmaxf(x, -30.f), 30.f);
    return __fdividef(1.f, 1.f + __expf(-xc));
}
__device__ __forceinline__ float tanh_fast(float x) {
    float x2 = fminf(fmaxf(2.f * x, -30.f), 30.f);
    float e  = __expf(x2);
    return __fdividef(e - 1.f, e + 1.f);
}

// ============================================================================
// prepare_all (R15 proven)
// ============================================================================
__global__ void prepare_all(const int* __restrict__ tokens,
                            const float* __restrict__ emb_W,
                            const float* __restrict__ Wih0, const float* __restrict__ Wih1,
                            const float* __restrict__ Wih2, const float* __restrict__ dec_W,
                            const float* __restrict__ h0_0, const float* __restrict__ h0_1,
                            const float* __restrict__ h0_2,
                            __half* __restrict__ Ah0, __half* __restrict__ Wh,
                            __half* __restrict__ h0p)
{
    const int stride = gridDim.x * blockDim.x;
    const int tid0 = blockIdx.x * blockDim.x + threadIdx.x;
    if (tid0 < 4) g_bars[tid0] = 0;

    for (int i = tid0; i < TB * Ee; i += stride) {
        int tb = i / Ee, e = i - tb * Ee;
        Ah0[i] = __float2half_rn(emb_W[(size_t)tokens[tb] * Ee + e]);
    }
    for (int i = tid0; i < 4600 * 400; i += stride)
        Wh[WOFF0 + i] = __float2half_rn(Wih0[i]);
    for (int i = tid0; i < 4600 * 1152; i += stride) {
        int r = i / 1152, k = i - r * 1152;
        Wh[WOFF1 + i] = (k < 1150) ? __float2half_rn(Wih1[(size_t)r * 1150 + k])
                                   : __ushort_as_half(0);
    }
    for (int i = tid0; i < 1600 * 1152; i += stride) {
        int r = i / 1152, k = i - r * 1152;
        Wh[WOFF2 + i] = (k < 1150) ? __float2half_rn(Wih2[(size_t)r * 1150 + k])
                                   : __ushort_as_half(0);
    }
    for (int i = tid0; i < Vv * 400; i += stride)
        Wh[WOFFD + i] = __float2half_rn(dec_W[i]);
    for (int i = tid0; i < Bb * 1152; i += stride) {
        int r = i / 1152, j = i - r * 1152;
        h0p[0 * Bb * KPAD_MAX + i] = (j < Hh) ? __float2half_rn(h0_0[(size_t)r * Hh + j]) : __ushort_as_half(0);
        h0p[1 * Bb * KPAD_MAX + i] = (j < Hh) ? __float2half_rn(h0_1[(size_t)r * Hh + j]) : __ushort_as_half(0);
    }
    for (int i = tid0; i < Bb * 448; i += stride) {
        int r = i / 448, j = i - r * 448;
        h0p[2 * Bb * KPAD_MAX + r * 448 + j] =
            (j < Ee) ? __float2half_rn(h0_2[(size_t)r * Ee + j]) : __ushort_as_half(0);
    }
}

// ============================================================================
// fp16 GEMM — R17: BK=64, 3-stage cp.async (18 barriers for K=1152).
// GSTR=72 halves (144B row): 16B granule index = 9r+s; 9r mod 8 distinct over
// any 8 consecutive rows -> ldmatrix conflict-free (same proof as GSTR 24/40).
// K remainder (K%64) zero-filled per 16B segment.
// ============================================================================
#define GSTR 72
#define GTPS (128 * GSTR * 2)   // halves per stage (A tile + B tile)

__global__ __launch_bounds__(256)
void hgemm_f16(const __half* __restrict__ Ah, const __half* __restrict__ Wh,
               const float* __restrict__ bias0, const float* __restrict__ bias1,
               float* __restrict__ C, int M, int N, int K, int lda, int ldw)
{
    extern __shared__ __half smem[];

    const int tid  = threadIdx.x;
    const int lane = tid & 31;
    const int warp = tid >> 5;
    const int wm   = warp >> 2;
    const int wn   = warp & 3;
    const int g    = lane >> 2;
    const int t4   = lane & 3;
    const int bm   = blockIdx.y * 128;
    const int bn   = blockIdx.x * 128;

    float acc[4][4][4];
#pragma unroll
    for (int i = 0; i < 4; i++)
#pragma unroll
        for (int j = 0; j < 4; j++)
#pragma unroll
            for (int q = 0; q < 4; q++) acc[i][j][q] = 0.f;

    auto issue = [&](int c, int s) {
        __half* st = smem + s * GTPS;
#pragma unroll
        for (int i = 0; i < 4; i++) {
            int e   = tid + i * 256;          // 0..1023
            int row = e >> 3;
            int seg = e & 7;
            int koff = c * 64 + seg * 8;
            {
                __half* dst = st + row * GSTR + seg * 8;
                int gm = bm + row;
                if (gm < M && koff < K) cp_async16(smem_u32(dst), Ah + (size_t)gm * lda + koff);
                else                    *(float4*)dst = make_float4(0.f,0.f,0.f,0.f);
            }
            {
                __half* dst = st + 128 * GSTR + row * GSTR + seg * 8;
                int gn = bn + row;
                if (gn < N && koff < K) cp_async16(smem_u32(dst), Wh + (size_t)gn * ldw + koff);
                else                    *(float4*)dst = make_float4(0.f,0.f,0.f,0.f);
            }
        }
    };

    // ldmatrix lane addressing (constant across chunks); per-quarter k offset added
    const int rA   = wm * 64 + (lane & 7) + ((lane >> 3) & 1) * 8;
    const int ksA  = (lane >> 4) * 8;
    const int matB = lane >> 3;
    const int rB   = lane & 7;
    const int ntqB = matB >> 1;
    const int ksB  = (matB & 1) * 8;
    const int bRow = wn * 32 + ntqB * 8 + rB;

    const int NCH = (K + 63) >> 6;
    issue(0, 0); cp_commit();
    issue(1, 1); cp_commit();

    for (int c = 0; c < NCH; c++) {
        cp_wait1();
        __syncthreads();
        __half* st  = smem + (c % 3) * GTPS;
        __half* AsH = st;
        __half* BsH = st + 128 * GSTR;

        // issue next chunk early (buffer (c+2)%3 is free: last read at c-1,
        // and the barrier above guarantees all warps are past it)
        bool doIssue = (c + 2 < NCH);

#pragma unroll
        for (int kq = 0; kq < 4; kq++) {
            const int ko = kq * 16;
            uint32_t ah[4][4], bf[8];
#pragma unroll
            for (int mt = 0; mt < 4; mt++)
                ldsm4(ah[mt], smem_u32(AsH + (rA + mt * 16) * GSTR + ko + ksA));
            {
                uint32_t b0 = smem_u32(BsH + bRow * GSTR + ko + ksB);
                ldsm4(bf,     b0);
                ldsm4(bf + 4, b0 + 16 * GSTR * 2);
            }
            if (kq == 0) {
                if (doIssue) issue(c + 2, (c + 2) % 3);
                cp_commit();
            }
#pragma unroll
            for (int mt = 0; mt < 4; mt++)
#pragma unroll
                for (int nt = 0; nt < 4; nt++)
                    mma_f16(acc[mt][nt], ah[mt], &bf[nt * 2]);
        }
    }

#pragma unroll
    for (int mt = 0; mt < 4; mt++) {
#pragma unroll
        for (int nt = 0; nt < 4; nt++) {
            int r0 = bm + wm * 64 + mt * 16 + g;
            int cc = bn + wn * 32 + nt * 8 + 2 * t4;
            if (cc >= N) continue;
            float bv0 = 0.f, bv1 = 0.f;
            if (bias0) { bv0 += bias0[cc]; bv1 += bias0[cc + 1]; }
            if (bias1) { bv0 += bias1[cc]; bv1 += bias1[cc + 1]; }
            if (r0 < M)
                *(float2*)(C + (size_t)r0 * N + cc) =
                    make_float2(acc[mt][nt][0] + bv0, acc[mt][nt][1] + bv1);
            if (r0 + 8 < M)
                *(float2*)(C + (size_t)(r0 + 8) * N + cc) =
                    make_float2(acc[mt][nt][2] + bv0, acc[mt][nt][3] + bv1);
        }
    }
}

// ============================================================================
// Persistent recurrent kernel (R15 proven, NT-templated)
// ============================================================================
#define ASTR 24
#define AROWS 320
#define ABUF (AROWS*ASTR)

template<int MTW, int NT>
__device__ __forceinline__ void rec_step_gemm(
    const __half* __restrict__ hiR,
    const __half* Bh, __half* Ah, float* sg,
    int BSTR, int Kpad, int lane, int wq, int gRowBase, int rowBaseS)
{
    const int SGS = NT * 8 + 1;
    const int NC   = Kpad >> 4;
    const int ncq  = NC >> 2;
    const int cbeg = wq * ncq;

    float acc[MTW][NT][4];
#pragma unroll
    for (int mt = 0; mt < MTW; mt++)
#pragma unroll
        for (int nt = 0; nt < NT; nt++)
#pragma unroll
            for (int q = 0; q < 4; q++) acc[mt][nt][q] = 0.f;

    auto issue = [&](int c, int buf) {
#pragma unroll
        for (int r = 0; r < MTW; r++) {
            int e   = lane + 32 * r;
            int row = e >> 1;
            int seg = e & 1;
            const __half* src = hiR + (size_t)(gRowBase + row) * Kpad + c * 16 + seg * 8;
            __half* dstp = Ah + buf * ABUF + (rowBaseS + row) * ASTR + seg * 8;
            cp_async16(smem_u32(dstp), src);
        }
    };

    issue(cbeg, 0);     cp_commit();
    issue(cbeg + 1, 1); cp_commit();
    issue(cbeg + 2, 2); cp_commit();

    for (int i = 0; i < ncq; i++) {
        const int c   = cbeg + i;
        const int buf = i & 3;
        cp_wait2();
        __syncwarp();

        uint32_t bfr[2 * NT];
        {
            int k0 = c * 16;
            if (NT == 4) {
                uint32_t bh0[4], bh1[4];
                ldsm4(bh0, smem_u32(Bh + (size_t)lane * BSTR + k0));
                ldsm4(bh1, smem_u32(Bh + (size_t)lane * BSTR + k0 + 8));
#pragma unroll
                for (int nt = 0; nt < 4; nt++) { bfr[2*nt] = bh0[nt]; bfr[2*nt+1] = bh1[nt]; }
            } else {
                uint32_t bx[4];
                uint32_t addr = smem_u32(Bh + (size_t)(lane & 15) * BSTR + k0 + ((lane >> 4) * 8));
                ldsm4(bx, addr);
                bfr[0] = bx[0]; bfr[1] = bx[2];
                bfr[2] = bx[1]; bfr[3] = bx[3];
            }
        }
        uint32_t ah[MTW][4];
        {
            int rAr  = rowBaseS + (lane & 7) + ((lane >> 3) & 1) * 8;
            int kseg = (lane >> 4) * 8;
#pragma unroll
            for (int mt = 0; mt < MTW; mt++)
                ldsm4(ah[mt], smem_u32(Ah + buf * ABUF + (rAr + mt * 16) * ASTR + kseg));
        }
        if (i + 3 < ncq) issue(c + 3, (i + 3) & 3);
        cp_commit();

#pragma unroll
        for (int mt = 0; mt < MTW; mt++)
#pragma unroll
            for (int nt = 0; nt < NT; nt++)
                mma_f16(acc[mt][nt], ah[mt], &bfr[2 * nt]);
    }

    const int gq = lane >> 2;
    const int t4 = lane & 3;
#pragma unroll
    for (int mt = 0; mt < MTW; mt++)
#pragma unroll
        for (int nt = 0; nt < NT; nt++) {
            int row = gRowBase + mt * 16 + gq;
            int col = nt * 8 + 2 * t4;
            atomicAdd(&sg[row * SGS + col],           acc[mt][nt][0]);
            atomicAdd(&sg[row * SGS + col + 1],       acc[mt][nt][1]);
            atomicAdd(&sg[(row + 8) * SGS + col],     acc[mt][nt][2]);
            atomicAdd(&sg[(row + 8) * SGS + col + 1], acc[mt][nt][3]);
        }
}

template<int NT>
__global__ __launch_bounds__(256, 1)
void rec_persist(const float* __restrict__ Whh, const float* __restrict__ xw,
                 const float* __restrict__ c0, float* __restrict__ cOut,
                 const __half* __restrict__ h0p,
                 __half* __restrict__ ysAh,
                 float* __restrict__ hT, int H, int Kpad, int NJ,
                 unsigned* __restrict__ barp)
{
    const int JT  = NT * 2;
    const int SGS = NT * 8 + 1;
    const int XWS = NT * 8 + 4;
    const int JSH = (NT == 4) ? 3 : 2;

    extern __shared__ char sraw[];
    const int BSTR = Kpad + 8;
    __half* Bh  = (__half*)sraw;
    __half* Ah  = Bh + 4 * JT * BSTR;
    float*  sg  = (float*)(Ah + 4 * ABUF);
    float*  sxw = sg + 96 * SGS;

    const int tid  = threadIdx.x;
    const int lane = tid & 31;
    const int warp = tid >> 5;
    const int wq   = warp & 3;
    const int wm   = warp >> 2;
    const int gRowBase = wm * 48;
    const int rowBaseS = wq * 80 + wm * 48;
    const int j0   = blockIdx.x * JT;
    const int N4   = 4 * H;

    auto issue_xw = [&](int t) {
        const float* xw_t = xw + (size_t)t * Bb * N4;
        const int upr = JT >> 1;
        const int total = 80 * 4 * upr;
        for (int u = tid; u < total; u += 256) {
            int r2   = u / (4 * upr);
            int v    = u - r2 * 4 * upr;
            int gate = v / upr;
            int pr   = v - gate * upr;
            const float* src = xw_t + (size_t)r2 * N4 + gate * H + j0 + 2 * pr;
            float* dst = sxw + r2 * XWS + gate * JT + 2 * pr;
            cp_async8(smem_u32(dst), src);
        }
        cp_commit();
    };

    {
        int Kh = Kpad >> 1;
        for (int idx = tid; idx < 4 * JT * Kh; idx += 256) {
            int r  = idx / Kh;
            int kp = idx - r * Kh;
            int k  = 2 * kp;
            int gate = r / JT, jj = r - gate * JT;
            int j = j0 + jj;
            float x = 0.f, y = 0.f;
            if (j < H) {
                const float* wp = Whh + (size_t)(gate * H + j) * H;
                if (k < H)     x = wp[k];
                if (k + 1 < H) y = wp[k + 1];
            }
            *(__half2*)&Bh[r * BSTR + k] =
                __halves2half2(__float2half_rn(x), __float2half_rn(y));
        }
    }

    float creg[3] = {0.f, 0.f, 0.f};
#pragma unroll
    for (int q = 0; q < 3; q++) {
        int e = tid + q * 256;
        if (e < Bb * JT) {
            int r2 = e >> JSH, jj = e & (JT - 1);
            int j = j0 + jj;
            if (j < H) creg[q] = c0[(size_t)r2 * H + j];
        }
    }

    for (int i = tid; i < 96 * SGS; i += 256) sg[i] = 0.f;
    issue_xw(0);
    __syncthreads();

    for (int t = 0; t < Tt; t++) {
        const __half* hiR = (t == 0) ? h0p : ysAh + (size_t)(t - 1) * Bb * Kpad;

        if (wm == 0)
            rec_step_gemm<3, NT>(hiR, Bh, Ah, sg,
                                 BSTR, Kpad, lane, wq, gRowBase, rowBaseS);
        else
            rec_step_gemm<2, NT>(hiR, Bh, Ah, sg,
                                 BSTR, Kpad, lane, wq, gRowBase, rowBaseS);
        cp_wait0();
        __syncthreads();

#pragma unroll
        for (int q = 0; q < 3; q++) {
            int e = tid + q * 256;
            if (e >= Bb * JT) break;
            int r2 = e >> JSH, jj = e & (JT - 1);
            int j = j0 + jj;
            if (j >= H) continue;
            const float* xr = sxw + r2 * XWS;
            float gi = sg[r2 * SGS + jj]          + xr[jj];
            float gf = sg[r2 * SGS + JT + jj]     + xr[JT + jj];
            float gg = sg[r2 * SGS + 2 * JT + jj] + xr[2 * JT + jj];
            float go = sg[r2 * SGS + 3 * JT + jj] + xr[3 * JT + jj];
            float cn = sig_fast(gf) * creg[q] + sig_fast(gi) * tanh_fast(gg);
            float hn = sig_fast(go) * tanh_fast(cn);
            creg[q] = cn;
            ysAh[((size_t)t * Bb + r2) * Kpad + j] = __float2half_rn(hn);
            if (t == Tt - 1) {
                hT[(size_t)r2 * H + j]   = hn;
                cOut[(size_t)r2 * H + j] = cn;
            }
        }
        __syncthreads();

        if (tid == 0) {
            __threadfence();
            atomicAdd(barp, 1u);
        }
        for (int i = tid; i < 96 * SGS; i += 256) sg[i] = 0.f;
        if (t + 1 < Tt) issue_xw(t + 1);
        if (tid == 0) {
            unsigned target = (unsigned)NJ * (unsigned)(t + 1);
            while (*(volatile unsigned*)barp < target) { }
            __threadfence();
        }
        __syncthreads();
    }
}

// ---------------- host orchestration ----------------
static inline int ceil_div(int a, int b) { return (a + b - 1) / b; }

extern "C" void kernel_launch(void* const* d_in, const int* in_sizes, int n_in,
                              void* d_out, int out_size)
{
    const int*   tokens = (const int*)d_in[0];
    const float* emb_W  = (const float*)d_in[1];
    const float* dec_W  = (const float*)d_in[2];
    const float* dec_b  = (const float*)d_in[3];

    const float *Wih[3], *Whh[3], *bih[3], *bhh[3], *h0[3], *c0[3];
    for (int l = 0; l < 3; l++) {
        int base = 4 + l * 6;
        Wih[l] = (const float*)d_in[base + 0];
        Whh[l] = (const float*)d_in[base + 1];
        bih[l] = (const float*)d_in[base + 2];
        bhh[l] = (const float*)d_in[base + 3];
        h0[l]  = (const float*)d_in[base + 4];
        c0[l]  = (const float*)d_in[base + 5];
    }

    float *pXW;
    __half *pH0p, *pAh0, *pAh1, *pWh;
    unsigned* pBars;
    cudaGetSymbolAddress((void**)&pXW, g_XW);
    cudaGetSymbolAddress((void**)&pH0p, g_h0p);
    cudaGetSymbolAddress((void**)&pAh0, g_Ahi);
    cudaGetSymbolAddress((void**)&pWh,  g_Whi);
    cudaGetSymbolAddress((void**)&pBars, g_bars);
    pAh1 = pAh0 + (size_t)TB * KPAD_MAX;

    float* out = (float*)d_out;

    // opt-in smem
    {
        int rec4 = 32 * (KPAD_MAX + 8) * 2 + 4 * ABUF * 2 + 96 * 33 * 4 + 80 * 36 * 4;
        cudaFuncSetAttribute(rec_persist<4>,
                             cudaFuncAttributeMaxDynamicSharedMemorySize, rec4);
        int rec2 = 16 * (448 + 8) * 2 + 4 * ABUF * 2 + 96 * 17 * 4 + 80 * 20 * 4;
        cudaFuncSetAttribute(rec_persist<2>,
                             cudaFuncAttributeMaxDynamicSharedMemorySize, rec2);
        cudaFuncSetAttribute(hgemm_f16,
                             cudaFuncAttributeMaxDynamicSharedMemorySize, 3 * GTPS * 2);
    }

    // 1) all input prep in one launch
    prepare_all<<<2048, 256>>>(tokens, emb_W, Wih[0], Wih[1], Wih[2], dec_W,
                               h0[0], h0[1], h0[2], pAh0, pWh, pH0p);

    const int Hd[3]   = {Hh, Hh, Ee};
    const int KpI[3]  = {400, 1152, 1152};
    const int KpR[3]  = {1152, 1152, 448};
    const size_t WOf[3] = {WOFF0, WOFF1, WOFF2};
    __half *aHin = pAh0, *aHout = pAh1;
    size_t out_off = (size_t)TB * Vv;

    for (int l = 0; l < 3; l++) {
        int H = Hd[l], N4 = 4 * H;
        int KI = KpI[l];

        // xW = Ah @ Wh^T + bih + bhh
        {
            dim3 grid(ceil_div(N4, 128), ceil_div(TB, 128));
            hgemm_f16<<<grid, 256, 3 * GTPS * 2>>>(
                aHin, pWh + WOf[l], bih[l], bhh[l], pXW, TB, N4, KI, KI, KI);
        }

        // persistent recurrent kernel; hT/cT straight into d_out
        if (l < 2) {
            int NJ = ceil_div(H, 8);
            int smemBytes = 32 * (KpR[l] + 8) * 2 + 4 * ABUF * 2
                          + 96 * 33 * 4 + 80 * 36 * 4;
            rec_persist<4><<<NJ, 256, smemBytes>>>(
                Whh[l], pXW, c0[l], out + out_off + (size_t)Bb * H,
                pH0p + (size_t)l * Bb * KPAD_MAX, aHout, out + out_off,
                H, KpR[l], NJ, pBars + l);
        } else {
            int NJ = ceil_div(H, 4);
            int smemBytes = 16 * (KpR[l] + 8) * 2 + 4 * ABUF * 2
                          + 96 * 17 * 4 + 80 * 20 * 4;
            rec_persist<2><<<NJ, 256, smemBytes>>>(
                Whh[l], pXW, c0[l], out + out_off + (size_t)Bb * H,
                pH0p + (size_t)l * Bb * KPAD_MAX, aHout, out + out_off,
                H, KpR[l], NJ, pBars + l);
        }
        out_off += 2 * (size_t)Bb * H;

        __half* th = aHin; aHin = aHout; aHout = th;
    }

    // 2) decoder
    {
        dim3 grid(ceil_div(Vv, 128), ceil_div(TB, 128));
        hgemm_f16<<<grid, 256, 3 * GTPS * 2>>>(
            aHin, pWh + WOFFD, dec_b, nullptr, out, TB, Vv, Ee, 448, Ee);
    }
}